// round 13
// baseline (speedup 1.0000x reference)
#include <cuda_runtime.h>
#include <cuda_bf16.h>
#include <math.h>
#include <stdint.h>

#define N0c 100000
#define N1c 25000
#define N2c 6250
#define E0c 1600000
#define E1c 400000
#define E2c 100000
#define NFc 128
#define NCc 40

// ---------------- scratch (no allocations allowed) ----------------
constexpr size_t F_XW   = 0;
constexpr size_t F_T    = F_XW  + (size_t)N0c*NFc;
constexpr size_t F_H1   = F_T   + (size_t)N0c*NCc;
constexpr size_t F_H01  = F_H1  + (size_t)N1c*NFc;
constexpr size_t F_Q1   = F_H01 + (size_t)N1c*NFc;
constexpr size_t F_K1   = F_Q1  + (size_t)N1c*NFc;
constexpr size_t F_H1R  = F_K1  + (size_t)N1c*NFc;
constexpr size_t F_U1   = F_H1R + (size_t)N1c*NFc;
constexpr size_t F_H2   = F_U1  + (size_t)N1c*NFc;
constexpr size_t F_H02  = F_H2  + (size_t)N2c*NFc;
constexpr size_t F_Q2   = F_H02 + (size_t)N2c*NFc;
constexpr size_t F_K2   = F_Q2  + (size_t)N2c*NFc;
constexpr size_t F_H2R  = F_K2  + (size_t)N2c*NFc;
constexpr size_t F_VAL0 = F_H2R + (size_t)N2c*NFc;
constexpr size_t F_VAL1 = F_VAL0 + (size_t)E0c;
constexpr size_t F_VAL2 = F_VAL1 + (size_t)E1c;
constexpr size_t F_TOT  = F_VAL2 + (size_t)E2c;
__device__ __align__(16) float g_f[F_TOT];

constexpr size_t I_OFF0 = 0;
constexpr size_t I_CNT0 = I_OFF0 + (size_t)N0c + 4;
constexpr size_t I_SRC0 = I_CNT0 + (size_t)N0c;
constexpr size_t I_OFF1 = I_SRC0 + (size_t)E0c;
constexpr size_t I_CNT1 = I_OFF1 + (size_t)N1c + 4;
constexpr size_t I_SRC1 = I_CNT1 + (size_t)N1c;
constexpr size_t I_OFF2 = I_SRC1 + (size_t)E1c;
constexpr size_t I_CNT2 = I_OFF2 + (size_t)N2c + 4;
constexpr size_t I_SRC2 = I_CNT2 + (size_t)N2c;
constexpr size_t I_POF0 = I_SRC2 + (size_t)E2c;
constexpr size_t I_PID0 = I_POF0 + (size_t)N1c + 4;
constexpr size_t I_POF1 = I_PID0 + (size_t)N0c;
constexpr size_t I_PID1 = I_POF1 + (size_t)N2c + 4;
constexpr size_t I_PART = I_PID1 + (size_t)N1c;
constexpr size_t I_PCN1 = I_PART + 256;
constexpr size_t I_PCN2 = I_PCN1 + (size_t)N1c;
constexpr size_t I_TOT  = I_PCN2 + (size_t)N2c;
__device__ int g_i[I_TOT];

// split-bf16 weights: 6 slots x 32768 bf16 (slot5 = gc2W, 40x128 hi + lo)
__device__ __align__(16) __nv_bfloat16 g_wt[6 * 32768];

#define SCAN_BLOCKS 162
struct Seg { int* cnt; int* off; int* cur; int pbase; int n; int sblk; };
__device__ __forceinline__ Seg seg_resolve(int b) {
    Seg s;
    if (b < 98)       { s.cnt = g_i + I_CNT0; s.off = g_i + I_OFF0; s.cur = g_i + I_CNT0; s.pbase = 0;   s.n = N0c; s.sblk = b; }
    else if (b < 123) { s.cnt = g_i + I_CNT1; s.off = g_i + I_OFF1; s.cur = g_i + I_CNT1; s.pbase = 98;  s.n = N1c; s.sblk = b - 98; }
    else if (b < 130) { s.cnt = g_i + I_CNT2; s.off = g_i + I_OFF2; s.cur = g_i + I_CNT2; s.pbase = 123; s.n = N2c; s.sblk = b - 123; }
    else if (b < 155) { s.cnt = g_i + I_PCN1; s.off = g_i + I_POF0; s.cur = g_i + I_PCN1; s.pbase = 130; s.n = N1c; s.sblk = b - 130; }
    else              { s.cnt = g_i + I_PCN2; s.off = g_i + I_POF1; s.cur = g_i + I_PCN2; s.pbase = 155; s.n = N2c; s.sblk = b - 155; }
    return s;
}

// ---------------- mma helpers ----------------
__device__ __forceinline__ void mma16816(float* c, const uint32_t* a,
                                         uint32_t b0, uint32_t b1) {
    asm volatile(
        "mma.sync.aligned.m16n8k16.row.col.f32.bf16.bf16.f32 "
        "{%0,%1,%2,%3}, {%4,%5,%6,%7}, {%8,%9}, {%0,%1,%2,%3};"
        : "+f"(c[0]), "+f"(c[1]), "+f"(c[2]), "+f"(c[3])
        : "r"(a[0]), "r"(a[1]), "r"(a[2]), "r"(a[3]), "r"(b0), "r"(b1));
}
__device__ __forceinline__ void split_bf16(float a, float b, uint32_t& hi, uint32_t& lo) {
    __nv_bfloat16 ha = __float2bfloat16(a), hb = __float2bfloat16(b);
    __nv_bfloat162 hp; hp.x = ha; hp.y = hb;
    __nv_bfloat162 lp;
    lp.x = __float2bfloat16(a - __bfloat162float(ha));
    lp.y = __float2bfloat16(b - __bfloat162float(hb));
    hi = *(uint32_t*)&hp;
    lo = *(uint32_t*)&lp;
}

// ---------------- batched weight prep: 5 x [128,128] + gc2W [128,40] ----------------
__global__ void wprep_all(const float* __restrict__ w0, const float* __restrict__ w1,
                          const float* __restrict__ w2, const float* __restrict__ w3,
                          const float* __restrict__ w4, const float* __restrict__ w5) {
    int b = blockIdx.x;
    if (b < 320) {
        int seg = b >> 6;
        int t = ((b & 63) << 8) + threadIdx.x;
        if (t >= 16384) return;
        const float* W = (seg == 0) ? w0 : (seg == 1) ? w1 : (seg == 2) ? w2
                        : (seg == 3) ? w3 : w4;
        __nv_bfloat16* out = g_wt + (size_t)seg * 32768;
        int n = t >> 7, k = t & 127;
        float v = __ldg(&W[(size_t)k * 128 + n]);
        __nv_bfloat16 h = __float2bfloat16(v);
        out[t] = h;
        out[16384 + t] = __float2bfloat16(v - __bfloat162float(h));
    } else {
        int t = ((b - 320) << 8) + threadIdx.x;    // gc2W: 40x128 = 5120
        if (t >= 5120) return;
        __nv_bfloat16* out = g_wt + (size_t)5 * 32768;
        int n = t >> 7, k = t & 127;
        float v = __ldg(&w5[(size_t)k * 40 + n]);
        __nv_bfloat16 h = __float2bfloat16(v);
        out[t] = h;
        out[5120 + t] = __float2bfloat16(v - __bfloat162float(h));
    }
}

// ---------------- tensor-core GEMM: Y = X[M,128] @ W[128,128], split bf16 ----------------
#define WROW 68
__global__ void __launch_bounds__(256, 2) gemm_mma(
    const float* __restrict__ X, const __nv_bfloat16* __restrict__ WA,
    float* __restrict__ Y, int M)
{
    extern __shared__ uint32_t sm[];
    uint32_t* XH = sm;            // 64*68 = 4352
    uint32_t* XL = sm + 4352;
    uint32_t* BH = sm + 8704;     // 128*68 = 8704
    uint32_t* BL = sm + 17408;    // total 26112 u32 = 104448 B
    const int tid = threadIdx.x;
    const int row0 = blockIdx.x * 64;

    for (int i = tid; i < 1024; i += 256) {
        int r = i >> 4, c8 = (i & 15) << 3;
        int gr = row0 + r;
        float4 v0 = make_float4(0.f, 0.f, 0.f, 0.f), v1 = v0;
        if (gr < M) {
            const float4* xp = (const float4*)(X + (size_t)gr * 128 + c8);
            v0 = __ldg(xp); v1 = __ldg(xp + 1);
        }
        uint32_t hi[4], lo[4];
        split_bf16(v0.x, v0.y, hi[0], lo[0]);
        split_bf16(v0.z, v0.w, hi[1], lo[1]);
        split_bf16(v1.x, v1.y, hi[2], lo[2]);
        split_bf16(v1.z, v1.w, hi[3], lo[3]);
        int si = r * WROW + (c8 >> 1);
        *(uint4*)(XH + si) = make_uint4(hi[0], hi[1], hi[2], hi[3]);
        *(uint4*)(XL + si) = make_uint4(lo[0], lo[1], lo[2], lo[3]);
    }
    {
        const uint4* wa = (const uint4*)WA;
        for (int i = tid; i < 2048; i += 256) {
            int r = i >> 4, c4 = (i & 15) << 2;
            int si = r * WROW + c4;
            *(uint4*)(BH + si) = __ldg(wa + i);
            *(uint4*)(BL + si) = __ldg(wa + 2048 + i);
        }
    }
    __syncthreads();

    const int wid = tid >> 5, lane = tid & 31;
    const int wm = wid & 1, wn = wid >> 1;     // 2 x 4 warp grid
    const int g = lane >> 2, tq = lane & 3;

    float C[2][4][4];
    #pragma unroll
    for (int mt = 0; mt < 2; mt++)
        #pragma unroll
        for (int nt = 0; nt < 4; nt++)
            #pragma unroll
            for (int j = 0; j < 4; j++) C[mt][nt][j] = 0.f;

    #pragma unroll
    for (int ks = 0; ks < 8; ks++) {
        uint32_t Ah[2][4], Al[2][4];
        #pragma unroll
        for (int mt = 0; mt < 2; mt++) {
            int r0 = (wm * 32 + mt * 16 + g) * WROW + ks * 8 + tq;
            Ah[mt][0] = XH[r0];        Ah[mt][1] = XH[r0 + 8 * WROW];
            Ah[mt][2] = XH[r0 + 4];    Ah[mt][3] = XH[r0 + 8 * WROW + 4];
            Al[mt][0] = XL[r0];        Al[mt][1] = XL[r0 + 8 * WROW];
            Al[mt][2] = XL[r0 + 4];    Al[mt][3] = XL[r0 + 8 * WROW + 4];
        }
        #pragma unroll
        for (int nt = 0; nt < 4; nt++) {
            int bi = (wn * 32 + nt * 8 + g) * WROW + ks * 8 + tq;
            uint32_t bh0 = BH[bi], bh1 = BH[bi + 4];
            uint32_t bl0 = BL[bi], bl1 = BL[bi + 4];
            #pragma unroll
            for (int mt = 0; mt < 2; mt++) {
                mma16816(C[mt][nt], Ah[mt], bh0, bh1);
                mma16816(C[mt][nt], Ah[mt], bl0, bl1);
                mma16816(C[mt][nt], Al[mt], bh0, bh1);
            }
        }
    }
    #pragma unroll
    for (int mt = 0; mt < 2; mt++) {
        int row = row0 + wm * 32 + mt * 16 + g;
        #pragma unroll
        for (int nt = 0; nt < 4; nt++) {
            int col = wn * 32 + nt * 8 + tq * 2;
            if (row < M)
                *(float2*)(Y + (size_t)row * 128 + col) =
                    make_float2(C[mt][nt][0], C[mt][nt][1]);
            if (row + 8 < M)
                *(float2*)(Y + (size_t)(row + 8) * 128 + col) =
                    make_float2(C[mt][nt][2], C[mt][nt][3]);
        }
    }
}

// ---- fused pool + DUAL Q/K GEMM ----
// load phase: H[row] = sum_{ids in CSR seg} X[id]; H0 = H + emb[nwgt] -> gmem;
// split-bf16(H) -> smem; then Q = H@Wq, K = H@Wk (both B tiles resident).
__global__ void __launch_bounds__(256, 1) gemm_qk_pool(
    const int* __restrict__ off, const int* __restrict__ ids,
    const float* __restrict__ X,
    const int* __restrict__ nw, const float* __restrict__ emb,
    const __nv_bfloat16* __restrict__ WQ, const __nv_bfloat16* __restrict__ WK,
    float* __restrict__ H0, float* __restrict__ Q, float* __restrict__ K, int M)
{
    extern __shared__ uint32_t sm[];
    uint32_t* XH = sm;            // 4352
    uint32_t* XL = sm + 4352;
    // B planes: QH@8704, QL@17408, KH@26112, KL@34816; total 43520 u32 = 174080 B
    const int tid = threadIdx.x;
    const int row0 = blockIdx.x * 64;

    for (int i = tid; i < 1024; i += 256) {
        int r = i >> 4, c8 = (i & 15) << 3;
        int gr = row0 + r;
        float4 v0 = make_float4(0.f, 0.f, 0.f, 0.f), v1 = v0;
        if (gr < M) {
            int s = __ldg(&off[gr]), e = __ldg(&off[gr + 1]);
            for (int j = s; j < e; j++) {
                int node = __ldg(&ids[j]);
                const float4* xp = (const float4*)(X + (size_t)node * 128 + c8);
                float4 a = __ldg(xp), b = __ldg(xp + 1);
                v0.x += a.x; v0.y += a.y; v0.z += a.z; v0.w += a.w;
                v1.x += b.x; v1.y += b.y; v1.z += b.z; v1.w += b.w;
            }
            int w = __ldg(&nw[gr]);
            const float4* ep = (const float4*)(emb + (size_t)w * 128 + c8);
            float4 e0 = __ldg(ep), e1 = __ldg(ep + 1);
            float4 h00, h01;
            h00.x = v0.x + e0.x; h00.y = v0.y + e0.y;
            h00.z = v0.z + e0.z; h00.w = v0.w + e0.w;
            h01.x = v1.x + e1.x; h01.y = v1.y + e1.y;
            h01.z = v1.z + e1.z; h01.w = v1.w + e1.w;
            float4* hp = (float4*)(H0 + (size_t)gr * 128 + c8);
            hp[0] = h00; hp[1] = h01;
        }
        uint32_t hi[4], lo[4];
        split_bf16(v0.x, v0.y, hi[0], lo[0]);
        split_bf16(v0.z, v0.w, hi[1], lo[1]);
        split_bf16(v1.x, v1.y, hi[2], lo[2]);
        split_bf16(v1.z, v1.w, hi[3], lo[3]);
        int si = r * WROW + (c8 >> 1);
        *(uint4*)(XH + si) = make_uint4(hi[0], hi[1], hi[2], hi[3]);
        *(uint4*)(XL + si) = make_uint4(lo[0], lo[1], lo[2], lo[3]);
    }
    {
        const uint4* wq = (const uint4*)WQ;
        const uint4* wk = (const uint4*)WK;
        for (int i = tid; i < 2048; i += 256) {
            int r = i >> 4, c4 = (i & 15) << 2;
            int si = r * WROW + c4;
            *(uint4*)(sm + 8704  + si) = __ldg(wq + i);
            *(uint4*)(sm + 17408 + si) = __ldg(wq + 2048 + i);
            *(uint4*)(sm + 26112 + si) = __ldg(wk + i);
            *(uint4*)(sm + 34816 + si) = __ldg(wk + 2048 + i);
        }
    }
    __syncthreads();

    const int wid = tid >> 5, lane = tid & 31;
    const int wm = wid & 1, wn = wid >> 1;     // 2 x 4 warp grid
    const int g = lane >> 2, tq = lane & 3;

    for (int ob = 0; ob < 2; ob++) {
        const uint32_t* BH = sm + 8704 + ob * 17408;
        const uint32_t* BL = BH + 8704;
        float* Y = (ob == 0) ? Q : K;

        float C[2][4][4];
        #pragma unroll
        for (int mt = 0; mt < 2; mt++)
            #pragma unroll
            for (int nt = 0; nt < 4; nt++)
                #pragma unroll
                for (int j = 0; j < 4; j++) C[mt][nt][j] = 0.f;

        #pragma unroll
        for (int ks = 0; ks < 8; ks++) {
            uint32_t Ah[2][4], Al[2][4];
            #pragma unroll
            for (int mt = 0; mt < 2; mt++) {
                int r0 = (wm * 32 + mt * 16 + g) * WROW + ks * 8 + tq;
                Ah[mt][0] = XH[r0];        Ah[mt][1] = XH[r0 + 8 * WROW];
                Ah[mt][2] = XH[r0 + 4];    Ah[mt][3] = XH[r0 + 8 * WROW + 4];
                Al[mt][0] = XL[r0];        Al[mt][1] = XL[r0 + 8 * WROW];
                Al[mt][2] = XL[r0 + 4];    Al[mt][3] = XL[r0 + 8 * WROW + 4];
            }
            #pragma unroll
            for (int nt = 0; nt < 4; nt++) {
                int bi = (wn * 32 + nt * 8 + g) * WROW + ks * 8 + tq;
                uint32_t bh0 = BH[bi], bh1 = BH[bi + 4];
                uint32_t bl0 = BL[bi], bl1 = BL[bi + 4];
                #pragma unroll
                for (int mt = 0; mt < 2; mt++) {
                    mma16816(C[mt][nt], Ah[mt], bh0, bh1);
                    mma16816(C[mt][nt], Ah[mt], bl0, bl1);
                    mma16816(C[mt][nt], Al[mt], bh0, bh1);
                }
            }
        }
        #pragma unroll
        for (int mt = 0; mt < 2; mt++) {
            int row = row0 + wm * 32 + mt * 16 + g;
            #pragma unroll
            for (int nt = 0; nt < 4; nt++) {
                int col = wn * 32 + nt * 8 + tq * 2;
                if (row < M)
                    *(float2*)(Y + (size_t)row * 128 + col) =
                        make_float2(C[mt][nt][0], C[mt][nt][1]);
                if (row + 8 < M)
                    *(float2*)(Y + (size_t)(row + 8) * 128 + col) =
                        make_float2(C[mt][nt][2], C[mt][nt][3]);
            }
        }
    }
}

// ---- fused DOUBLE unpool + gc2 GEMM ----
__global__ void __launch_bounds__(256, 2) gemm40_mma(
    const float* __restrict__ H2R, const int* __restrict__ assign1,
    const float* __restrict__ H1R, const int* __restrict__ assign0,
    const float* __restrict__ gcn, float* __restrict__ crf_out,
    float* __restrict__ Y, int M)
{
    extern __shared__ uint32_t sm[];
    uint32_t* XH = sm;
    uint32_t* XL = sm + 4352;
    uint32_t* BH = sm + 8704;
    uint32_t* BL = sm + 13056;
    const int tid = threadIdx.x;
    const int row0 = blockIdx.x * 64;
    const __nv_bfloat16* W40 = g_wt + (size_t)5 * 32768;

    for (int i = tid; i < 1024; i += 256) {
        int r = i >> 4, c8 = (i & 15) << 3;
        int gr = row0 + r;
        float4 v0 = make_float4(0.f, 0.f, 0.f, 0.f), v1 = v0;
        if (gr < M) {
            int a = __ldg(&assign0[gr]);
            int b = __ldg(&assign1[a]);
            const float4* u2 = (const float4*)(H2R + (size_t)b * 128 + c8);
            const float4* u1 = (const float4*)(H1R + (size_t)a * 128 + c8);
            const float4* gp = (const float4*)(gcn + (size_t)gr * 128 + c8);
            float4 a0 = __ldg(u2), a1 = __ldg(u2 + 1);
            float4 b0 = __ldg(u1), b1 = __ldg(u1 + 1);
            float4 g0 = __ldg(gp), g1 = __ldg(gp + 1);
            v0.x = a0.x + b0.x + g0.x; v0.y = a0.y + b0.y + g0.y;
            v0.z = a0.z + b0.z + g0.z; v0.w = a0.w + b0.w + g0.w;
            v1.x = a1.x + b1.x + g1.x; v1.y = a1.y + b1.y + g1.y;
            v1.z = a1.z + b1.z + g1.z; v1.w = a1.w + b1.w + g1.w;
            float4* cp = (float4*)(crf_out + (size_t)gr * 128 + c8);
            cp[0] = v0; cp[1] = v1;
        }
        uint32_t hi[4], lo[4];
        split_bf16(v0.x, v0.y, hi[0], lo[0]);
        split_bf16(v0.z, v0.w, hi[1], lo[1]);
        split_bf16(v1.x, v1.y, hi[2], lo[2]);
        split_bf16(v1.z, v1.w, hi[3], lo[3]);
        int si = r * WROW + (c8 >> 1);
        *(uint4*)(XH + si) = make_uint4(hi[0], hi[1], hi[2], hi[3]);
        *(uint4*)(XL + si) = make_uint4(lo[0], lo[1], lo[2], lo[3]);
    }
    {
        const uint4* wh = (const uint4*)W40;
        const uint4* wl = (const uint4*)(W40 + 5120);
        for (int i = tid; i < 1024; i += 256) {
            int r = i >> 4, c4 = (i & 15) << 2;
            int si = r * WROW + c4;
            uint4 h = make_uint4(0, 0, 0, 0), l = h;
            if (r < 40) { h = __ldg(wh + i); l = __ldg(wl + i); }
            *(uint4*)(BH + si) = h;
            *(uint4*)(BL + si) = l;
        }
    }
    __syncthreads();

    const int wid = tid >> 5, lane = tid & 31;
    const int wm = wid & 3, wn = wid >> 2;     // 4x2 grid; 16x32 warp tiles
    const int g = lane >> 2, tq = lane & 3;

    float C[4][4];
    #pragma unroll
    for (int nt = 0; nt < 4; nt++)
        #pragma unroll
        for (int j = 0; j < 4; j++) C[nt][j] = 0.f;

    #pragma unroll
    for (int ks = 0; ks < 8; ks++) {
        uint32_t Ah[4], Al[4];
        int r0 = (wm * 16 + g) * WROW + ks * 8 + tq;
        Ah[0] = XH[r0];        Ah[1] = XH[r0 + 8 * WROW];
        Ah[2] = XH[r0 + 4];    Ah[3] = XH[r0 + 8 * WROW + 4];
        Al[0] = XL[r0];        Al[1] = XL[r0 + 8 * WROW];
        Al[2] = XL[r0 + 4];    Al[3] = XL[r0 + 8 * WROW + 4];
        #pragma unroll
        for (int nt = 0; nt < 4; nt++) {
            int bi = (wn * 32 + nt * 8 + g) * WROW + ks * 8 + tq;
            uint32_t bh0 = BH[bi], bh1 = BH[bi + 4];
            uint32_t bl0 = BL[bi], bl1 = BL[bi + 4];
            mma16816(C[nt], Ah, bh0, bh1);
            mma16816(C[nt], Ah, bl0, bl1);
            mma16816(C[nt], Al, bh0, bh1);
        }
    }
    {
        int row = row0 + wm * 16 + g;
        #pragma unroll
        for (int nt = 0; nt < 4; nt++) {
            int col = wn * 32 + nt * 8 + tq * 2;
            if (col < 40) {
                if (row < M)
                    *(float2*)(Y + (size_t)row * 40 + col) = make_float2(C[nt][0], C[nt][1]);
                if (row + 8 < M)
                    *(float2*)(Y + (size_t)(row + 8) * 40 + col) = make_float2(C[nt][2], C[nt][3]);
            }
        }
    }
}

// ---------------- batched CSR build kernels ----------------
__global__ void kzero_all() {
    int i = blockIdx.x * 256 + threadIdx.x;
    if (i < 100000)      g_i[I_CNT0 + i] = 0;
    else if (i < 125000) g_i[I_CNT1 + (i - 100000)] = 0;
    else if (i < 131250) g_i[I_CNT2 + (i - 125000)] = 0;
    else if (i < 156250) g_i[I_PCN1 + (i - 131250)] = 0;
    else if (i < 162500) g_i[I_PCN2 + (i - 156250)] = 0;
}
__global__ void khist_all(const int* __restrict__ A0, const int* __restrict__ A1,
                          const int* __restrict__ A2, const int* __restrict__ as0,
                          const int* __restrict__ as1) {
    int i = blockIdx.x * 256 + threadIdx.x;
    if (i < 1600000)      atomicAdd(&g_i[I_CNT0 + __ldg(&A0[i])], 1);
    else if (i < 2000000) atomicAdd(&g_i[I_CNT1 + __ldg(&A1[i - 1600000])], 1);
    else if (i < 2100000) atomicAdd(&g_i[I_CNT2 + __ldg(&A2[i - 2000000])], 1);
    else if (i < 2200000) atomicAdd(&g_i[I_PCN1 + __ldg(&as0[i - 2100000])], 1);
    else if (i < 2225000) atomicAdd(&g_i[I_PCN2 + __ldg(&as1[i - 2200000])], 1);
}
__global__ void scan_blk_all() {
    __shared__ int wsum[32];
    Seg s = seg_resolve(blockIdx.x);
    int t = threadIdx.x;
    int i = s.sblk * 1024 + t;
    int v = (i < s.n) ? s.cnt[i] : 0;
    int x = v;
    #pragma unroll
    for (int o = 1; o < 32; o <<= 1) {
        int tmp = __shfl_up_sync(0xffffffffu, x, o);
        if ((t & 31) >= o) x += tmp;
    }
    if ((t & 31) == 31) wsum[t >> 5] = x;
    __syncthreads();
    if (t < 32) {
        int y = wsum[t];
        #pragma unroll
        for (int o = 1; o < 32; o <<= 1) {
            int tmp = __shfl_up_sync(0xffffffffu, y, o);
            if (t >= o) y += tmp;
        }
        wsum[t] = y;
    }
    __syncthreads();
    int base = (t >= 32) ? wsum[(t >> 5) - 1] : 0;
    int incl = base + x;
    if (i < s.n) s.off[i] = incl - v;
    if (t == 1023) g_i[I_PART + s.pbase + s.sblk] = incl;
}
__global__ void scan_part_all() {
    __shared__ int sh[128];
    const int bases[5] = {0, 98, 123, 130, 155};
    const int cnts[5]  = {98, 25, 7, 25, 7};
    int b = blockIdx.x, t = threadIdx.x;
    int* part = g_i + I_PART + bases[b];
    int nb = cnts[b];
    int v = (t < nb) ? part[t] : 0;
    sh[t] = v;
    __syncthreads();
    #pragma unroll
    for (int o = 1; o < 128; o <<= 1) {
        int tmp = (t >= o) ? sh[t - o] : 0;
        __syncthreads();
        sh[t] += tmp;
        __syncthreads();
    }
    if (t < nb) part[t] = sh[t] - v;
    if (t == 0) {
        int total = sh[127];
        int* off = (b == 0) ? g_i + I_OFF0 : (b == 1) ? g_i + I_OFF1
                 : (b == 2) ? g_i + I_OFF2 : (b == 3) ? g_i + I_POF0 : g_i + I_POF1;
        int n = (b == 0) ? N0c : (b == 1) ? N1c : (b == 2) ? N2c
              : (b == 3) ? N1c : N2c;
        off[n] = total;
    }
}
__global__ void scan_add_all() {
    Seg s = seg_resolve(blockIdx.x);
    int i = s.sblk * 1024 + threadIdx.x;
    if (i < s.n) {
        int v = s.off[i] + g_i[I_PART + s.pbase + s.sblk];
        s.off[i] = v;
        s.cur[i] = v;
    }
}
__global__ void kscatter_all(const int* __restrict__ A0, const float* __restrict__ A0v,
                             const int* __restrict__ A1, const float* __restrict__ A1v,
                             const int* __restrict__ A2, const float* __restrict__ A2v,
                             const int* __restrict__ as0, const int* __restrict__ as1) {
    int i = blockIdx.x * 256 + threadIdx.x;
    if (i < 1600000) {
        int pos = atomicAdd(&g_i[I_CNT0 + __ldg(&A0[i])], 1);
        g_i[I_SRC0 + pos] = __ldg(&A0[1600000 + i]);
        g_f[F_VAL0 + pos] = __ldg(&A0v[i]);
    } else if (i < 2000000) {
        int e = i - 1600000;
        int pos = atomicAdd(&g_i[I_CNT1 + __ldg(&A1[e])], 1);
        g_i[I_SRC1 + pos] = __ldg(&A1[400000 + e]);
        g_f[F_VAL1 + pos] = __ldg(&A1v[e]);
    } else if (i < 2100000) {
        int e = i - 2000000;
        int pos = atomicAdd(&g_i[I_CNT2 + __ldg(&A2[e])], 1);
        g_i[I_SRC2 + pos] = __ldg(&A2[100000 + e]);
        g_f[F_VAL2 + pos] = __ldg(&A2v[e]);
    } else if (i < 2200000) {
        int e = i - 2100000;
        int pos = atomicAdd(&g_i[I_PCN1 + __ldg(&as0[e])], 1);
        g_i[I_PID0 + pos] = e;
    } else if (i < 2225000) {
        int e = i - 2200000;
        int pos = atomicAdd(&g_i[I_PCN2 + __ldg(&as1[e])], 1);
        g_i[I_PID1 + pos] = e;
    }
}

// ---------------- CSR SpMM, 128 cols, warp per row ----------------
__global__ void spmm128(const int* __restrict__ off, const int* __restrict__ srcs,
                        const float* __restrict__ vals, const float* __restrict__ X,
                        const float* __restrict__ bias, float* __restrict__ Y,
                        int n, int relu) {
    int row = blockIdx.x * blockDim.y + threadIdx.y;
    if (row >= n) return;
    int lane = threadIdx.x;
    int s = off[row], e = off[row + 1];
    float4 acc = make_float4(0.f, 0.f, 0.f, 0.f);
    for (int j = s; j < e; j++) {
        int src = __ldg(&srcs[j]);
        float v = __ldg(&vals[j]);
        float4 xv = __ldg((const float4*)(X + (size_t)src * 128) + lane);
        acc.x = fmaf(v, xv.x, acc.x); acc.y = fmaf(v, xv.y, acc.y);
        acc.z = fmaf(v, xv.z, acc.z); acc.w = fmaf(v, xv.w, acc.w);
    }
    float4 b = __ldg((const float4*)bias + lane);
    acc.x += b.x; acc.y += b.y; acc.z += b.z; acc.w += b.w;
    if (relu) {
        acc.x = fmaxf(acc.x, 0.f); acc.y = fmaxf(acc.y, 0.f);
        acc.z = fmaxf(acc.z, 0.f); acc.w = fmaxf(acc.w, 0.f);
    }
    *((float4*)(Y + (size_t)row * 128) + lane) = acc;
}

// ---------------- CSR SpMM, 40 cols, warp per row ----------------
__global__ void spmm40(const int* __restrict__ off, const int* __restrict__ srcs,
                       const float* __restrict__ vals, const float* __restrict__ X,
                       const float* __restrict__ bias, float* __restrict__ Y, int n) {
    int row = blockIdx.x * blockDim.y + threadIdx.y;
    if (row >= n) return;
    int lane = threadIdx.x;
    int s = off[row], e = off[row + 1];
    float a0 = 0.f, a1 = 0.f;
    for (int j = s; j < e; j++) {
        int src = __ldg(&srcs[j]);
        float v = __ldg(&vals[j]);
        a0 = fmaf(v, __ldg(&X[(size_t)src * 40 + lane]), a0);
        if (lane < 8) a1 = fmaf(v, __ldg(&X[(size_t)src * 40 + 32 + lane]), a1);
    }
    Y[(size_t)row * 40 + lane] = a0 + __ldg(&bias[lane]);
    if (lane < 8) Y[(size_t)row * 40 + 32 + lane] = a1 + __ldg(&bias[32 + lane]);
}

// ---------------- CRF refinement: warp per dst row, online softmax ----------------
__global__ void crf_refine(const int* __restrict__ off, const int* __restrict__ srcs,
                           const float* __restrict__ Q, const float* __restrict__ Km,
                           const float* __restrict__ H0,
                           const float* __restrict__ alpha_p, const float* __restrict__ beta_p,
                           float* __restrict__ Out, int n) {
    int row = blockIdx.x * blockDim.y + threadIdx.y;
    if (row >= n) return;
    int lane = threadIdx.x;
    float4 q = __ldg((const float4*)(Q + (size_t)row * 128) + lane);
    int s = off[row], e = off[row + 1];
    float m = -3.4e38f, z = 0.f;
    float4 macc = make_float4(0.f, 0.f, 0.f, 0.f);
    for (int j = s; j < e; j++) {
        int src = __ldg(&srcs[j]);
        float4 kv = __ldg((const float4*)(Km + (size_t)src * 128) + lane);
        float p = q.x * kv.x + q.y * kv.y + q.z * kv.z + q.w * kv.w;
        #pragma unroll
        for (int o = 16; o; o >>= 1) p += __shfl_xor_sync(0xffffffffu, p, o);
        p *= 0.08838834764831845f;
        float4 hv = __ldg((const float4*)(H0 + (size_t)src * 128) + lane);
        if (p > m) {
            float sc = __expf(m - p);
            z *= sc; macc.x *= sc; macc.y *= sc; macc.z *= sc; macc.w *= sc;
            m = p;
        }
        float w = __expf(p - m);
        z += w;
        macc.x = fmaf(w, hv.x, macc.x); macc.y = fmaf(w, hv.y, macc.y);
        macc.z = fmaf(w, hv.z, macc.z); macc.w = fmaf(w, hv.w, macc.w);
    }
    float alpha = __ldg(alpha_p), beta = __ldg(beta_p);
    float4 h0d = __ldg((const float4*)(H0 + (size_t)row * 128) + lane);
    float invz = 1.f / (z + 1e-16f);
    float invab = 1.f / (alpha + beta);
    float4 r;
    r.x = (alpha * h0d.x + beta * macc.x * invz) * invab;
    r.y = (alpha * h0d.y + beta * macc.y * invz) * invab;
    r.z = (alpha * h0d.z + beta * macc.z * invz) * invab;
    r.w = (alpha * h0d.w + beta * macc.w * invz) * invab;
    *((float4*)(Out + (size_t)row * 128) + lane) = r;
}

// ---------------- streams/events (created at static init) ----------------
struct StreamEnv {
    cudaStream_t sB, sK;
    cudaEvent_t evF, evB;
    StreamEnv() {
        cudaStreamCreateWithFlags(&sB, cudaStreamNonBlocking);
        cudaStreamCreateWithFlags(&sK, cudaStreamNonBlocking);
        cudaEventCreateWithFlags(&evF,  cudaEventDisableTiming);
        cudaEventCreateWithFlags(&evB,  cudaEventDisableTiming);
    }
};
static StreamEnv g_se;

// ---------------- host ----------------
extern "C" void kernel_launch(void* const* d_in, const int* in_sizes, int n_in,
                              void* d_out, int out_size) {
    const float* x       = (const float*)d_in[0];
    const int*   A0      = (const int*)d_in[1];
    const float* A0v     = (const float*)d_in[2];
    const int*   A1      = (const int*)d_in[3];
    const float* A1v     = (const float*)d_in[4];
    const int*   A2      = (const int*)d_in[5];
    const float* A2v     = (const float*)d_in[6];
    const int*   assign0 = (const int*)d_in[7];
    const int*   assign1 = (const int*)d_in[8];
    const int*   nwgt1   = (const int*)d_in[9];
    const int*   nwgt2   = (const int*)d_in[10];
    const float* gc1b    = (const float*)d_in[12];
    const float* gc2b    = (const float*)d_in[14];
    const float* c1emb   = (const float*)d_in[17];
    const float* c1a     = (const float*)d_in[18];
    const float* c1be    = (const float*)d_in[19];
    const float* c2emb   = (const float*)d_in[22];
    const float* c2a     = (const float*)d_in[23];
    const float* c2be    = (const float*)d_in[24];

    float* out_sec = (float*)d_out;
    float* gcn_sec = out_sec + (size_t)N0c * NCc;
    float* crf_sec = gcn_sec + (size_t)N0c * NFc;

    void* fp; cudaGetSymbolAddress(&fp, g_f);
    void* ip; cudaGetSymbolAddress(&ip, g_i);
    void* wp; cudaGetSymbolAddress(&wp, g_wt);
    float* F = (float*)fp;
    int*   I = (int*)ip;
    __nv_bfloat16* WT = (__nv_bfloat16*)wp;

    float* xW  = F + F_XW;  float* T   = F + F_T;
    float* H01 = F + F_H01;
    float* Q1  = F + F_Q1;  float* K1  = F + F_K1;
    float* H1R = F + F_H1R;
    float* H02 = F + F_H02;
    float* Q2  = F + F_Q2;  float* K2  = F + F_K2;
    float* H2R = F + F_H2R;
    float* V0  = F + F_VAL0;

    int* OFF0 = I + I_OFF0; int* SRC0 = I + I_SRC0;
    int* OFF1 = I + I_OFF1; int* SRC1 = I + I_SRC1;
    int* OFF2 = I + I_OFF2; int* SRC2 = I + I_SRC2;
    int* POF0 = I + I_POF0; int* PID0 = I + I_PID0;
    int* POF1 = I + I_POF1; int* PID1 = I + I_PID1;

    __nv_bfloat16* WT_gc1 = WT + 0 * 32768;
    __nv_bfloat16* WT_q1  = WT + 1 * 32768;
    __nv_bfloat16* WT_k1  = WT + 2 * 32768;
    __nv_bfloat16* WT_q2  = WT + 3 * 32768;
    __nv_bfloat16* WT_k2  = WT + 4 * 32768;

    const int SMEM_G  = 26112 * 4;   // 104448
    const int SMEM_QK = 43520 * 4;   // 174080
    const int SMEM_40 = 17408 * 4;   // 69632

    static bool attr_done = false;
    if (!attr_done) {
        cudaFuncSetAttribute(gemm_mma, cudaFuncAttributeMaxDynamicSharedMemorySize, SMEM_G);
        cudaFuncSetAttribute(gemm_qk_pool, cudaFuncAttributeMaxDynamicSharedMemorySize, SMEM_QK);
        cudaFuncSetAttribute(gemm40_mma, cudaFuncAttributeMaxDynamicSharedMemorySize, SMEM_40);
        attr_done = true;
    }

    dim3 warp8(32, 8);
    cudaStream_t s0 = 0;
    cudaStream_t sB = g_se.sB;

    cudaEventRecord(g_se.evF, s0);
    cudaStreamWaitEvent(sB, g_se.evF, 0);

    // enqueue order keeps gemm_mma(gc1) as 4th launch for ncu
    wprep_all<<<340, 256, 0, s0>>>((const float*)d_in[11], (const float*)d_in[15],
                                   (const float*)d_in[16], (const float*)d_in[20],
                                   (const float*)d_in[21], (const float*)d_in[13]);
    kzero_all<<<(162500 + 255) / 256, 256, 0, sB>>>();
    khist_all<<<(2225000 + 255) / 256, 256, 0, sB>>>(A0, A1, A2, assign0, assign1);
    gemm_mma<<<(N0c + 63) / 64, 256, SMEM_G, s0>>>(x, WT_gc1, xW, N0c);
    scan_blk_all<<<SCAN_BLOCKS, 1024, 0, sB>>>();
    scan_part_all<<<5, 128, 0, sB>>>();
    scan_add_all<<<SCAN_BLOCKS, 1024, 0, sB>>>();
    kscatter_all<<<(2225000 + 255) / 256, 256, 0, sB>>>(A0, A0v, A1, A1v, A2, A2v,
                                                        assign0, assign1);
    cudaEventRecord(g_se.evB, sB);

    cudaStreamWaitEvent(s0, g_se.evB, 0);
    spmm128<<<(N0c + 7) / 8, warp8, 0, s0>>>(OFF0, SRC0, V0, xW, gc1b, gcn_sec, N0c, 1);

    // level 1: fused pool + QK GEMM, then CRF
    gemm_qk_pool<<<(N1c + 63) / 64, 256, SMEM_QK, s0>>>(POF0, PID0, gcn_sec, nwgt1,
                                                        c1emb, WT_q1, WT_k1,
                                                        H01, Q1, K1, N1c);
    crf_refine<<<(N1c + 7) / 8, warp8, 0, s0>>>(OFF1, SRC1, Q1, K1, H01, c1a, c1be,
                                                H1R, N1c);

    // level 2: fused pool + QK GEMM, then CRF
    gemm_qk_pool<<<(N2c + 63) / 64, 256, SMEM_QK, s0>>>(POF1, PID1, H1R, nwgt2,
                                                        c2emb, WT_q2, WT_k2,
                                                        H02, Q2, K2, N2c);
    crf_refine<<<(N2c + 7) / 8, warp8, 0, s0>>>(OFF2, SRC2, Q2, K2, H02, c2a, c2be,
                                                H2R, N2c);

    // fused double unpool + gc2 GEMM
    gemm40_mma<<<(N0c + 63) / 64, 256, SMEM_40, s0>>>(H2R, assign1, H1R, assign0,
                                                      gcn_sec, crf_sec, T, N0c);
    spmm40<<<(N0c + 7) / 8, warp8, 0, s0>>>(OFF0, SRC0, V0, T, gc2b, out_sec, N0c);
}

// round 14
// speedup vs baseline: 1.0601x; 1.0601x over previous
#include <cuda_runtime.h>
#include <cuda_bf16.h>
#include <math.h>
#include <stdint.h>

#define N0c 100000
#define N1c 25000
#define N2c 6250
#define E0c 1600000
#define E1c 400000
#define E2c 100000
#define NFc 128
#define NCc 40

// ---------------- scratch (no allocations allowed) ----------------
constexpr size_t F_XW   = 0;
constexpr size_t F_T    = F_XW  + (size_t)N0c*NFc;
constexpr size_t F_H1   = F_T   + (size_t)N0c*NCc;
constexpr size_t F_H01  = F_H1  + (size_t)N1c*NFc;
constexpr size_t F_Q1   = F_H01 + (size_t)N1c*NFc;
constexpr size_t F_K1   = F_Q1  + (size_t)N1c*NFc;
constexpr size_t F_H1R  = F_K1  + (size_t)N1c*NFc;
constexpr size_t F_U1   = F_H1R + (size_t)N1c*NFc;
constexpr size_t F_H2   = F_U1  + (size_t)N1c*NFc;
constexpr size_t F_H02  = F_H2  + (size_t)N2c*NFc;
constexpr size_t F_Q2   = F_H02 + (size_t)N2c*NFc;
constexpr size_t F_K2   = F_Q2  + (size_t)N2c*NFc;
constexpr size_t F_H2R  = F_K2  + (size_t)N2c*NFc;
constexpr size_t F_VAL0 = F_H2R + (size_t)N2c*NFc;
constexpr size_t F_VAL1 = F_VAL0 + (size_t)E0c;
constexpr size_t F_VAL2 = F_VAL1 + (size_t)E1c;
constexpr size_t F_TOT  = F_VAL2 + (size_t)E2c;
__device__ __align__(16) float g_f[F_TOT];

constexpr size_t I_OFF0 = 0;
constexpr size_t I_CNT0 = I_OFF0 + (size_t)N0c + 4;
constexpr size_t I_SRC0 = I_CNT0 + (size_t)N0c;
constexpr size_t I_OFF1 = I_SRC0 + (size_t)E0c;
constexpr size_t I_CNT1 = I_OFF1 + (size_t)N1c + 4;
constexpr size_t I_SRC1 = I_CNT1 + (size_t)N1c;
constexpr size_t I_OFF2 = I_SRC1 + (size_t)E1c;
constexpr size_t I_CNT2 = I_OFF2 + (size_t)N2c + 4;
constexpr size_t I_SRC2 = I_CNT2 + (size_t)N2c;
constexpr size_t I_POF0 = I_SRC2 + (size_t)E2c;
constexpr size_t I_PID0 = I_POF0 + (size_t)N1c + 4;
constexpr size_t I_POF1 = I_PID0 + (size_t)N0c;
constexpr size_t I_PID1 = I_POF1 + (size_t)N2c + 4;
constexpr size_t I_PART = I_PID1 + (size_t)N1c;
constexpr size_t I_PCN1 = I_PART + 256;
constexpr size_t I_PCN2 = I_PCN1 + (size_t)N1c;
constexpr size_t I_TOT  = I_PCN2 + (size_t)N2c;
__device__ int g_i[I_TOT];

// split-bf16 weights: 6 slots x 32768 bf16 (slot5 = gc2W, 40x128 hi + lo)
__device__ __align__(16) __nv_bfloat16 g_wt[6 * 32768];

#define SCAN_BLOCKS 162
struct Seg { int* cnt; int* off; int* cur; int pbase; int n; int sblk; };
__device__ __forceinline__ Seg seg_resolve(int b) {
    Seg s;
    if (b < 98)       { s.cnt = g_i + I_CNT0; s.off = g_i + I_OFF0; s.cur = g_i + I_CNT0; s.pbase = 0;   s.n = N0c; s.sblk = b; }
    else if (b < 123) { s.cnt = g_i + I_CNT1; s.off = g_i + I_OFF1; s.cur = g_i + I_CNT1; s.pbase = 98;  s.n = N1c; s.sblk = b - 98; }
    else if (b < 130) { s.cnt = g_i + I_CNT2; s.off = g_i + I_OFF2; s.cur = g_i + I_CNT2; s.pbase = 123; s.n = N2c; s.sblk = b - 123; }
    else if (b < 155) { s.cnt = g_i + I_PCN1; s.off = g_i + I_POF0; s.cur = g_i + I_PCN1; s.pbase = 130; s.n = N1c; s.sblk = b - 130; }
    else              { s.cnt = g_i + I_PCN2; s.off = g_i + I_POF1; s.cur = g_i + I_PCN2; s.pbase = 155; s.n = N2c; s.sblk = b - 155; }
    return s;
}

// ---------------- mma helpers ----------------
__device__ __forceinline__ void mma16816(float* c, const uint32_t* a,
                                         uint32_t b0, uint32_t b1) {
    asm volatile(
        "mma.sync.aligned.m16n8k16.row.col.f32.bf16.bf16.f32 "
        "{%0,%1,%2,%3}, {%4,%5,%6,%7}, {%8,%9}, {%0,%1,%2,%3};"
        : "+f"(c[0]), "+f"(c[1]), "+f"(c[2]), "+f"(c[3])
        : "r"(a[0]), "r"(a[1]), "r"(a[2]), "r"(a[3]), "r"(b0), "r"(b1));
}
__device__ __forceinline__ void split_bf16(float a, float b, uint32_t& hi, uint32_t& lo) {
    __nv_bfloat16 ha = __float2bfloat16(a), hb = __float2bfloat16(b);
    __nv_bfloat162 hp; hp.x = ha; hp.y = hb;
    __nv_bfloat162 lp;
    lp.x = __float2bfloat16(a - __bfloat162float(ha));
    lp.y = __float2bfloat16(b - __bfloat162float(hb));
    hi = *(uint32_t*)&hp;
    lo = *(uint32_t*)&lp;
}

// ---------------- batched weight prep: 5 x [128,128] + gc2W [128,40] ----------------
__global__ void wprep_all(const float* __restrict__ w0, const float* __restrict__ w1,
                          const float* __restrict__ w2, const float* __restrict__ w3,
                          const float* __restrict__ w4, const float* __restrict__ w5) {
    int b = blockIdx.x;
    if (b < 320) {
        int seg = b >> 6;
        int t = ((b & 63) << 8) + threadIdx.x;
        if (t >= 16384) return;
        const float* W = (seg == 0) ? w0 : (seg == 1) ? w1 : (seg == 2) ? w2
                        : (seg == 3) ? w3 : w4;
        __nv_bfloat16* out = g_wt + (size_t)seg * 32768;
        int n = t >> 7, k = t & 127;
        float v = __ldg(&W[(size_t)k * 128 + n]);
        __nv_bfloat16 h = __float2bfloat16(v);
        out[t] = h;
        out[16384 + t] = __float2bfloat16(v - __bfloat162float(h));
    } else {
        int t = ((b - 320) << 8) + threadIdx.x;    // gc2W: 40x128 = 5120
        if (t >= 5120) return;
        __nv_bfloat16* out = g_wt + (size_t)5 * 32768;
        int n = t >> 7, k = t & 127;
        float v = __ldg(&w5[(size_t)k * 40 + n]);
        __nv_bfloat16 h = __float2bfloat16(v);
        out[t] = h;
        out[5120 + t] = __float2bfloat16(v - __bfloat162float(h));
    }
}

// ---------------- tensor-core GEMM: Y = X[M,128] @ W[128,128], split bf16 ----------------
// 64-row CTA tile, 256 threads (8 warps, 2x4 grid of 32x32 warp tiles), 2 CTAs/SM.
// Dual-output via blockIdx.y: y==0 -> (WA,Y1), y==1 -> (WB,Y2). WB may equal WA.
#define WROW 68
__global__ void __launch_bounds__(256, 2) gemm_mma(
    const float* __restrict__ X,
    const __nv_bfloat16* __restrict__ WA, const __nv_bfloat16* __restrict__ WB,
    float* __restrict__ Y1, float* __restrict__ Y2, int M)
{
    extern __shared__ uint32_t sm[];
    uint32_t* XH = sm;            // 64*68 = 4352
    uint32_t* XL = sm + 4352;
    uint32_t* BH = sm + 8704;     // 128*68 = 8704
    uint32_t* BL = sm + 17408;    // total 26112 u32 = 104448 B
    const int tid = threadIdx.x;
    const int row0 = blockIdx.x * 64;
    const __nv_bfloat16* W = (blockIdx.y == 0) ? WA : WB;
    float* Y = (blockIdx.y == 0) ? Y1 : Y2;

    for (int i = tid; i < 1024; i += 256) {
        int r = i >> 4, c8 = (i & 15) << 3;
        int gr = row0 + r;
        float4 v0 = make_float4(0.f, 0.f, 0.f, 0.f), v1 = v0;
        if (gr < M) {
            const float4* xp = (const float4*)(X + (size_t)gr * 128 + c8);
            v0 = __ldg(xp); v1 = __ldg(xp + 1);
        }
        uint32_t hi[4], lo[4];
        split_bf16(v0.x, v0.y, hi[0], lo[0]);
        split_bf16(v0.z, v0.w, hi[1], lo[1]);
        split_bf16(v1.x, v1.y, hi[2], lo[2]);
        split_bf16(v1.z, v1.w, hi[3], lo[3]);
        int si = r * WROW + (c8 >> 1);
        *(uint4*)(XH + si) = make_uint4(hi[0], hi[1], hi[2], hi[3]);
        *(uint4*)(XL + si) = make_uint4(lo[0], lo[1], lo[2], lo[3]);
    }
    {
        const uint4* wa = (const uint4*)W;
        for (int i = tid; i < 2048; i += 256) {
            int r = i >> 4, c4 = (i & 15) << 2;
            int si = r * WROW + c4;
            *(uint4*)(BH + si) = __ldg(wa + i);
            *(uint4*)(BL + si) = __ldg(wa + 2048 + i);
        }
    }
    __syncthreads();

    const int wid = tid >> 5, lane = tid & 31;
    const int wm = wid & 1, wn = wid >> 1;     // 2 x 4 warp grid
    const int g = lane >> 2, tq = lane & 3;

    float C[2][4][4];
    #pragma unroll
    for (int mt = 0; mt < 2; mt++)
        #pragma unroll
        for (int nt = 0; nt < 4; nt++)
            #pragma unroll
            for (int j = 0; j < 4; j++) C[mt][nt][j] = 0.f;

    #pragma unroll
    for (int ks = 0; ks < 8; ks++) {
        uint32_t Ah[2][4], Al[2][4];
        #pragma unroll
        for (int mt = 0; mt < 2; mt++) {
            int r0 = (wm * 32 + mt * 16 + g) * WROW + ks * 8 + tq;
            Ah[mt][0] = XH[r0];        Ah[mt][1] = XH[r0 + 8 * WROW];
            Ah[mt][2] = XH[r0 + 4];    Ah[mt][3] = XH[r0 + 8 * WROW + 4];
            Al[mt][0] = XL[r0];        Al[mt][1] = XL[r0 + 8 * WROW];
            Al[mt][2] = XL[r0 + 4];    Al[mt][3] = XL[r0 + 8 * WROW + 4];
        }
        #pragma unroll
        for (int nt = 0; nt < 4; nt++) {
            int bi = (wn * 32 + nt * 8 + g) * WROW + ks * 8 + tq;
            uint32_t bh0 = BH[bi], bh1 = BH[bi + 4];
            uint32_t bl0 = BL[bi], bl1 = BL[bi + 4];
            #pragma unroll
            for (int mt = 0; mt < 2; mt++) {
                mma16816(C[mt][nt], Ah[mt], bh0, bh1);
                mma16816(C[mt][nt], Ah[mt], bl0, bl1);
                mma16816(C[mt][nt], Al[mt], bh0, bh1);
            }
        }
    }
    #pragma unroll
    for (int mt = 0; mt < 2; mt++) {
        int row = row0 + wm * 32 + mt * 16 + g;
        #pragma unroll
        for (int nt = 0; nt < 4; nt++) {
            int col = wn * 32 + nt * 8 + tq * 2;
            if (row < M)
                *(float2*)(Y + (size_t)row * 128 + col) =
                    make_float2(C[mt][nt][0], C[mt][nt][1]);
            if (row + 8 < M)
                *(float2*)(Y + (size_t)(row + 8) * 128 + col) =
                    make_float2(C[mt][nt][2], C[mt][nt][3]);
        }
    }
}

// ---- fused: crf = U1[assign0[row]] + gcn[row]; write crf_sec; T = crf @ gc2W (mma) ----
__global__ void __launch_bounds__(256, 2) gemm40_mma(
    const float* __restrict__ U1, const int* __restrict__ assign0,
    const float* __restrict__ gcn, float* __restrict__ crf_out,
    float* __restrict__ Y, int M)
{
    extern __shared__ uint32_t sm[];
    uint32_t* XH = sm;
    uint32_t* XL = sm + 4352;
    uint32_t* BH = sm + 8704;
    uint32_t* BL = sm + 13056;
    const int tid = threadIdx.x;
    const int row0 = blockIdx.x * 64;
    const __nv_bfloat16* W40 = g_wt + (size_t)5 * 32768;

    for (int i = tid; i < 1024; i += 256) {
        int r = i >> 4, c8 = (i & 15) << 3;
        int gr = row0 + r;
        float4 v0 = make_float4(0.f, 0.f, 0.f, 0.f), v1 = v0;
        if (gr < M) {
            int a = __ldg(&assign0[gr]);
            const float4* up = (const float4*)(U1 + (size_t)a * 128 + c8);
            const float4* gp = (const float4*)(gcn + (size_t)gr * 128 + c8);
            float4 u0 = __ldg(up), u1 = __ldg(up + 1);
            float4 g0 = __ldg(gp), g1 = __ldg(gp + 1);
            v0.x = u0.x + g0.x; v0.y = u0.y + g0.y; v0.z = u0.z + g0.z; v0.w = u0.w + g0.w;
            v1.x = u1.x + g1.x; v1.y = u1.y + g1.y; v1.z = u1.z + g1.z; v1.w = u1.w + g1.w;
            float4* cp = (float4*)(crf_out + (size_t)gr * 128 + c8);
            cp[0] = v0; cp[1] = v1;
        }
        uint32_t hi[4], lo[4];
        split_bf16(v0.x, v0.y, hi[0], lo[0]);
        split_bf16(v0.z, v0.w, hi[1], lo[1]);
        split_bf16(v1.x, v1.y, hi[2], lo[2]);
        split_bf16(v1.z, v1.w, hi[3], lo[3]);
        int si = r * WROW + (c8 >> 1);
        *(uint4*)(XH + si) = make_uint4(hi[0], hi[1], hi[2], hi[3]);
        *(uint4*)(XL + si) = make_uint4(lo[0], lo[1], lo[2], lo[3]);
    }
    {
        const uint4* wh = (const uint4*)W40;
        const uint4* wl = (const uint4*)(W40 + 5120);
        for (int i = tid; i < 1024; i += 256) {
            int r = i >> 4, c4 = (i & 15) << 2;
            int si = r * WROW + c4;
            uint4 h = make_uint4(0, 0, 0, 0), l = h;
            if (r < 40) { h = __ldg(wh + i); l = __ldg(wl + i); }
            *(uint4*)(BH + si) = h;
            *(uint4*)(BL + si) = l;
        }
    }
    __syncthreads();

    const int wid = tid >> 5, lane = tid & 31;
    const int wm = wid & 3, wn = wid >> 2;     // 4x2 grid; 16x32 warp tiles
    const int g = lane >> 2, tq = lane & 3;

    float C[4][4];
    #pragma unroll
    for (int nt = 0; nt < 4; nt++)
        #pragma unroll
        for (int j = 0; j < 4; j++) C[nt][j] = 0.f;

    #pragma unroll
    for (int ks = 0; ks < 8; ks++) {
        uint32_t Ah[4], Al[4];
        int r0 = (wm * 16 + g) * WROW + ks * 8 + tq;
        Ah[0] = XH[r0];        Ah[1] = XH[r0 + 8 * WROW];
        Ah[2] = XH[r0 + 4];    Ah[3] = XH[r0 + 8 * WROW + 4];
        Al[0] = XL[r0];        Al[1] = XL[r0 + 8 * WROW];
        Al[2] = XL[r0 + 4];    Al[3] = XL[r0 + 8 * WROW + 4];
        #pragma unroll
        for (int nt = 0; nt < 4; nt++) {
            int bi = (wn * 32 + nt * 8 + g) * WROW + ks * 8 + tq;
            uint32_t bh0 = BH[bi], bh1 = BH[bi + 4];
            uint32_t bl0 = BL[bi], bl1 = BL[bi + 4];
            mma16816(C[nt], Ah, bh0, bh1);
            mma16816(C[nt], Ah, bl0, bl1);
            mma16816(C[nt], Al, bh0, bh1);
        }
    }
    {
        int row = row0 + wm * 16 + g;
        #pragma unroll
        for (int nt = 0; nt < 4; nt++) {
            int col = wn * 32 + nt * 8 + tq * 2;
            if (col < 40) {
                if (row < M)
                    *(float2*)(Y + (size_t)row * 40 + col) = make_float2(C[nt][0], C[nt][1]);
                if (row + 8 < M)
                    *(float2*)(Y + (size_t)(row + 8) * 40 + col) = make_float2(C[nt][2], C[nt][3]);
            }
        }
    }
}

// ---------------- batched CSR build kernels ----------------
__global__ void kzero_all() {
    int i = blockIdx.x * 256 + threadIdx.x;
    if (i < 100000)      g_i[I_CNT0 + i] = 0;
    else if (i < 125000) g_i[I_CNT1 + (i - 100000)] = 0;
    else if (i < 131250) g_i[I_CNT2 + (i - 125000)] = 0;
    else if (i < 156250) g_i[I_PCN1 + (i - 131250)] = 0;
    else if (i < 162500) g_i[I_PCN2 + (i - 156250)] = 0;
}
__global__ void khist_all(const int* __restrict__ A0, const int* __restrict__ A1,
                          const int* __restrict__ A2, const int* __restrict__ as0,
                          const int* __restrict__ as1) {
    int i = blockIdx.x * 256 + threadIdx.x;
    if (i < 1600000)      atomicAdd(&g_i[I_CNT0 + __ldg(&A0[i])], 1);
    else if (i < 2000000) atomicAdd(&g_i[I_CNT1 + __ldg(&A1[i - 1600000])], 1);
    else if (i < 2100000) atomicAdd(&g_i[I_CNT2 + __ldg(&A2[i - 2000000])], 1);
    else if (i < 2200000) atomicAdd(&g_i[I_PCN1 + __ldg(&as0[i - 2100000])], 1);
    else if (i < 2225000) atomicAdd(&g_i[I_PCN2 + __ldg(&as1[i - 2200000])], 1);
}
__global__ void scan_blk_all() {
    __shared__ int wsum[32];
    Seg s = seg_resolve(blockIdx.x);
    int t = threadIdx.x;
    int i = s.sblk * 1024 + t;
    int v = (i < s.n) ? s.cnt[i] : 0;
    int x = v;
    #pragma unroll
    for (int o = 1; o < 32; o <<= 1) {
        int tmp = __shfl_up_sync(0xffffffffu, x, o);
        if ((t & 31) >= o) x += tmp;
    }
    if ((t & 31) == 31) wsum[t >> 5] = x;
    __syncthreads();
    if (t < 32) {
        int y = wsum[t];
        #pragma unroll
        for (int o = 1; o < 32; o <<= 1) {
            int tmp = __shfl_up_sync(0xffffffffu, y, o);
            if (t >= o) y += tmp;
        }
        wsum[t] = y;
    }
    __syncthreads();
    int base = (t >= 32) ? wsum[(t >> 5) - 1] : 0;
    int incl = base + x;
    if (i < s.n) s.off[i] = incl - v;
    if (t == 1023) g_i[I_PART + s.pbase + s.sblk] = incl;
}
__global__ void scan_part_all() {
    __shared__ int sh[128];
    const int bases[5] = {0, 98, 123, 130, 155};
    const int cnts[5]  = {98, 25, 7, 25, 7};
    int b = blockIdx.x, t = threadIdx.x;
    int* part = g_i + I_PART + bases[b];
    int nb = cnts[b];
    int v = (t < nb) ? part[t] : 0;
    sh[t] = v;
    __syncthreads();
    #pragma unroll
    for (int o = 1; o < 128; o <<= 1) {
        int tmp = (t >= o) ? sh[t - o] : 0;
        __syncthreads();
        sh[t] += tmp;
        __syncthreads();
    }
    if (t < nb) part[t] = sh[t] - v;
    if (t == 0) {
        int total = sh[127];
        int* off = (b == 0) ? g_i + I_OFF0 : (b == 1) ? g_i + I_OFF1
                 : (b == 2) ? g_i + I_OFF2 : (b == 3) ? g_i + I_POF0 : g_i + I_POF1;
        int n = (b == 0) ? N0c : (b == 1) ? N1c : (b == 2) ? N2c
              : (b == 3) ? N1c : N2c;
        off[n] = total;
    }
}
__global__ void scan_add_all() {
    Seg s = seg_resolve(blockIdx.x);
    int i = s.sblk * 1024 + threadIdx.x;
    if (i < s.n) {
        int v = s.off[i] + g_i[I_PART + s.pbase + s.sblk];
        s.off[i] = v;
        s.cur[i] = v;
    }
}
__global__ void kscatter_all(const int* __restrict__ A0, const float* __restrict__ A0v,
                             const int* __restrict__ A1, const float* __restrict__ A1v,
                             const int* __restrict__ A2, const float* __restrict__ A2v,
                             const int* __restrict__ as0, const int* __restrict__ as1) {
    int i = blockIdx.x * 256 + threadIdx.x;
    if (i < 1600000) {
        int pos = atomicAdd(&g_i[I_CNT0 + __ldg(&A0[i])], 1);
        g_i[I_SRC0 + pos] = __ldg(&A0[1600000 + i]);
        g_f[F_VAL0 + pos] = __ldg(&A0v[i]);
    } else if (i < 2000000) {
        int e = i - 1600000;
        int pos = atomicAdd(&g_i[I_CNT1 + __ldg(&A1[e])], 1);
        g_i[I_SRC1 + pos] = __ldg(&A1[400000 + e]);
        g_f[F_VAL1 + pos] = __ldg(&A1v[e]);
    } else if (i < 2100000) {
        int e = i - 2000000;
        int pos = atomicAdd(&g_i[I_CNT2 + __ldg(&A2[e])], 1);
        g_i[I_SRC2 + pos] = __ldg(&A2[100000 + e]);
        g_f[F_VAL2 + pos] = __ldg(&A2v[e]);
    } else if (i < 2200000) {
        int e = i - 2100000;
        int pos = atomicAdd(&g_i[I_PCN1 + __ldg(&as0[e])], 1);
        g_i[I_PID0 + pos] = e;
    } else if (i < 2225000) {
        int e = i - 2200000;
        int pos = atomicAdd(&g_i[I_PCN2 + __ldg(&as1[e])], 1);
        g_i[I_PID1 + pos] = e;
    }
}

// ---------------- CSR SpMM, 128 cols, warp per row ----------------
__global__ void spmm128(const int* __restrict__ off, const int* __restrict__ srcs,
                        const float* __restrict__ vals, const float* __restrict__ X,
                        const float* __restrict__ bias, float* __restrict__ Y,
                        int n, int relu) {
    int row = blockIdx.x * blockDim.y + threadIdx.y;
    if (row >= n) return;
    int lane = threadIdx.x;
    int s = off[row], e = off[row + 1];
    float4 acc = make_float4(0.f, 0.f, 0.f, 0.f);
    for (int j = s; j < e; j++) {
        int src = __ldg(&srcs[j]);
        float v = __ldg(&vals[j]);
        float4 xv = __ldg((const float4*)(X + (size_t)src * 128) + lane);
        acc.x = fmaf(v, xv.x, acc.x); acc.y = fmaf(v, xv.y, acc.y);
        acc.z = fmaf(v, xv.z, acc.z); acc.w = fmaf(v, xv.w, acc.w);
    }
    float4 b = __ldg((const float4*)bias + lane);
    acc.x += b.x; acc.y += b.y; acc.z += b.z; acc.w += b.w;
    if (relu) {
        acc.x = fmaxf(acc.x, 0.f); acc.y = fmaxf(acc.y, 0.f);
        acc.z = fmaxf(acc.z, 0.f); acc.w = fmaxf(acc.w, 0.f);
    }
    *((float4*)(Y + (size_t)row * 128) + lane) = acc;
}

// ---------------- CSR SpMM, 40 cols, warp per row ----------------
__global__ void spmm40(const int* __restrict__ off, const int* __restrict__ srcs,
                       const float* __restrict__ vals, const float* __restrict__ X,
                       const float* __restrict__ bias, float* __restrict__ Y, int n) {
    int row = blockIdx.x * blockDim.y + threadIdx.y;
    if (row >= n) return;
    int lane = threadIdx.x;
    int s = off[row], e = off[row + 1];
    float a0 = 0.f, a1 = 0.f;
    for (int j = s; j < e; j++) {
        int src = __ldg(&srcs[j]);
        float v = __ldg(&vals[j]);
        a0 = fmaf(v, __ldg(&X[(size_t)src * 40 + lane]), a0);
        if (lane < 8) a1 = fmaf(v, __ldg(&X[(size_t)src * 40 + 32 + lane]), a1);
    }
    Y[(size_t)row * 40 + lane] = a0 + __ldg(&bias[lane]);
    if (lane < 8) Y[(size_t)row * 40 + 32 + lane] = a1 + __ldg(&bias[32 + lane]);
}

// ---------------- pooling via CSR gather + fused emb add ----------------
__global__ void pool_gather(const int* __restrict__ off, const int* __restrict__ ids,
                            const float* __restrict__ X,
                            const int* __restrict__ nw, const float* __restrict__ emb,
                            float* __restrict__ H, float* __restrict__ H0, int n) {
    int row = blockIdx.x * blockDim.y + threadIdx.y;
    if (row >= n) return;
    int lane = threadIdx.x;
    int s = off[row], e = off[row + 1];
    float4 acc = make_float4(0.f, 0.f, 0.f, 0.f);
    for (int j = s; j < e; j++) {
        int node = __ldg(&ids[j]);
        float4 v = __ldg((const float4*)(X + (size_t)node * 128) + lane);
        acc.x += v.x; acc.y += v.y; acc.z += v.z; acc.w += v.w;
    }
    *((float4*)(H + (size_t)row * 128) + lane) = acc;
    int w = __ldg(&nw[row]);
    float4 em = __ldg((const float4*)(emb + (size_t)w * 128) + lane);
    acc.x += em.x; acc.y += em.y; acc.z += em.z; acc.w += em.w;
    *((float4*)(H0 + (size_t)row * 128) + lane) = acc;
}

// ---------------- CRF refinement: warp per dst row, online softmax ----------------
__global__ void crf_refine(const int* __restrict__ off, const int* __restrict__ srcs,
                           const float* __restrict__ Q, const float* __restrict__ Km,
                           const float* __restrict__ H0,
                           const float* __restrict__ alpha_p, const float* __restrict__ beta_p,
                           float* __restrict__ Out, int n) {
    int row = blockIdx.x * blockDim.y + threadIdx.y;
    if (row >= n) return;
    int lane = threadIdx.x;
    float4 q = __ldg((const float4*)(Q + (size_t)row * 128) + lane);
    int s = off[row], e = off[row + 1];
    float m = -3.4e38f, z = 0.f;
    float4 macc = make_float4(0.f, 0.f, 0.f, 0.f);
    for (int j = s; j < e; j++) {
        int src = __ldg(&srcs[j]);
        float4 kv = __ldg((const float4*)(Km + (size_t)src * 128) + lane);
        float p = q.x * kv.x + q.y * kv.y + q.z * kv.z + q.w * kv.w;
        #pragma unroll
        for (int o = 16; o; o >>= 1) p += __shfl_xor_sync(0xffffffffu, p, o);
        p *= 0.08838834764831845f;
        float4 hv = __ldg((const float4*)(H0 + (size_t)src * 128) + lane);
        if (p > m) {
            float sc = __expf(m - p);
            z *= sc; macc.x *= sc; macc.y *= sc; macc.z *= sc; macc.w *= sc;
            m = p;
        }
        float w = __expf(p - m);
        z += w;
        macc.x = fmaf(w, hv.x, macc.x); macc.y = fmaf(w, hv.y, macc.y);
        macc.z = fmaf(w, hv.z, macc.z); macc.w = fmaf(w, hv.w, macc.w);
    }
    float alpha = __ldg(alpha_p), beta = __ldg(beta_p);
    float4 h0d = __ldg((const float4*)(H0 + (size_t)row * 128) + lane);
    float invz = 1.f / (z + 1e-16f);
    float invab = 1.f / (alpha + beta);
    float4 r;
    r.x = (alpha * h0d.x + beta * macc.x * invz) * invab;
    r.y = (alpha * h0d.y + beta * macc.y * invz) * invab;
    r.z = (alpha * h0d.z + beta * macc.z * invz) * invab;
    r.w = (alpha * h0d.w + beta * macc.w * invz) * invab;
    *((float4*)(Out + (size_t)row * 128) + lane) = r;
}

// ---------------- unpool + skip ----------------
__global__ void unpool_add(const float* __restrict__ Hi, const int* __restrict__ assign,
                           const float* __restrict__ skip, float* __restrict__ Out, int n) {
    int i = blockIdx.x * blockDim.y + threadIdx.y;
    if (i >= n) return;
    int lane = threadIdx.x;
    int a = assign[i];
    float4 v = __ldg((const float4*)(Hi + (size_t)a * 128) + lane);
    float4 sk = *((const float4*)(skip + (size_t)i * 128) + lane);
    v.x += sk.x; v.y += sk.y; v.z += sk.z; v.w += sk.w;
    *((float4*)(Out + (size_t)i * 128) + lane) = v;
}

// ---------------- streams/events (created at static init) ----------------
struct StreamEnv {
    cudaStream_t sB;
    cudaEvent_t evF, evB;
    StreamEnv() {
        cudaStreamCreateWithFlags(&sB, cudaStreamNonBlocking);
        cudaEventCreateWithFlags(&evF, cudaEventDisableTiming);
        cudaEventCreateWithFlags(&evB, cudaEventDisableTiming);
    }
};
static StreamEnv g_se;

// ---------------- host ----------------
extern "C" void kernel_launch(void* const* d_in, const int* in_sizes, int n_in,
                              void* d_out, int out_size) {
    const float* x       = (const float*)d_in[0];
    const int*   A0      = (const int*)d_in[1];
    const float* A0v     = (const float*)d_in[2];
    const int*   A1      = (const int*)d_in[3];
    const float* A1v     = (const float*)d_in[4];
    const int*   A2      = (const int*)d_in[5];
    const float* A2v     = (const float*)d_in[6];
    const int*   assign0 = (const int*)d_in[7];
    const int*   assign1 = (const int*)d_in[8];
    const int*   nwgt1   = (const int*)d_in[9];
    const int*   nwgt2   = (const int*)d_in[10];
    const float* gc1b    = (const float*)d_in[12];
    const float* gc2b    = (const float*)d_in[14];
    const float* c1emb   = (const float*)d_in[17];
    const float* c1a     = (const float*)d_in[18];
    const float* c1be    = (const float*)d_in[19];
    const float* c2emb   = (const float*)d_in[22];
    const float* c2a     = (const float*)d_in[23];
    const float* c2be    = (const float*)d_in[24];

    float* out_sec = (float*)d_out;
    float* gcn_sec = out_sec + (size_t)N0c * NCc;
    float* crf_sec = gcn_sec + (size_t)N0c * NFc;

    void* fp; cudaGetSymbolAddress(&fp, g_f);
    void* ip; cudaGetSymbolAddress(&ip, g_i);
    void* wp; cudaGetSymbolAddress(&wp, g_wt);
    float* F = (float*)fp;
    int*   I = (int*)ip;
    __nv_bfloat16* WT = (__nv_bfloat16*)wp;

    float* xW  = F + F_XW;  float* T   = F + F_T;
    float* H1  = F + F_H1;  float* H01 = F + F_H01;
    float* Q1  = F + F_Q1;  float* K1  = F + F_K1;
    float* H1R = F + F_H1R; float* U1  = F + F_U1;
    float* H2  = F + F_H2;  float* H02 = F + F_H02;
    float* Q2  = F + F_Q2;  float* K2  = F + F_K2;
    float* H2R = F + F_H2R;
    float* V0  = F + F_VAL0;

    int* OFF0 = I + I_OFF0; int* SRC0 = I + I_SRC0;
    int* OFF1 = I + I_OFF1; int* SRC1 = I + I_SRC1;
    int* OFF2 = I + I_OFF2; int* SRC2 = I + I_SRC2;
    int* POF0 = I + I_POF0; int* PID0 = I + I_PID0;
    int* POF1 = I + I_POF1; int* PID1 = I + I_PID1;

    __nv_bfloat16* WT_gc1 = WT + 0 * 32768;
    __nv_bfloat16* WT_q1  = WT + 1 * 32768;
    __nv_bfloat16* WT_k1  = WT + 2 * 32768;
    __nv_bfloat16* WT_q2  = WT + 3 * 32768;
    __nv_bfloat16* WT_k2  = WT + 4 * 32768;

    const int SMEM_G  = 26112 * 4;
    const int SMEM_40 = 17408 * 4;

    static bool attr_done = false;
    if (!attr_done) {
        cudaFuncSetAttribute(gemm_mma, cudaFuncAttributeMaxDynamicSharedMemorySize, SMEM_G);
        cudaFuncSetAttribute(gemm40_mma, cudaFuncAttributeMaxDynamicSharedMemorySize, SMEM_40);
        attr_done = true;
    }

    dim3 warp8(32, 8);
    cudaStream_t s0 = 0;
    cudaStream_t sB = g_se.sB;

    cudaEventRecord(g_se.evF, s0);
    cudaStreamWaitEvent(sB, g_se.evF, 0);

    // enqueue order keeps gemm_mma(gc1) as 4th launch for ncu
    wprep_all<<<340, 256, 0, s0>>>((const float*)d_in[11], (const float*)d_in[15],
                                   (const float*)d_in[16], (const float*)d_in[20],
                                   (const float*)d_in[21], (const float*)d_in[13]);
    kzero_all<<<(162500 + 255) / 256, 256, 0, sB>>>();
    khist_all<<<(2225000 + 255) / 256, 256, 0, sB>>>(A0, A1, A2, assign0, assign1);
    gemm_mma<<<dim3((N0c + 63) / 64, 1), 256, SMEM_G, s0>>>(x, WT_gc1, WT_gc1,
                                                            xW, xW, N0c);
    scan_blk_all<<<SCAN_BLOCKS, 1024, 0, sB>>>();
    scan_part_all<<<5, 128, 0, sB>>>();
    scan_add_all<<<SCAN_BLOCKS, 1024, 0, sB>>>();
    kscatter_all<<<(2225000 + 255) / 256, 256, 0, sB>>>(A0, A0v, A1, A1v, A2, A2v,
                                                        assign0, assign1);
    cudaEventRecord(g_se.evB, sB);

    cudaStreamWaitEvent(s0, g_se.evB, 0);
    spmm128<<<(N0c + 7) / 8, warp8, 0, s0>>>(OFF0, SRC0, V0, xW, gc1b, gcn_sec, N0c, 1);

    // level 1: pool + dual QK GEMM (one launch, gridDim.y=2) + CRF
    pool_gather<<<(N1c + 7) / 8, warp8, 0, s0>>>(POF0, PID0, gcn_sec, nwgt1, c1emb,
                                                 H1, H01, N1c);
    gemm_mma<<<dim3((N1c + 63) / 64, 2), 256, SMEM_G, s0>>>(H1, WT_q1, WT_k1,
                                                            Q1, K1, N1c);
    crf_refine<<<(N1c + 7) / 8, warp8, 0, s0>>>(OFF1, SRC1, Q1, K1, H01, c1a, c1be,
                                                H1R, N1c);

    // level 2: pool + dual QK GEMM + CRF
    pool_gather<<<(N2c + 7) / 8, warp8, 0, s0>>>(POF1, PID1, H1R, nwgt2, c2emb,
                                                 H2, H02, N2c);
    gemm_mma<<<dim3((N2c + 63) / 64, 2), 256, SMEM_G, s0>>>(H2, WT_q2, WT_k2,
                                                            Q2, K2, N2c);
    crf_refine<<<(N2c + 7) / 8, warp8, 0, s0>>>(OFF2, SRC2, Q2, K2, H02, c2a, c2be,
                                                H2R, N2c);

    // unpool level 2->1
    unpool_add<<<(N1c + 7) / 8, warp8, 0, s0>>>(H2R, assign1, H1R, U1, N1c);

    // fused unpool 1->0 + gc2 GEMM
    gemm40_mma<<<(N0c + 63) / 64, 256, SMEM_40, s0>>>(U1, assign0, gcn_sec, crf_sec,
                                                      T, N0c);
    spmm40<<<(N0c + 7) / 8, warp8, 0, s0>>>(OFF0, SRC0, V0, T, gc2b, out_sec, N0c);
}

// round 15
// speedup vs baseline: 1.0757x; 1.0147x over previous
#include <cuda_runtime.h>
#include <cuda_bf16.h>
#include <math.h>
#include <stdint.h>

#define N0c 100000
#define N1c 25000
#define N2c 6250
#define E0c 1600000
#define E1c 400000
#define E2c 100000
#define NFc 128
#define NCc 40

// ---------------- scratch (no allocations allowed) ----------------
constexpr size_t F_XW   = 0;
constexpr size_t F_T    = F_XW  + (size_t)N0c*NFc;
constexpr size_t F_H1   = F_T   + (size_t)N0c*NCc;
constexpr size_t F_H01  = F_H1  + (size_t)N1c*NFc;
constexpr size_t F_Q1   = F_H01 + (size_t)N1c*NFc;
constexpr size_t F_K1   = F_Q1  + (size_t)N1c*NFc;
constexpr size_t F_H1R  = F_K1  + (size_t)N1c*NFc;
constexpr size_t F_U1   = F_H1R + (size_t)N1c*NFc;
constexpr size_t F_H2   = F_U1  + (size_t)N1c*NFc;
constexpr size_t F_H02  = F_H2  + (size_t)N2c*NFc;
constexpr size_t F_Q2   = F_H02 + (size_t)N2c*NFc;
constexpr size_t F_K2   = F_Q2  + (size_t)N2c*NFc;
constexpr size_t F_H2R  = F_K2  + (size_t)N2c*NFc;
constexpr size_t F_VAL0 = F_H2R + (size_t)N2c*NFc;
constexpr size_t F_VAL1 = F_VAL0 + (size_t)E0c;
constexpr size_t F_VAL2 = F_VAL1 + (size_t)E1c;
constexpr size_t F_TOT  = F_VAL2 + (size_t)E2c;
__device__ __align__(16) float g_f[F_TOT];

constexpr size_t I_OFF0 = 0;
constexpr size_t I_CNT0 = I_OFF0 + (size_t)N0c + 4;
constexpr size_t I_SRC0 = I_CNT0 + (size_t)N0c;
constexpr size_t I_OFF1 = I_SRC0 + (size_t)E0c;
constexpr size_t I_CNT1 = I_OFF1 + (size_t)N1c + 4;
constexpr size_t I_SRC1 = I_CNT1 + (size_t)N1c;
constexpr size_t I_OFF2 = I_SRC1 + (size_t)E1c;
constexpr size_t I_CNT2 = I_OFF2 + (size_t)N2c + 4;
constexpr size_t I_SRC2 = I_CNT2 + (size_t)N2c;
constexpr size_t I_POF0 = I_SRC2 + (size_t)E2c;
constexpr size_t I_PID0 = I_POF0 + (size_t)N1c + 4;
constexpr size_t I_POF1 = I_PID0 + (size_t)N0c;
constexpr size_t I_PID1 = I_POF1 + (size_t)N2c + 4;
constexpr size_t I_PART = I_PID1 + (size_t)N1c;
constexpr size_t I_PCN1 = I_PART + 256;
constexpr size_t I_PCN2 = I_PCN1 + (size_t)N1c;
constexpr size_t I_TOT  = I_PCN2 + (size_t)N2c;
__device__ int g_i[I_TOT];

// split-bf16 weights: 6 slots x 32768 bf16 (slot5 = gc2W, 40x128 hi + lo)
__device__ __align__(16) __nv_bfloat16 g_wt[6 * 32768];

#define SCAN_BLOCKS 162
struct Seg { int* cnt; int* off; int* cur; int pbase; int n; int sblk; };
__device__ __forceinline__ Seg seg_resolve(int b) {
    Seg s;
    if (b < 98)       { s.cnt = g_i + I_CNT0; s.off = g_i + I_OFF0; s.cur = g_i + I_CNT0; s.pbase = 0;   s.n = N0c; s.sblk = b; }
    else if (b < 123) { s.cnt = g_i + I_CNT1; s.off = g_i + I_OFF1; s.cur = g_i + I_CNT1; s.pbase = 98;  s.n = N1c; s.sblk = b - 98; }
    else if (b < 130) { s.cnt = g_i + I_CNT2; s.off = g_i + I_OFF2; s.cur = g_i + I_CNT2; s.pbase = 123; s.n = N2c; s.sblk = b - 123; }
    else if (b < 155) { s.cnt = g_i + I_PCN1; s.off = g_i + I_POF0; s.cur = g_i + I_PCN1; s.pbase = 130; s.n = N1c; s.sblk = b - 130; }
    else              { s.cnt = g_i + I_PCN2; s.off = g_i + I_POF1; s.cur = g_i + I_PCN2; s.pbase = 155; s.n = N2c; s.sblk = b - 155; }
    return s;
}

// ---------------- mma helpers ----------------
__device__ __forceinline__ void mma16816(float* c, const uint32_t* a,
                                         uint32_t b0, uint32_t b1) {
    asm volatile(
        "mma.sync.aligned.m16n8k16.row.col.f32.bf16.bf16.f32 "
        "{%0,%1,%2,%3}, {%4,%5,%6,%7}, {%8,%9}, {%0,%1,%2,%3};"
        : "+f"(c[0]), "+f"(c[1]), "+f"(c[2]), "+f"(c[3])
        : "r"(a[0]), "r"(a[1]), "r"(a[2]), "r"(a[3]), "r"(b0), "r"(b1));
}
__device__ __forceinline__ void split_bf16(float a, float b, uint32_t& hi, uint32_t& lo) {
    __nv_bfloat16 ha = __float2bfloat16(a), hb = __float2bfloat16(b);
    __nv_bfloat162 hp; hp.x = ha; hp.y = hb;
    __nv_bfloat162 lp;
    lp.x = __float2bfloat16(a - __bfloat162float(ha));
    lp.y = __float2bfloat16(b - __bfloat162float(hb));
    hi = *(uint32_t*)&hp;
    lo = *(uint32_t*)&lp;
}

// ---------------- batched weight prep: 5 x [128,128] + gc2W [128,40] ----------------
__global__ void wprep_all(const float* __restrict__ w0, const float* __restrict__ w1,
                          const float* __restrict__ w2, const float* __restrict__ w3,
                          const float* __restrict__ w4, const float* __restrict__ w5) {
    int b = blockIdx.x;
    if (b < 320) {
        int seg = b >> 6;
        int t = ((b & 63) << 8) + threadIdx.x;
        if (t >= 16384) return;
        const float* W = (seg == 0) ? w0 : (seg == 1) ? w1 : (seg == 2) ? w2
                        : (seg == 3) ? w3 : w4;
        __nv_bfloat16* out = g_wt + (size_t)seg * 32768;
        int n = t >> 7, k = t & 127;
        float v = __ldg(&W[(size_t)k * 128 + n]);
        __nv_bfloat16 h = __float2bfloat16(v);
        out[t] = h;
        out[16384 + t] = __float2bfloat16(v - __bfloat162float(h));
    } else {
        int t = ((b - 320) << 8) + threadIdx.x;    // gc2W: 40x128 = 5120
        if (t >= 5120) return;
        __nv_bfloat16* out = g_wt + (size_t)5 * 32768;
        int n = t >> 7, k = t & 127;
        float v = __ldg(&w5[(size_t)k * 40 + n]);
        __nv_bfloat16 h = __float2bfloat16(v);
        out[t] = h;
        out[5120 + t] = __float2bfloat16(v - __bfloat162float(h));
    }
}

// ---------------- tensor-core GEMM: Y = X[M,128] @ W[128,128], split bf16 ----------------
// Dual-output via blockIdx.y: y==0 -> (WA,Y1), y==1 -> (WB,Y2).
#define WROW 68
__global__ void __launch_bounds__(256, 2) gemm_mma(
    const float* __restrict__ X,
    const __nv_bfloat16* __restrict__ WA, const __nv_bfloat16* __restrict__ WB,
    float* __restrict__ Y1, float* __restrict__ Y2, int M)
{
    extern __shared__ uint32_t sm[];
    uint32_t* XH = sm;            // 64*68 = 4352
    uint32_t* XL = sm + 4352;
    uint32_t* BH = sm + 8704;     // 128*68 = 8704
    uint32_t* BL = sm + 17408;    // total 26112 u32 = 104448 B
    const int tid = threadIdx.x;
    const int row0 = blockIdx.x * 64;
    const __nv_bfloat16* W = (blockIdx.y == 0) ? WA : WB;
    float* Y = (blockIdx.y == 0) ? Y1 : Y2;

    for (int i = tid; i < 1024; i += 256) {
        int r = i >> 4, c8 = (i & 15) << 3;
        int gr = row0 + r;
        float4 v0 = make_float4(0.f, 0.f, 0.f, 0.f), v1 = v0;
        if (gr < M) {
            const float4* xp = (const float4*)(X + (size_t)gr * 128 + c8);
            v0 = __ldg(xp); v1 = __ldg(xp + 1);
        }
        uint32_t hi[4], lo[4];
        split_bf16(v0.x, v0.y, hi[0], lo[0]);
        split_bf16(v0.z, v0.w, hi[1], lo[1]);
        split_bf16(v1.x, v1.y, hi[2], lo[2]);
        split_bf16(v1.z, v1.w, hi[3], lo[3]);
        int si = r * WROW + (c8 >> 1);
        *(uint4*)(XH + si) = make_uint4(hi[0], hi[1], hi[2], hi[3]);
        *(uint4*)(XL + si) = make_uint4(lo[0], lo[1], lo[2], lo[3]);
    }
    {
        const uint4* wa = (const uint4*)W;
        for (int i = tid; i < 2048; i += 256) {
            int r = i >> 4, c4 = (i & 15) << 2;
            int si = r * WROW + c4;
            *(uint4*)(BH + si) = __ldg(wa + i);
            *(uint4*)(BL + si) = __ldg(wa + 2048 + i);
        }
    }
    __syncthreads();

    const int wid = tid >> 5, lane = tid & 31;
    const int wm = wid & 1, wn = wid >> 1;     // 2 x 4 warp grid
    const int g = lane >> 2, tq = lane & 3;

    float C[2][4][4];
    #pragma unroll
    for (int mt = 0; mt < 2; mt++)
        #pragma unroll
        for (int nt = 0; nt < 4; nt++)
            #pragma unroll
            for (int j = 0; j < 4; j++) C[mt][nt][j] = 0.f;

    #pragma unroll
    for (int ks = 0; ks < 8; ks++) {
        uint32_t Ah[2][4], Al[2][4];
        #pragma unroll
        for (int mt = 0; mt < 2; mt++) {
            int r0 = (wm * 32 + mt * 16 + g) * WROW + ks * 8 + tq;
            Ah[mt][0] = XH[r0];        Ah[mt][1] = XH[r0 + 8 * WROW];
            Ah[mt][2] = XH[r0 + 4];    Ah[mt][3] = XH[r0 + 8 * WROW + 4];
            Al[mt][0] = XL[r0];        Al[mt][1] = XL[r0 + 8 * WROW];
            Al[mt][2] = XL[r0 + 4];    Al[mt][3] = XL[r0 + 8 * WROW + 4];
        }
        #pragma unroll
        for (int nt = 0; nt < 4; nt++) {
            int bi = (wn * 32 + nt * 8 + g) * WROW + ks * 8 + tq;
            uint32_t bh0 = BH[bi], bh1 = BH[bi + 4];
            uint32_t bl0 = BL[bi], bl1 = BL[bi + 4];
            #pragma unroll
            for (int mt = 0; mt < 2; mt++) {
                mma16816(C[mt][nt], Ah[mt], bh0, bh1);
                mma16816(C[mt][nt], Ah[mt], bl0, bl1);
                mma16816(C[mt][nt], Al[mt], bh0, bh1);
            }
        }
    }
    #pragma unroll
    for (int mt = 0; mt < 2; mt++) {
        int row = row0 + wm * 32 + mt * 16 + g;
        #pragma unroll
        for (int nt = 0; nt < 4; nt++) {
            int col = wn * 32 + nt * 8 + tq * 2;
            if (row < M)
                *(float2*)(Y + (size_t)row * 128 + col) =
                    make_float2(C[mt][nt][0], C[mt][nt][1]);
            if (row + 8 < M)
                *(float2*)(Y + (size_t)(row + 8) * 128 + col) =
                    make_float2(C[mt][nt][2], C[mt][nt][3]);
        }
    }
}

// ---- fused: crf = U1[assign0[row]] + gcn[row]; write crf_sec; T = crf @ gc2W (mma) ----
__global__ void __launch_bounds__(256, 2) gemm40_mma(
    const float* __restrict__ U1, const int* __restrict__ assign0,
    const float* __restrict__ gcn, float* __restrict__ crf_out,
    float* __restrict__ Y, int M)
{
    extern __shared__ uint32_t sm[];
    uint32_t* XH = sm;
    uint32_t* XL = sm + 4352;
    uint32_t* BH = sm + 8704;
    uint32_t* BL = sm + 13056;
    const int tid = threadIdx.x;
    const int row0 = blockIdx.x * 64;
    const __nv_bfloat16* W40 = g_wt + (size_t)5 * 32768;

    for (int i = tid; i < 1024; i += 256) {
        int r = i >> 4, c8 = (i & 15) << 3;
        int gr = row0 + r;
        float4 v0 = make_float4(0.f, 0.f, 0.f, 0.f), v1 = v0;
        if (gr < M) {
            int a = __ldg(&assign0[gr]);
            const float4* up = (const float4*)(U1 + (size_t)a * 128 + c8);
            const float4* gp = (const float4*)(gcn + (size_t)gr * 128 + c8);
            float4 u0 = __ldg(up), u1 = __ldg(up + 1);
            float4 g0 = __ldg(gp), g1 = __ldg(gp + 1);
            v0.x = u0.x + g0.x; v0.y = u0.y + g0.y; v0.z = u0.z + g0.z; v0.w = u0.w + g0.w;
            v1.x = u1.x + g1.x; v1.y = u1.y + g1.y; v1.z = u1.z + g1.z; v1.w = u1.w + g1.w;
            float4* cp = (float4*)(crf_out + (size_t)gr * 128 + c8);
            cp[0] = v0; cp[1] = v1;
        }
        uint32_t hi[4], lo[4];
        split_bf16(v0.x, v0.y, hi[0], lo[0]);
        split_bf16(v0.z, v0.w, hi[1], lo[1]);
        split_bf16(v1.x, v1.y, hi[2], lo[2]);
        split_bf16(v1.z, v1.w, hi[3], lo[3]);
        int si = r * WROW + (c8 >> 1);
        *(uint4*)(XH + si) = make_uint4(hi[0], hi[1], hi[2], hi[3]);
        *(uint4*)(XL + si) = make_uint4(lo[0], lo[1], lo[2], lo[3]);
    }
    {
        const uint4* wh = (const uint4*)W40;
        const uint4* wl = (const uint4*)(W40 + 5120);
        for (int i = tid; i < 1024; i += 256) {
            int r = i >> 4, c4 = (i & 15) << 2;
            int si = r * WROW + c4;
            uint4 h = make_uint4(0, 0, 0, 0), l = h;
            if (r < 40) { h = __ldg(wh + i); l = __ldg(wl + i); }
            *(uint4*)(BH + si) = h;
            *(uint4*)(BL + si) = l;
        }
    }
    __syncthreads();

    const int wid = tid >> 5, lane = tid & 31;
    const int wm = wid & 3, wn = wid >> 2;     // 4x2 grid; 16x32 warp tiles
    const int g = lane >> 2, tq = lane & 3;

    float C[4][4];
    #pragma unroll
    for (int nt = 0; nt < 4; nt++)
        #pragma unroll
        for (int j = 0; j < 4; j++) C[nt][j] = 0.f;

    #pragma unroll
    for (int ks = 0; ks < 8; ks++) {
        uint32_t Ah[4], Al[4];
        int r0 = (wm * 16 + g) * WROW + ks * 8 + tq;
        Ah[0] = XH[r0];        Ah[1] = XH[r0 + 8 * WROW];
        Ah[2] = XH[r0 + 4];    Ah[3] = XH[r0 + 8 * WROW + 4];
        Al[0] = XL[r0];        Al[1] = XL[r0 + 8 * WROW];
        Al[2] = XL[r0 + 4];    Al[3] = XL[r0 + 8 * WROW + 4];
        #pragma unroll
        for (int nt = 0; nt < 4; nt++) {
            int bi = (wn * 32 + nt * 8 + g) * WROW + ks * 8 + tq;
            uint32_t bh0 = BH[bi], bh1 = BH[bi + 4];
            uint32_t bl0 = BL[bi], bl1 = BL[bi + 4];
            mma16816(C[nt], Ah, bh0, bh1);
            mma16816(C[nt], Ah, bl0, bl1);
            mma16816(C[nt], Al, bh0, bh1);
        }
    }
    {
        int row = row0 + wm * 16 + g;
        #pragma unroll
        for (int nt = 0; nt < 4; nt++) {
            int col = wn * 32 + nt * 8 + tq * 2;
            if (col < 40) {
                if (row < M)
                    *(float2*)(Y + (size_t)row * 40 + col) = make_float2(C[nt][0], C[nt][1]);
                if (row + 8 < M)
                    *(float2*)(Y + (size_t)(row + 8) * 40 + col) = make_float2(C[nt][2], C[nt][3]);
            }
        }
    }
}

// ---------------- batched CSR build kernels ----------------
__global__ void kzero_all() {
    int i = blockIdx.x * 256 + threadIdx.x;
    if (i < 100000)      g_i[I_CNT0 + i] = 0;
    else if (i < 125000) g_i[I_CNT1 + (i - 100000)] = 0;
    else if (i < 131250) g_i[I_CNT2 + (i - 125000)] = 0;
    else if (i < 156250) g_i[I_PCN1 + (i - 131250)] = 0;
    else if (i < 162500) g_i[I_PCN2 + (i - 156250)] = 0;
}
__global__ void khist_all(const int* __restrict__ A0, const int* __restrict__ A1,
                          const int* __restrict__ A2, const int* __restrict__ as0,
                          const int* __restrict__ as1) {
    int i = blockIdx.x * 256 + threadIdx.x;
    if (i < 1600000)      atomicAdd(&g_i[I_CNT0 + __ldg(&A0[i])], 1);
    else if (i < 2000000) atomicAdd(&g_i[I_CNT1 + __ldg(&A1[i - 1600000])], 1);
    else if (i < 2100000) atomicAdd(&g_i[I_CNT2 + __ldg(&A2[i - 2000000])], 1);
    else if (i < 2200000) atomicAdd(&g_i[I_PCN1 + __ldg(&as0[i - 2100000])], 1);
    else if (i < 2225000) atomicAdd(&g_i[I_PCN2 + __ldg(&as1[i - 2200000])], 1);
}
__global__ void scan_blk_all() {
    __shared__ int wsum[32];
    Seg s = seg_resolve(blockIdx.x);
    int t = threadIdx.x;
    int i = s.sblk * 1024 + t;
    int v = (i < s.n) ? s.cnt[i] : 0;
    int x = v;
    #pragma unroll
    for (int o = 1; o < 32; o <<= 1) {
        int tmp = __shfl_up_sync(0xffffffffu, x, o);
        if ((t & 31) >= o) x += tmp;
    }
    if ((t & 31) == 31) wsum[t >> 5] = x;
    __syncthreads();
    if (t < 32) {
        int y = wsum[t];
        #pragma unroll
        for (int o = 1; o < 32; o <<= 1) {
            int tmp = __shfl_up_sync(0xffffffffu, y, o);
            if (t >= o) y += tmp;
        }
        wsum[t] = y;
    }
    __syncthreads();
    int base = (t >= 32) ? wsum[(t >> 5) - 1] : 0;
    int incl = base + x;
    if (i < s.n) s.off[i] = incl - v;
    if (t == 1023) g_i[I_PART + s.pbase + s.sblk] = incl;
}
__global__ void scan_part_all() {
    __shared__ int sh[128];
    const int bases[5] = {0, 98, 123, 130, 155};
    const int cnts[5]  = {98, 25, 7, 25, 7};
    int b = blockIdx.x, t = threadIdx.x;
    int* part = g_i + I_PART + bases[b];
    int nb = cnts[b];
    int v = (t < nb) ? part[t] : 0;
    sh[t] = v;
    __syncthreads();
    #pragma unroll
    for (int o = 1; o < 128; o <<= 1) {
        int tmp = (t >= o) ? sh[t - o] : 0;
        __syncthreads();
        sh[t] += tmp;
        __syncthreads();
    }
    if (t < nb) part[t] = sh[t] - v;
    if (t == 0) {
        int total = sh[127];
        int* off = (b == 0) ? g_i + I_OFF0 : (b == 1) ? g_i + I_OFF1
                 : (b == 2) ? g_i + I_OFF2 : (b == 3) ? g_i + I_POF0 : g_i + I_POF1;
        int n = (b == 0) ? N0c : (b == 1) ? N1c : (b == 2) ? N2c
              : (b == 3) ? N1c : N2c;
        off[n] = total;
    }
}
__global__ void scan_add_all() {
    Seg s = seg_resolve(blockIdx.x);
    int i = s.sblk * 1024 + threadIdx.x;
    if (i < s.n) {
        int v = s.off[i] + g_i[I_PART + s.pbase + s.sblk];
        s.off[i] = v;
        s.cur[i] = v;
    }
}
__global__ void kscatter_all(const int* __restrict__ A0, const float* __restrict__ A0v,
                             const int* __restrict__ A1, const float* __restrict__ A1v,
                             const int* __restrict__ A2, const float* __restrict__ A2v,
                             const int* __restrict__ as0, const int* __restrict__ as1) {
    int i = blockIdx.x * 256 + threadIdx.x;
    if (i < 1600000) {
        int pos = atomicAdd(&g_i[I_CNT0 + __ldg(&A0[i])], 1);
        g_i[I_SRC0 + pos] = __ldg(&A0[1600000 + i]);
        g_f[F_VAL0 + pos] = __ldg(&A0v[i]);
    } else if (i < 2000000) {
        int e = i - 1600000;
        int pos = atomicAdd(&g_i[I_CNT1 + __ldg(&A1[e])], 1);
        g_i[I_SRC1 + pos] = __ldg(&A1[400000 + e]);
        g_f[F_VAL1 + pos] = __ldg(&A1v[e]);
    } else if (i < 2100000) {
        int e = i - 2000000;
        int pos = atomicAdd(&g_i[I_CNT2 + __ldg(&A2[e])], 1);
        g_i[I_SRC2 + pos] = __ldg(&A2[100000 + e]);
        g_f[F_VAL2 + pos] = __ldg(&A2v[e]);
    } else if (i < 2200000) {
        int e = i - 2100000;
        int pos = atomicAdd(&g_i[I_PCN1 + __ldg(&as0[e])], 1);
        g_i[I_PID0 + pos] = e;
    } else if (i < 2225000) {
        int e = i - 2200000;
        int pos = atomicAdd(&g_i[I_PCN2 + __ldg(&as1[e])], 1);
        g_i[I_PID1 + pos] = e;
    }
}

// ---------------- CSR SpMM, 128 cols, warp per row, unroll-2 ----------------
__global__ void spmm128(const int* __restrict__ off, const int* __restrict__ srcs,
                        const float* __restrict__ vals, const float* __restrict__ X,
                        const float* __restrict__ bias, float* __restrict__ Y,
                        int n, int relu) {
    int row = blockIdx.x * blockDim.y + threadIdx.y;
    if (row >= n) return;
    int lane = threadIdx.x;
    int s = off[row], e = off[row + 1];
    float4 acc = make_float4(0.f, 0.f, 0.f, 0.f);
    int j = s;
    for (; j + 2 <= e; j += 2) {
        int s0 = __ldg(&srcs[j]), s1 = __ldg(&srcs[j + 1]);
        float v0 = __ldg(&vals[j]), v1 = __ldg(&vals[j + 1]);
        float4 x0 = __ldg((const float4*)(X + (size_t)s0 * 128) + lane);
        float4 x1 = __ldg((const float4*)(X + (size_t)s1 * 128) + lane);
        acc.x = fmaf(v0, x0.x, acc.x); acc.y = fmaf(v0, x0.y, acc.y);
        acc.z = fmaf(v0, x0.z, acc.z); acc.w = fmaf(v0, x0.w, acc.w);
        acc.x = fmaf(v1, x1.x, acc.x); acc.y = fmaf(v1, x1.y, acc.y);
        acc.z = fmaf(v1, x1.z, acc.z); acc.w = fmaf(v1, x1.w, acc.w);
    }
    if (j < e) {
        int src = __ldg(&srcs[j]);
        float v = __ldg(&vals[j]);
        float4 xv = __ldg((const float4*)(X + (size_t)src * 128) + lane);
        acc.x = fmaf(v, xv.x, acc.x); acc.y = fmaf(v, xv.y, acc.y);
        acc.z = fmaf(v, xv.z, acc.z); acc.w = fmaf(v, xv.w, acc.w);
    }
    float4 b = __ldg((const float4*)bias + lane);
    acc.x += b.x; acc.y += b.y; acc.z += b.z; acc.w += b.w;
    if (relu) {
        acc.x = fmaxf(acc.x, 0.f); acc.y = fmaxf(acc.y, 0.f);
        acc.z = fmaxf(acc.z, 0.f); acc.w = fmaxf(acc.w, 0.f);
    }
    *((float4*)(Y + (size_t)row * 128) + lane) = acc;
}

// ---------------- CSR SpMM, 40 cols, warp per row, unroll-2 ----------------
__global__ void spmm40(const int* __restrict__ off, const int* __restrict__ srcs,
                       const float* __restrict__ vals, const float* __restrict__ X,
                       const float* __restrict__ bias, float* __restrict__ Y, int n) {
    int row = blockIdx.x * blockDim.y + threadIdx.y;
    if (row >= n) return;
    int lane = threadIdx.x;
    int s = off[row], e = off[row + 1];
    float a0 = 0.f, a1 = 0.f;
    int j = s;
    for (; j + 2 <= e; j += 2) {
        int s0 = __ldg(&srcs[j]), s1 = __ldg(&srcs[j + 1]);
        float v0 = __ldg(&vals[j]), v1 = __ldg(&vals[j + 1]);
        float x0a = __ldg(&X[(size_t)s0 * 40 + lane]);
        float x1a = __ldg(&X[(size_t)s1 * 40 + lane]);
        float x0b = 0.f, x1b = 0.f;
        if (lane < 8) {
            x0b = __ldg(&X[(size_t)s0 * 40 + 32 + lane]);
            x1b = __ldg(&X[(size_t)s1 * 40 + 32 + lane]);
        }
        a0 = fmaf(v0, x0a, a0); a0 = fmaf(v1, x1a, a0);
        a1 = fmaf(v0, x0b, a1); a1 = fmaf(v1, x1b, a1);
    }
    if (j < e) {
        int src = __ldg(&srcs[j]);
        float v = __ldg(&vals[j]);
        a0 = fmaf(v, __ldg(&X[(size_t)src * 40 + lane]), a0);
        if (lane < 8) a1 = fmaf(v, __ldg(&X[(size_t)src * 40 + 32 + lane]), a1);
    }
    Y[(size_t)row * 40 + lane] = a0 + __ldg(&bias[lane]);
    if (lane < 8) Y[(size_t)row * 40 + 32 + lane] = a1 + __ldg(&bias[32 + lane]);
}

// ---------------- pooling via CSR gather + fused emb add, unroll-2 ----------------
__global__ void pool_gather(const int* __restrict__ off, const int* __restrict__ ids,
                            const float* __restrict__ X,
                            const int* __restrict__ nw, const float* __restrict__ emb,
                            float* __restrict__ H, float* __restrict__ H0, int n) {
    int row = blockIdx.x * blockDim.y + threadIdx.y;
    if (row >= n) return;
    int lane = threadIdx.x;
    int s = off[row], e = off[row + 1];
    float4 acc = make_float4(0.f, 0.f, 0.f, 0.f);
    int j = s;
    for (; j + 2 <= e; j += 2) {
        int n0 = __ldg(&ids[j]), n1 = __ldg(&ids[j + 1]);
        float4 v0 = __ldg((const float4*)(X + (size_t)n0 * 128) + lane);
        float4 v1 = __ldg((const float4*)(X + (size_t)n1 * 128) + lane);
        acc.x += v0.x + v1.x; acc.y += v0.y + v1.y;
        acc.z += v0.z + v1.z; acc.w += v0.w + v1.w;
    }
    if (j < e) {
        int node = __ldg(&ids[j]);
        float4 v = __ldg((const float4*)(X + (size_t)node * 128) + lane);
        acc.x += v.x; acc.y += v.y; acc.z += v.z; acc.w += v.w;
    }
    *((float4*)(H + (size_t)row * 128) + lane) = acc;
    int w = __ldg(&nw[row]);
    float4 em = __ldg((const float4*)(emb + (size_t)w * 128) + lane);
    acc.x += em.x; acc.y += em.y; acc.z += em.z; acc.w += em.w;
    *((float4*)(H0 + (size_t)row * 128) + lane) = acc;
}

// ---------------- CRF refinement: warp per dst row, online softmax, unroll-2 ----------
__global__ void crf_refine(const int* __restrict__ off, const int* __restrict__ srcs,
                           const float* __restrict__ Q, const float* __restrict__ Km,
                           const float* __restrict__ H0,
                           const float* __restrict__ alpha_p, const float* __restrict__ beta_p,
                           float* __restrict__ Out, int n) {
    int row = blockIdx.x * blockDim.y + threadIdx.y;
    if (row >= n) return;
    int lane = threadIdx.x;
    float4 q = __ldg((const float4*)(Q + (size_t)row * 128) + lane);
    int s = off[row], e = off[row + 1];
    float m = -3.4e38f, z = 0.f;
    float4 macc = make_float4(0.f, 0.f, 0.f, 0.f);
    int j = s;
    for (; j + 2 <= e; j += 2) {
        int s0 = __ldg(&srcs[j]), s1 = __ldg(&srcs[j + 1]);
        float4 k0 = __ldg((const float4*)(Km + (size_t)s0 * 128) + lane);
        float4 k1 = __ldg((const float4*)(Km + (size_t)s1 * 128) + lane);
        float4 h0 = __ldg((const float4*)(H0 + (size_t)s0 * 128) + lane);
        float4 h1 = __ldg((const float4*)(H0 + (size_t)s1 * 128) + lane);
        float p0 = q.x * k0.x + q.y * k0.y + q.z * k0.z + q.w * k0.w;
        float p1 = q.x * k1.x + q.y * k1.y + q.z * k1.z + q.w * k1.w;
        #pragma unroll
        for (int o = 16; o; o >>= 1) {
            p0 += __shfl_xor_sync(0xffffffffu, p0, o);
            p1 += __shfl_xor_sync(0xffffffffu, p1, o);
        }
        p0 *= 0.08838834764831845f;
        p1 *= 0.08838834764831845f;
        if (p0 > m) {
            float sc = __expf(m - p0);
            z *= sc; macc.x *= sc; macc.y *= sc; macc.z *= sc; macc.w *= sc;
            m = p0;
        }
        float w0 = __expf(p0 - m);
        z += w0;
        macc.x = fmaf(w0, h0.x, macc.x); macc.y = fmaf(w0, h0.y, macc.y);
        macc.z = fmaf(w0, h0.z, macc.z); macc.w = fmaf(w0, h0.w, macc.w);
        if (p1 > m) {
            float sc = __expf(m - p1);
            z *= sc; macc.x *= sc; macc.y *= sc; macc.z *= sc; macc.w *= sc;
            m = p1;
        }
        float w1 = __expf(p1 - m);
        z += w1;
        macc.x = fmaf(w1, h1.x, macc.x); macc.y = fmaf(w1, h1.y, macc.y);
        macc.z = fmaf(w1, h1.z, macc.z); macc.w = fmaf(w1, h1.w, macc.w);
    }
    if (j < e) {
        int src = __ldg(&srcs[j]);
        float4 kv = __ldg((const float4*)(Km + (size_t)src * 128) + lane);
        float4 hv = __ldg((const float4*)(H0 + (size_t)src * 128) + lane);
        float p = q.x * kv.x + q.y * kv.y + q.z * kv.z + q.w * kv.w;
        #pragma unroll
        for (int o = 16; o; o >>= 1) p += __shfl_xor_sync(0xffffffffu, p, o);
        p *= 0.08838834764831845f;
        if (p > m) {
            float sc = __expf(m - p);
            z *= sc; macc.x *= sc; macc.y *= sc; macc.z *= sc; macc.w *= sc;
            m = p;
        }
        float w = __expf(p - m);
        z += w;
        macc.x = fmaf(w, hv.x, macc.x); macc.y = fmaf(w, hv.y, macc.y);
        macc.z = fmaf(w, hv.z, macc.z); macc.w = fmaf(w, hv.w, macc.w);
    }
    float alpha = __ldg(alpha_p), beta = __ldg(beta_p);
    float4 h0d = __ldg((const float4*)(H0 + (size_t)row * 128) + lane);
    float invz = 1.f / (z + 1e-16f);
    float invab = 1.f / (alpha + beta);
    float4 r;
    r.x = (alpha * h0d.x + beta * macc.x * invz) * invab;
    r.y = (alpha * h0d.y + beta * macc.y * invz) * invab;
    r.z = (alpha * h0d.z + beta * macc.z * invz) * invab;
    r.w = (alpha * h0d.w + beta * macc.w * invz) * invab;
    *((float4*)(Out + (size_t)row * 128) + lane) = r;
}

// ---------------- unpool + skip ----------------
__global__ void unpool_add(const float* __restrict__ Hi, const int* __restrict__ assign,
                           const float* __restrict__ skip, float* __restrict__ Out, int n) {
    int i = blockIdx.x * blockDim.y + threadIdx.y;
    if (i >= n) return;
    int lane = threadIdx.x;
    int a = assign[i];
    float4 v = __ldg((const float4*)(Hi + (size_t)a * 128) + lane);
    float4 sk = *((const float4*)(skip + (size_t)i * 128) + lane);
    v.x += sk.x; v.y += sk.y; v.z += sk.z; v.w += sk.w;
    *((float4*)(Out + (size_t)i * 128) + lane) = v;
}

// ---------------- streams/events (created at static init) ----------------
struct StreamEnv {
    cudaStream_t sB;
    cudaEvent_t evF, evB;
    StreamEnv() {
        cudaStreamCreateWithFlags(&sB, cudaStreamNonBlocking);
        cudaEventCreateWithFlags(&evF, cudaEventDisableTiming);
        cudaEventCreateWithFlags(&evB, cudaEventDisableTiming);
    }
};
static StreamEnv g_se;

// ---------------- host ----------------
extern "C" void kernel_launch(void* const* d_in, const int* in_sizes, int n_in,
                              void* d_out, int out_size) {
    const float* x       = (const float*)d_in[0];
    const int*   A0      = (const int*)d_in[1];
    const float* A0v     = (const float*)d_in[2];
    const int*   A1      = (const int*)d_in[3];
    const float* A1v     = (const float*)d_in[4];
    const int*   A2      = (const int*)d_in[5];
    const float* A2v     = (const float*)d_in[6];
    const int*   assign0 = (const int*)d_in[7];
    const int*   assign1 = (const int*)d_in[8];
    const int*   nwgt1   = (const int*)d_in[9];
    const int*   nwgt2   = (const int*)d_in[10];
    const float* gc1b    = (const float*)d_in[12];
    const float* gc2b    = (const float*)d_in[14];
    const float* c1emb   = (const float*)d_in[17];
    const float* c1a     = (const float*)d_in[18];
    const float* c1be    = (const float*)d_in[19];
    const float* c2emb   = (const float*)d_in[22];
    const float* c2a     = (const float*)d_in[23];
    const float* c2be    = (const float*)d_in[24];

    float* out_sec = (float*)d_out;
    float* gcn_sec = out_sec + (size_t)N0c * NCc;
    float* crf_sec = gcn_sec + (size_t)N0c * NFc;

    void* fp; cudaGetSymbolAddress(&fp, g_f);
    void* ip; cudaGetSymbolAddress(&ip, g_i);
    void* wp; cudaGetSymbolAddress(&wp, g_wt);
    float* F = (float*)fp;
    int*   I = (int*)ip;
    __nv_bfloat16* WT = (__nv_bfloat16*)wp;

    float* xW  = F + F_XW;  float* T   = F + F_T;
    float* H1  = F + F_H1;  float* H01 = F + F_H01;
    float* Q1  = F + F_Q1;  float* K1  = F + F_K1;
    float* H1R = F + F_H1R; float* U1  = F + F_U1;
    float* H2  = F + F_H2;  float* H02 = F + F_H02;
    float* Q2  = F + F_Q2;  float* K2  = F + F_K2;
    float* H2R = F + F_H2R;
    float* V0  = F + F_VAL0;

    int* OFF0 = I + I_OFF0; int* SRC0 = I + I_SRC0;
    int* OFF1 = I + I_OFF1; int* SRC1 = I + I_SRC1;
    int* OFF2 = I + I_OFF2; int* SRC2 = I + I_SRC2;
    int* POF0 = I + I_POF0; int* PID0 = I + I_PID0;
    int* POF1 = I + I_POF1; int* PID1 = I + I_PID1;

    __nv_bfloat16* WT_gc1 = WT + 0 * 32768;
    __nv_bfloat16* WT_q1  = WT + 1 * 32768;
    __nv_bfloat16* WT_k1  = WT + 2 * 32768;
    __nv_bfloat16* WT_q2  = WT + 3 * 32768;
    __nv_bfloat16* WT_k2  = WT + 4 * 32768;

    const int SMEM_G  = 26112 * 4;
    const int SMEM_40 = 17408 * 4;

    static bool attr_done = false;
    if (!attr_done) {
        cudaFuncSetAttribute(gemm_mma, cudaFuncAttributeMaxDynamicSharedMemorySize, SMEM_G);
        cudaFuncSetAttribute(gemm40_mma, cudaFuncAttributeMaxDynamicSharedMemorySize, SMEM_40);
        attr_done = true;
    }

    dim3 warp8(32, 8);
    cudaStream_t s0 = 0;
    cudaStream_t sB = g_se.sB;

    cudaEventRecord(g_se.evF, s0);
    cudaStreamWaitEvent(sB, g_se.evF, 0);

    // enqueue order keeps gemm_mma(gc1) as 4th launch for ncu
    wprep_all<<<340, 256, 0, s0>>>((const float*)d_in[11], (const float*)d_in[15],
                                   (const float*)d_in[16], (const float*)d_in[20],
                                   (const float*)d_in[21], (const float*)d_in[13]);
    kzero_all<<<(162500 + 255) / 256, 256, 0, sB>>>();
    khist_all<<<(2225000 + 255) / 256, 256, 0, sB>>>(A0, A1, A2, assign0, assign1);
    gemm_mma<<<dim3((N0c + 63) / 64, 1), 256, SMEM_G, s0>>>(x, WT_gc1, WT_gc1,
                                                            xW, xW, N0c);
    scan_blk_all<<<SCAN_BLOCKS, 1024, 0, sB>>>();
    scan_part_all<<<5, 128, 0, sB>>>();
    scan_add_all<<<SCAN_BLOCKS, 1024, 0, sB>>>();
    kscatter_all<<<(2225000 + 255) / 256, 256, 0, sB>>>(A0, A0v, A1, A1v, A2, A2v,
                                                        assign0, assign1);
    cudaEventRecord(g_se.evB, sB);

    cudaStreamWaitEvent(s0, g_se.evB, 0);
    spmm128<<<(N0c + 7) / 8, warp8, 0, s0>>>(OFF0, SRC0, V0, xW, gc1b, gcn_sec, N0c, 1);

    // level 1: pool + dual QK GEMM (one launch, gridDim.y=2) + CRF
    pool_gather<<<(N1c + 7) / 8, warp8, 0, s0>>>(POF0, PID0, gcn_sec, nwgt1, c1emb,
                                                 H1, H01, N1c);
    gemm_mma<<<dim3((N1c + 63) / 64, 2), 256, SMEM_G, s0>>>(H1, WT_q1, WT_k1,
                                                            Q1, K1, N1c);
    crf_refine<<<(N1c + 7) / 8, warp8, 0, s0>>>(OFF1, SRC1, Q1, K1, H01, c1a, c1be,
                                                H1R, N1c);

    // level 2: pool + dual QK GEMM + CRF
    pool_gather<<<(N2c + 7) / 8, warp8, 0, s0>>>(POF1, PID1, H1R, nwgt2, c2emb,
                                                 H2, H02, N2c);
    gemm_mma<<<dim3((N2c + 63) / 64, 2), 256, SMEM_G, s0>>>(H2, WT_q2, WT_k2,
                                                            Q2, K2, N2c);
    crf_refine<<<(N2c + 7) / 8, warp8, 0, s0>>>(OFF2, SRC2, Q2, K2, H02, c2a, c2be,
                                                H2R, N2c);

    // unpool level 2->1
    unpool_add<<<(N1c + 7) / 8, warp8, 0, s0>>>(H2R, assign1, H1R, U1, N1c);

    // fused unpool 1->0 + gc2 GEMM
    gemm40_mma<<<(N0c + 63) / 64, 256, SMEM_40, s0>>>(U1, assign0, gcn_sec, crf_sec,
                                                      T, N0c);
    spmm40<<<(N0c + 7) / 8, warp8, 0, s0>>>(OFF0, SRC0, V0, T, gc2b, out_sec, N0c);
}

// round 16
// speedup vs baseline: 1.0796x; 1.0036x over previous
#include <cuda_runtime.h>
#include <cuda_bf16.h>
#include <math.h>
#include <stdint.h>

#define N0c 100000
#define N1c 25000
#define N2c 6250
#define E0c 1600000
#define E1c 400000
#define E2c 100000
#define NFc 128
#define NCc 40

// ---------------- scratch (no allocations allowed) ----------------
constexpr size_t F_XW   = 0;
constexpr size_t F_T    = F_XW  + (size_t)N0c*NFc;
constexpr size_t F_H1   = F_T   + (size_t)N0c*NCc;
constexpr size_t F_H01  = F_H1  + (size_t)N1c*NFc;
constexpr size_t F_Q1   = F_H01 + (size_t)N1c*NFc;
constexpr size_t F_K1   = F_Q1  + (size_t)N1c*NFc;
constexpr size_t F_H1R  = F_K1  + (size_t)N1c*NFc;
constexpr size_t F_U1   = F_H1R + (size_t)N1c*NFc;
constexpr size_t F_H2   = F_U1  + (size_t)N1c*NFc;
constexpr size_t F_H02  = F_H2  + (size_t)N2c*NFc;
constexpr size_t F_Q2   = F_H02 + (size_t)N2c*NFc;
constexpr size_t F_K2   = F_Q2  + (size_t)N2c*NFc;
constexpr size_t F_H2R  = F_K2  + (size_t)N2c*NFc;
constexpr size_t F_VAL0 = F_H2R + (size_t)N2c*NFc;
constexpr size_t F_VAL1 = F_VAL0 + (size_t)E0c;
constexpr size_t F_VAL2 = F_VAL1 + (size_t)E1c;
constexpr size_t F_TOT  = F_VAL2 + (size_t)E2c;
__device__ __align__(16) float g_f[F_TOT];

constexpr size_t I_OFF0 = 0;
constexpr size_t I_CNT0 = I_OFF0 + (size_t)N0c + 4;
constexpr size_t I_SRC0 = I_CNT0 + (size_t)N0c;
constexpr size_t I_OFF1 = I_SRC0 + (size_t)E0c;
constexpr size_t I_CNT1 = I_OFF1 + (size_t)N1c + 4;
constexpr size_t I_SRC1 = I_CNT1 + (size_t)N1c;
constexpr size_t I_OFF2 = I_SRC1 + (size_t)E1c;
constexpr size_t I_CNT2 = I_OFF2 + (size_t)N2c + 4;
constexpr size_t I_SRC2 = I_CNT2 + (size_t)N2c;
constexpr size_t I_POF0 = I_SRC2 + (size_t)E2c;
constexpr size_t I_PID0 = I_POF0 + (size_t)N1c + 4;
constexpr size_t I_POF1 = I_PID0 + (size_t)N0c;
constexpr size_t I_PID1 = I_POF1 + (size_t)N2c + 4;
constexpr size_t I_PART = I_PID1 + (size_t)N1c;
constexpr size_t I_PCN1 = I_PART + 256;
constexpr size_t I_PCN2 = I_PCN1 + (size_t)N1c;
constexpr size_t I_TOT  = I_PCN2 + (size_t)N2c;
__device__ int g_i[I_TOT];

// split-bf16 weights: 6 slots x 32768 bf16 (slot5 = gc2W, 40x128 hi + lo)
__device__ __align__(16) __nv_bfloat16 g_wt[6 * 32768];

#define SCAN_BLOCKS 162
struct Seg { int* cnt; int* off; int* cur; int pbase; int n; int sblk; };
__device__ __forceinline__ Seg seg_resolve(int b) {
    Seg s;
    if (b < 98)       { s.cnt = g_i + I_CNT0; s.off = g_i + I_OFF0; s.cur = g_i + I_CNT0; s.pbase = 0;   s.n = N0c; s.sblk = b; }
    else if (b < 123) { s.cnt = g_i + I_CNT1; s.off = g_i + I_OFF1; s.cur = g_i + I_CNT1; s.pbase = 98;  s.n = N1c; s.sblk = b - 98; }
    else if (b < 130) { s.cnt = g_i + I_CNT2; s.off = g_i + I_OFF2; s.cur = g_i + I_CNT2; s.pbase = 123; s.n = N2c; s.sblk = b - 123; }
    else if (b < 155) { s.cnt = g_i + I_PCN1; s.off = g_i + I_POF0; s.cur = g_i + I_PCN1; s.pbase = 130; s.n = N1c; s.sblk = b - 130; }
    else              { s.cnt = g_i + I_PCN2; s.off = g_i + I_POF1; s.cur = g_i + I_PCN2; s.pbase = 155; s.n = N2c; s.sblk = b - 155; }
    return s;
}

// ---------------- mma helpers ----------------
__device__ __forceinline__ void mma16816(float* c, const uint32_t* a,
                                         uint32_t b0, uint32_t b1) {
    asm volatile(
        "mma.sync.aligned.m16n8k16.row.col.f32.bf16.bf16.f32 "
        "{%0,%1,%2,%3}, {%4,%5,%6,%7}, {%8,%9}, {%0,%1,%2,%3};"
        : "+f"(c[0]), "+f"(c[1]), "+f"(c[2]), "+f"(c[3])
        : "r"(a[0]), "r"(a[1]), "r"(a[2]), "r"(a[3]), "r"(b0), "r"(b1));
}
__device__ __forceinline__ void split_bf16(float a, float b, uint32_t& hi, uint32_t& lo) {
    __nv_bfloat16 ha = __float2bfloat16(a), hb = __float2bfloat16(b);
    __nv_bfloat162 hp; hp.x = ha; hp.y = hb;
    __nv_bfloat162 lp;
    lp.x = __float2bfloat16(a - __bfloat162float(ha));
    lp.y = __float2bfloat16(b - __bfloat162float(hb));
    hi = *(uint32_t*)&hp;
    lo = *(uint32_t*)&lp;
}

// ---------------- batched weight prep: 5 x [128,128] + gc2W [128,40] ----------------
__global__ void wprep_all(const float* __restrict__ w0, const float* __restrict__ w1,
                          const float* __restrict__ w2, const float* __restrict__ w3,
                          const float* __restrict__ w4, const float* __restrict__ w5) {
    int b = blockIdx.x;
    if (b < 320) {
        int seg = b >> 6;
        int t = ((b & 63) << 8) + threadIdx.x;
        if (t >= 16384) return;
        const float* W = (seg == 0) ? w0 : (seg == 1) ? w1 : (seg == 2) ? w2
                        : (seg == 3) ? w3 : w4;
        __nv_bfloat16* out = g_wt + (size_t)seg * 32768;
        int n = t >> 7, k = t & 127;
        float v = __ldg(&W[(size_t)k * 128 + n]);
        __nv_bfloat16 h = __float2bfloat16(v);
        out[t] = h;
        out[16384 + t] = __float2bfloat16(v - __bfloat162float(h));
    } else {
        int t = ((b - 320) << 8) + threadIdx.x;    // gc2W: 40x128 = 5120
        if (t >= 5120) return;
        __nv_bfloat16* out = g_wt + (size_t)5 * 32768;
        int n = t >> 7, k = t & 127;
        float v = __ldg(&w5[(size_t)k * 40 + n]);
        __nv_bfloat16 h = __float2bfloat16(v);
        out[t] = h;
        out[5120 + t] = __float2bfloat16(v - __bfloat162float(h));
    }
}

// ---------------- tensor-core GEMM: Y = X[M,128] @ W[128,128], split bf16 ----------------
// Dual-output via blockIdx.y: y==0 -> (WA,Y1), y==1 -> (WB,Y2).
#define WROW 68
__global__ void __launch_bounds__(256, 2) gemm_mma(
    const float* __restrict__ X,
    const __nv_bfloat16* __restrict__ WA, const __nv_bfloat16* __restrict__ WB,
    float* __restrict__ Y1, float* __restrict__ Y2, int M)
{
    extern __shared__ uint32_t sm[];
    uint32_t* XH = sm;            // 64*68 = 4352
    uint32_t* XL = sm + 4352;
    uint32_t* BH = sm + 8704;     // 128*68 = 8704
    uint32_t* BL = sm + 17408;    // total 26112 u32 = 104448 B
    const int tid = threadIdx.x;
    const int row0 = blockIdx.x * 64;
    const __nv_bfloat16* W = (blockIdx.y == 0) ? WA : WB;
    float* Y = (blockIdx.y == 0) ? Y1 : Y2;

    for (int i = tid; i < 1024; i += 256) {
        int r = i >> 4, c8 = (i & 15) << 3;
        int gr = row0 + r;
        float4 v0 = make_float4(0.f, 0.f, 0.f, 0.f), v1 = v0;
        if (gr < M) {
            const float4* xp = (const float4*)(X + (size_t)gr * 128 + c8);
            v0 = __ldg(xp); v1 = __ldg(xp + 1);
        }
        uint32_t hi[4], lo[4];
        split_bf16(v0.x, v0.y, hi[0], lo[0]);
        split_bf16(v0.z, v0.w, hi[1], lo[1]);
        split_bf16(v1.x, v1.y, hi[2], lo[2]);
        split_bf16(v1.z, v1.w, hi[3], lo[3]);
        int si = r * WROW + (c8 >> 1);
        *(uint4*)(XH + si) = make_uint4(hi[0], hi[1], hi[2], hi[3]);
        *(uint4*)(XL + si) = make_uint4(lo[0], lo[1], lo[2], lo[3]);
    }
    {
        const uint4* wa = (const uint4*)W;
        for (int i = tid; i < 2048; i += 256) {
            int r = i >> 4, c4 = (i & 15) << 2;
            int si = r * WROW + c4;
            *(uint4*)(BH + si) = __ldg(wa + i);
            *(uint4*)(BL + si) = __ldg(wa + 2048 + i);
        }
    }
    __syncthreads();

    const int wid = tid >> 5, lane = tid & 31;
    const int wm = wid & 1, wn = wid >> 1;     // 2 x 4 warp grid
    const int g = lane >> 2, tq = lane & 3;

    float C[2][4][4];
    #pragma unroll
    for (int mt = 0; mt < 2; mt++)
        #pragma unroll
        for (int nt = 0; nt < 4; nt++)
            #pragma unroll
            for (int j = 0; j < 4; j++) C[mt][nt][j] = 0.f;

    #pragma unroll
    for (int ks = 0; ks < 8; ks++) {
        uint32_t Ah[2][4], Al[2][4];
        #pragma unroll
        for (int mt = 0; mt < 2; mt++) {
            int r0 = (wm * 32 + mt * 16 + g) * WROW + ks * 8 + tq;
            Ah[mt][0] = XH[r0];        Ah[mt][1] = XH[r0 + 8 * WROW];
            Ah[mt][2] = XH[r0 + 4];    Ah[mt][3] = XH[r0 + 8 * WROW + 4];
            Al[mt][0] = XL[r0];        Al[mt][1] = XL[r0 + 8 * WROW];
            Al[mt][2] = XL[r0 + 4];    Al[mt][3] = XL[r0 + 8 * WROW + 4];
        }
        #pragma unroll
        for (int nt = 0; nt < 4; nt++) {
            int bi = (wn * 32 + nt * 8 + g) * WROW + ks * 8 + tq;
            uint32_t bh0 = BH[bi], bh1 = BH[bi + 4];
            uint32_t bl0 = BL[bi], bl1 = BL[bi + 4];
            #pragma unroll
            for (int mt = 0; mt < 2; mt++) {
                mma16816(C[mt][nt], Ah[mt], bh0, bh1);
                mma16816(C[mt][nt], Ah[mt], bl0, bl1);
                mma16816(C[mt][nt], Al[mt], bh0, bh1);
            }
        }
    }
    #pragma unroll
    for (int mt = 0; mt < 2; mt++) {
        int row = row0 + wm * 32 + mt * 16 + g;
        #pragma unroll
        for (int nt = 0; nt < 4; nt++) {
            int col = wn * 32 + nt * 8 + tq * 2;
            if (row < M)
                *(float2*)(Y + (size_t)row * 128 + col) =
                    make_float2(C[mt][nt][0], C[mt][nt][1]);
            if (row + 8 < M)
                *(float2*)(Y + (size_t)(row + 8) * 128 + col) =
                    make_float2(C[mt][nt][2], C[mt][nt][3]);
        }
    }
}

// ---- fused: crf = U1[assign0[row]] + gcn[row]; write crf_sec; T = crf @ gc2W (mma) ----
__global__ void __launch_bounds__(256, 2) gemm40_mma(
    const float* __restrict__ U1, const int* __restrict__ assign0,
    const float* __restrict__ gcn, float* __restrict__ crf_out,
    float* __restrict__ Y, int M)
{
    extern __shared__ uint32_t sm[];
    uint32_t* XH = sm;
    uint32_t* XL = sm + 4352;
    uint32_t* BH = sm + 8704;
    uint32_t* BL = sm + 13056;
    const int tid = threadIdx.x;
    const int row0 = blockIdx.x * 64;
    const __nv_bfloat16* W40 = g_wt + (size_t)5 * 32768;

    for (int i = tid; i < 1024; i += 256) {
        int r = i >> 4, c8 = (i & 15) << 3;
        int gr = row0 + r;
        float4 v0 = make_float4(0.f, 0.f, 0.f, 0.f), v1 = v0;
        if (gr < M) {
            int a = __ldg(&assign0[gr]);
            const float4* up = (const float4*)(U1 + (size_t)a * 128 + c8);
            const float4* gp = (const float4*)(gcn + (size_t)gr * 128 + c8);
            float4 u0 = __ldg(up), u1 = __ldg(up + 1);
            float4 g0 = __ldg(gp), g1 = __ldg(gp + 1);
            v0.x = u0.x + g0.x; v0.y = u0.y + g0.y; v0.z = u0.z + g0.z; v0.w = u0.w + g0.w;
            v1.x = u1.x + g1.x; v1.y = u1.y + g1.y; v1.z = u1.z + g1.z; v1.w = u1.w + g1.w;
            float4* cp = (float4*)(crf_out + (size_t)gr * 128 + c8);
            cp[0] = v0; cp[1] = v1;
        }
        uint32_t hi[4], lo[4];
        split_bf16(v0.x, v0.y, hi[0], lo[0]);
        split_bf16(v0.z, v0.w, hi[1], lo[1]);
        split_bf16(v1.x, v1.y, hi[2], lo[2]);
        split_bf16(v1.z, v1.w, hi[3], lo[3]);
        int si = r * WROW + (c8 >> 1);
        *(uint4*)(XH + si) = make_uint4(hi[0], hi[1], hi[2], hi[3]);
        *(uint4*)(XL + si) = make_uint4(lo[0], lo[1], lo[2], lo[3]);
    }
    {
        const uint4* wh = (const uint4*)W40;
        const uint4* wl = (const uint4*)(W40 + 5120);
        for (int i = tid; i < 1024; i += 256) {
            int r = i >> 4, c4 = (i & 15) << 2;
            int si = r * WROW + c4;
            uint4 h = make_uint4(0, 0, 0, 0), l = h;
            if (r < 40) { h = __ldg(wh + i); l = __ldg(wl + i); }
            *(uint4*)(BH + si) = h;
            *(uint4*)(BL + si) = l;
        }
    }
    __syncthreads();

    const int wid = tid >> 5, lane = tid & 31;
    const int wm = wid & 3, wn = wid >> 2;     // 4x2 grid; 16x32 warp tiles
    const int g = lane >> 2, tq = lane & 3;

    float C[4][4];
    #pragma unroll
    for (int nt = 0; nt < 4; nt++)
        #pragma unroll
        for (int j = 0; j < 4; j++) C[nt][j] = 0.f;

    #pragma unroll
    for (int ks = 0; ks < 8; ks++) {
        uint32_t Ah[4], Al[4];
        int r0 = (wm * 16 + g) * WROW + ks * 8 + tq;
        Ah[0] = XH[r0];        Ah[1] = XH[r0 + 8 * WROW];
        Ah[2] = XH[r0 + 4];    Ah[3] = XH[r0 + 8 * WROW + 4];
        Al[0] = XL[r0];        Al[1] = XL[r0 + 8 * WROW];
        Al[2] = XL[r0 + 4];    Al[3] = XL[r0 + 8 * WROW + 4];
        #pragma unroll
        for (int nt = 0; nt < 4; nt++) {
            int bi = (wn * 32 + nt * 8 + g) * WROW + ks * 8 + tq;
            uint32_t bh0 = BH[bi], bh1 = BH[bi + 4];
            uint32_t bl0 = BL[bi], bl1 = BL[bi + 4];
            mma16816(C[nt], Ah, bh0, bh1);
            mma16816(C[nt], Ah, bl0, bl1);
            mma16816(C[nt], Al, bh0, bh1);
        }
    }
    {
        int row = row0 + wm * 16 + g;
        #pragma unroll
        for (int nt = 0; nt < 4; nt++) {
            int col = wn * 32 + nt * 8 + tq * 2;
            if (col < 40) {
                if (row < M)
                    *(float2*)(Y + (size_t)row * 40 + col) = make_float2(C[nt][0], C[nt][1]);
                if (row + 8 < M)
                    *(float2*)(Y + (size_t)(row + 8) * 40 + col) = make_float2(C[nt][2], C[nt][3]);
            }
        }
    }
}

// ---------------- batched CSR build kernels ----------------
__global__ void kzero_all() {
    int i = blockIdx.x * 256 + threadIdx.x;
    if (i < 100000)      g_i[I_CNT0 + i] = 0;
    else if (i < 125000) g_i[I_CNT1 + (i - 100000)] = 0;
    else if (i < 131250) g_i[I_CNT2 + (i - 125000)] = 0;
    else if (i < 156250) g_i[I_PCN1 + (i - 131250)] = 0;
    else if (i < 162500) g_i[I_PCN2 + (i - 156250)] = 0;
}
// 4-wide histogram: all segment boundaries are multiples of 4
__global__ void khist_all(const int* __restrict__ A0, const int* __restrict__ A1,
                          const int* __restrict__ A2, const int* __restrict__ as0,
                          const int* __restrict__ as1) {
    int i4 = (blockIdx.x * 256 + threadIdx.x) * 4;
    if (i4 >= 2225000) return;
    if (i4 < 1600000) {
        int4 d = __ldg((const int4*)(A0 + i4));
        atomicAdd(&g_i[I_CNT0 + d.x], 1); atomicAdd(&g_i[I_CNT0 + d.y], 1);
        atomicAdd(&g_i[I_CNT0 + d.z], 1); atomicAdd(&g_i[I_CNT0 + d.w], 1);
    } else if (i4 < 2000000) {
        int4 d = __ldg((const int4*)(A1 + (i4 - 1600000)));
        atomicAdd(&g_i[I_CNT1 + d.x], 1); atomicAdd(&g_i[I_CNT1 + d.y], 1);
        atomicAdd(&g_i[I_CNT1 + d.z], 1); atomicAdd(&g_i[I_CNT1 + d.w], 1);
    } else if (i4 < 2100000) {
        int4 d = __ldg((const int4*)(A2 + (i4 - 2000000)));
        atomicAdd(&g_i[I_CNT2 + d.x], 1); atomicAdd(&g_i[I_CNT2 + d.y], 1);
        atomicAdd(&g_i[I_CNT2 + d.z], 1); atomicAdd(&g_i[I_CNT2 + d.w], 1);
    } else if (i4 < 2200000) {
        int4 d = __ldg((const int4*)(as0 + (i4 - 2100000)));
        atomicAdd(&g_i[I_PCN1 + d.x], 1); atomicAdd(&g_i[I_PCN1 + d.y], 1);
        atomicAdd(&g_i[I_PCN1 + d.z], 1); atomicAdd(&g_i[I_PCN1 + d.w], 1);
    } else {
        int4 d = __ldg((const int4*)(as1 + (i4 - 2200000)));
        atomicAdd(&g_i[I_PCN2 + d.x], 1); atomicAdd(&g_i[I_PCN2 + d.y], 1);
        atomicAdd(&g_i[I_PCN2 + d.z], 1); atomicAdd(&g_i[I_PCN2 + d.w], 1);
    }
}
__global__ void scan_blk_all() {
    __shared__ int wsum[32];
    Seg s = seg_resolve(blockIdx.x);
    int t = threadIdx.x;
    int i = s.sblk * 1024 + t;
    int v = (i < s.n) ? s.cnt[i] : 0;
    int x = v;
    #pragma unroll
    for (int o = 1; o < 32; o <<= 1) {
        int tmp = __shfl_up_sync(0xffffffffu, x, o);
        if ((t & 31) >= o) x += tmp;
    }
    if ((t & 31) == 31) wsum[t >> 5] = x;
    __syncthreads();
    if (t < 32) {
        int y = wsum[t];
        #pragma unroll
        for (int o = 1; o < 32; o <<= 1) {
            int tmp = __shfl_up_sync(0xffffffffu, y, o);
            if (t >= o) y += tmp;
        }
        wsum[t] = y;
    }
    __syncthreads();
    int base = (t >= 32) ? wsum[(t >> 5) - 1] : 0;
    int incl = base + x;
    if (i < s.n) s.off[i] = incl - v;
    if (t == 1023) g_i[I_PART + s.pbase + s.sblk] = incl;
}
__global__ void scan_part_all() {
    __shared__ int sh[128];
    const int bases[5] = {0, 98, 123, 130, 155};
    const int cnts[5]  = {98, 25, 7, 25, 7};
    int b = blockIdx.x, t = threadIdx.x;
    int* part = g_i + I_PART + bases[b];
    int nb = cnts[b];
    int v = (t < nb) ? part[t] : 0;
    sh[t] = v;
    __syncthreads();
    #pragma unroll
    for (int o = 1; o < 128; o <<= 1) {
        int tmp = (t >= o) ? sh[t - o] : 0;
        __syncthreads();
        sh[t] += tmp;
        __syncthreads();
    }
    if (t < nb) part[t] = sh[t] - v;
    if (t == 0) {
        int total = sh[127];
        int* off = (b == 0) ? g_i + I_OFF0 : (b == 1) ? g_i + I_OFF1
                 : (b == 2) ? g_i + I_OFF2 : (b == 3) ? g_i + I_POF0 : g_i + I_POF1;
        int n = (b == 0) ? N0c : (b == 1) ? N1c : (b == 2) ? N2c
              : (b == 3) ? N1c : N2c;
        off[n] = total;
    }
}
__global__ void scan_add_all() {
    Seg s = seg_resolve(blockIdx.x);
    int i = s.sblk * 1024 + threadIdx.x;
    if (i < s.n) {
        int v = s.off[i] + g_i[I_PART + s.pbase + s.sblk];
        s.off[i] = v;
        s.cur[i] = v;
    }
}
// 4-wide scatter over [lo, hi); boundaries are multiples of 4
__global__ void kscatter_all(const int* __restrict__ A0, const float* __restrict__ A0v,
                             const int* __restrict__ A1, const float* __restrict__ A1v,
                             const int* __restrict__ A2, const float* __restrict__ A2v,
                             const int* __restrict__ as0, const int* __restrict__ as1,
                             int lo, int hi) {
    int i4 = lo + (blockIdx.x * 256 + threadIdx.x) * 4;
    if (i4 >= hi) return;
    if (i4 < 1600000) {
        int4 d  = __ldg((const int4*)(A0 + i4));
        int4 sv = __ldg((const int4*)(A0 + 1600000 + i4));
        float4 vv = __ldg((const float4*)(A0v + i4));
        int p;
        p = atomicAdd(&g_i[I_CNT0 + d.x], 1); g_i[I_SRC0 + p] = sv.x; g_f[F_VAL0 + p] = vv.x;
        p = atomicAdd(&g_i[I_CNT0 + d.y], 1); g_i[I_SRC0 + p] = sv.y; g_f[F_VAL0 + p] = vv.y;
        p = atomicAdd(&g_i[I_CNT0 + d.z], 1); g_i[I_SRC0 + p] = sv.z; g_f[F_VAL0 + p] = vv.z;
        p = atomicAdd(&g_i[I_CNT0 + d.w], 1); g_i[I_SRC0 + p] = sv.w; g_f[F_VAL0 + p] = vv.w;
    } else if (i4 < 2000000) {
        int e = i4 - 1600000;
        int4 d  = __ldg((const int4*)(A1 + e));
        int4 sv = __ldg((const int4*)(A1 + 400000 + e));
        float4 vv = __ldg((const float4*)(A1v + e));
        int p;
        p = atomicAdd(&g_i[I_CNT1 + d.x], 1); g_i[I_SRC1 + p] = sv.x; g_f[F_VAL1 + p] = vv.x;
        p = atomicAdd(&g_i[I_CNT1 + d.y], 1); g_i[I_SRC1 + p] = sv.y; g_f[F_VAL1 + p] = vv.y;
        p = atomicAdd(&g_i[I_CNT1 + d.z], 1); g_i[I_SRC1 + p] = sv.z; g_f[F_VAL1 + p] = vv.z;
        p = atomicAdd(&g_i[I_CNT1 + d.w], 1); g_i[I_SRC1 + p] = sv.w; g_f[F_VAL1 + p] = vv.w;
    } else if (i4 < 2100000) {
        int e = i4 - 2000000;
        int4 d  = __ldg((const int4*)(A2 + e));
        int4 sv = __ldg((const int4*)(A2 + 100000 + e));
        float4 vv = __ldg((const float4*)(A2v + e));
        int p;
        p = atomicAdd(&g_i[I_CNT2 + d.x], 1); g_i[I_SRC2 + p] = sv.x; g_f[F_VAL2 + p] = vv.x;
        p = atomicAdd(&g_i[I_CNT2 + d.y], 1); g_i[I_SRC2 + p] = sv.y; g_f[F_VAL2 + p] = vv.y;
        p = atomicAdd(&g_i[I_CNT2 + d.z], 1); g_i[I_SRC2 + p] = sv.z; g_f[F_VAL2 + p] = vv.z;
        p = atomicAdd(&g_i[I_CNT2 + d.w], 1); g_i[I_SRC2 + p] = sv.w; g_f[F_VAL2 + p] = vv.w;
    } else if (i4 < 2200000) {
        int e = i4 - 2100000;
        int4 d = __ldg((const int4*)(as0 + e));
        int p;
        p = atomicAdd(&g_i[I_PCN1 + d.x], 1); g_i[I_PID0 + p] = e;
        p = atomicAdd(&g_i[I_PCN1 + d.y], 1); g_i[I_PID0 + p] = e + 1;
        p = atomicAdd(&g_i[I_PCN1 + d.z], 1); g_i[I_PID0 + p] = e + 2;
        p = atomicAdd(&g_i[I_PCN1 + d.w], 1); g_i[I_PID0 + p] = e + 3;
    } else {
        int e = i4 - 2200000;
        int4 d = __ldg((const int4*)(as1 + e));
        int p;
        p = atomicAdd(&g_i[I_PCN2 + d.x], 1); g_i[I_PID1 + p] = e;
        p = atomicAdd(&g_i[I_PCN2 + d.y], 1); g_i[I_PID1 + p] = e + 1;
        p = atomicAdd(&g_i[I_PCN2 + d.z], 1); g_i[I_PID1 + p] = e + 2;
        p = atomicAdd(&g_i[I_PCN2 + d.w], 1); g_i[I_PID1 + p] = e + 3;
    }
}

// ---------------- CSR SpMM, 128 cols, warp per row, unroll-2 ----------------
__global__ void spmm128(const int* __restrict__ off, const int* __restrict__ srcs,
                        const float* __restrict__ vals, const float* __restrict__ X,
                        const float* __restrict__ bias, float* __restrict__ Y,
                        int n, int relu) {
    int row = blockIdx.x * blockDim.y + threadIdx.y;
    if (row >= n) return;
    int lane = threadIdx.x;
    int s = off[row], e = off[row + 1];
    float4 acc = make_float4(0.f, 0.f, 0.f, 0.f);
    int j = s;
    for (; j + 2 <= e; j += 2) {
        int s0 = __ldg(&srcs[j]), s1 = __ldg(&srcs[j + 1]);
        float v0 = __ldg(&vals[j]), v1 = __ldg(&vals[j + 1]);
        float4 x0 = __ldg((const float4*)(X + (size_t)s0 * 128) + lane);
        float4 x1 = __ldg((const float4*)(X + (size_t)s1 * 128) + lane);
        acc.x = fmaf(v0, x0.x, acc.x); acc.y = fmaf(v0, x0.y, acc.y);
        acc.z = fmaf(v0, x0.z, acc.z); acc.w = fmaf(v0, x0.w, acc.w);
        acc.x = fmaf(v1, x1.x, acc.x); acc.y = fmaf(v1, x1.y, acc.y);
        acc.z = fmaf(v1, x1.z, acc.z); acc.w = fmaf(v1, x1.w, acc.w);
    }
    if (j < e) {
        int src = __ldg(&srcs[j]);
        float v = __ldg(&vals[j]);
        float4 xv = __ldg((const float4*)(X + (size_t)src * 128) + lane);
        acc.x = fmaf(v, xv.x, acc.x); acc.y = fmaf(v, xv.y, acc.y);
        acc.z = fmaf(v, xv.z, acc.z); acc.w = fmaf(v, xv.w, acc.w);
    }
    float4 b = __ldg((const float4*)bias + lane);
    acc.x += b.x; acc.y += b.y; acc.z += b.z; acc.w += b.w;
    if (relu) {
        acc.x = fmaxf(acc.x, 0.f); acc.y = fmaxf(acc.y, 0.f);
        acc.z = fmaxf(acc.z, 0.f); acc.w = fmaxf(acc.w, 0.f);
    }
    *((float4*)(Y + (size_t)row * 128) + lane) = acc;
}

// ---------------- CSR SpMM, 40 cols, warp per row, unroll-2 ----------------
__global__ void spmm40(const int* __restrict__ off, const int* __restrict__ srcs,
                       const float* __restrict__ vals, const float* __restrict__ X,
                       const float* __restrict__ bias, float* __restrict__ Y, int n) {
    int row = blockIdx.x * blockDim.y + threadIdx.y;
    if (row >= n) return;
    int lane = threadIdx.x;
    int s = off[row], e = off[row + 1];
    float a0 = 0.f, a1 = 0.f;
    int j = s;
    for (; j + 2 <= e; j += 2) {
        int s0 = __ldg(&srcs[j]), s1 = __ldg(&srcs[j + 1]);
        float v0 = __ldg(&vals[j]), v1 = __ldg(&vals[j + 1]);
        float x0a = __ldg(&X[(size_t)s0 * 40 + lane]);
        float x1a = __ldg(&X[(size_t)s1 * 40 + lane]);
        float x0b = 0.f, x1b = 0.f;
        if (lane < 8) {
            x0b = __ldg(&X[(size_t)s0 * 40 + 32 + lane]);
            x1b = __ldg(&X[(size_t)s1 * 40 + 32 + lane]);
        }
        a0 = fmaf(v0, x0a, a0); a0 = fmaf(v1, x1a, a0);
        a1 = fmaf(v0, x0b, a1); a1 = fmaf(v1, x1b, a1);
    }
    if (j < e) {
        int src = __ldg(&srcs[j]);
        float v = __ldg(&vals[j]);
        a0 = fmaf(v, __ldg(&X[(size_t)src * 40 + lane]), a0);
        if (lane < 8) a1 = fmaf(v, __ldg(&X[(size_t)src * 40 + 32 + lane]), a1);
    }
    Y[(size_t)row * 40 + lane] = a0 + __ldg(&bias[lane]);
    if (lane < 8) Y[(size_t)row * 40 + 32 + lane] = a1 + __ldg(&bias[32 + lane]);
}

// ---------------- pooling via CSR gather + fused emb add, unroll-2 ----------------
__global__ void pool_gather(const int* __restrict__ off, const int* __restrict__ ids,
                            const float* __restrict__ X,
                            const int* __restrict__ nw, const float* __restrict__ emb,
                            float* __restrict__ H, float* __restrict__ H0, int n) {
    int row = blockIdx.x * blockDim.y + threadIdx.y;
    if (row >= n) return;
    int lane = threadIdx.x;
    int s = off[row], e = off[row + 1];
    float4 acc = make_float4(0.f, 0.f, 0.f, 0.f);
    int j = s;
    for (; j + 2 <= e; j += 2) {
        int n0 = __ldg(&ids[j]), n1 = __ldg(&ids[j + 1]);
        float4 v0 = __ldg((const float4*)(X + (size_t)n0 * 128) + lane);
        float4 v1 = __ldg((const float4*)(X + (size_t)n1 * 128) + lane);
        acc.x += v0.x + v1.x; acc.y += v0.y + v1.y;
        acc.z += v0.z + v1.z; acc.w += v0.w + v1.w;
    }
    if (j < e) {
        int node = __ldg(&ids[j]);
        float4 v = __ldg((const float4*)(X + (size_t)node * 128) + lane);
        acc.x += v.x; acc.y += v.y; acc.z += v.z; acc.w += v.w;
    }
    *((float4*)(H + (size_t)row * 128) + lane) = acc;
    int w = __ldg(&nw[row]);
    float4 em = __ldg((const float4*)(emb + (size_t)w * 128) + lane);
    acc.x += em.x; acc.y += em.y; acc.z += em.z; acc.w += em.w;
    *((float4*)(H0 + (size_t)row * 128) + lane) = acc;
}

// ---------------- CRF refinement: warp per dst row, online softmax, unroll-2 ----------
__global__ void crf_refine(const int* __restrict__ off, const int* __restrict__ srcs,
                           const float* __restrict__ Q, const float* __restrict__ Km,
                           const float* __restrict__ H0,
                           const float* __restrict__ alpha_p, const float* __restrict__ beta_p,
                           float* __restrict__ Out, int n) {
    int row = blockIdx.x * blockDim.y + threadIdx.y;
    if (row >= n) return;
    int lane = threadIdx.x;
    float4 q = __ldg((const float4*)(Q + (size_t)row * 128) + lane);
    int s = off[row], e = off[row + 1];
    float m = -3.4e38f, z = 0.f;
    float4 macc = make_float4(0.f, 0.f, 0.f, 0.f);
    int j = s;
    for (; j + 2 <= e; j += 2) {
        int s0 = __ldg(&srcs[j]), s1 = __ldg(&srcs[j + 1]);
        float4 k0 = __ldg((const float4*)(Km + (size_t)s0 * 128) + lane);
        float4 k1 = __ldg((const float4*)(Km + (size_t)s1 * 128) + lane);
        float4 h0 = __ldg((const float4*)(H0 + (size_t)s0 * 128) + lane);
        float4 h1 = __ldg((const float4*)(H0 + (size_t)s1 * 128) + lane);
        float p0 = q.x * k0.x + q.y * k0.y + q.z * k0.z + q.w * k0.w;
        float p1 = q.x * k1.x + q.y * k1.y + q.z * k1.z + q.w * k1.w;
        #pragma unroll
        for (int o = 16; o; o >>= 1) {
            p0 += __shfl_xor_sync(0xffffffffu, p0, o);
            p1 += __shfl_xor_sync(0xffffffffu, p1, o);
        }
        p0 *= 0.08838834764831845f;
        p1 *= 0.08838834764831845f;
        if (p0 > m) {
            float sc = __expf(m - p0);
            z *= sc; macc.x *= sc; macc.y *= sc; macc.z *= sc; macc.w *= sc;
            m = p0;
        }
        float w0 = __expf(p0 - m);
        z += w0;
        macc.x = fmaf(w0, h0.x, macc.x); macc.y = fmaf(w0, h0.y, macc.y);
        macc.z = fmaf(w0, h0.z, macc.z); macc.w = fmaf(w0, h0.w, macc.w);
        if (p1 > m) {
            float sc = __expf(m - p1);
            z *= sc; macc.x *= sc; macc.y *= sc; macc.z *= sc; macc.w *= sc;
            m = p1;
        }
        float w1 = __expf(p1 - m);
        z += w1;
        macc.x = fmaf(w1, h1.x, macc.x); macc.y = fmaf(w1, h1.y, macc.y);
        macc.z = fmaf(w1, h1.z, macc.z); macc.w = fmaf(w1, h1.w, macc.w);
    }
    if (j < e) {
        int src = __ldg(&srcs[j]);
        float4 kv = __ldg((const float4*)(Km + (size_t)src * 128) + lane);
        float4 hv = __ldg((const float4*)(H0 + (size_t)src * 128) + lane);
        float p = q.x * kv.x + q.y * kv.y + q.z * kv.z + q.w * kv.w;
        #pragma unroll
        for (int o = 16; o; o >>= 1) p += __shfl_xor_sync(0xffffffffu, p, o);
        p *= 0.08838834764831845f;
        if (p > m) {
            float sc = __expf(m - p);
            z *= sc; macc.x *= sc; macc.y *= sc; macc.z *= sc; macc.w *= sc;
            m = p;
        }
        float w = __expf(p - m);
        z += w;
        macc.x = fmaf(w, hv.x, macc.x); macc.y = fmaf(w, hv.y, macc.y);
        macc.z = fmaf(w, hv.z, macc.z); macc.w = fmaf(w, hv.w, macc.w);
    }
    float alpha = __ldg(alpha_p), beta = __ldg(beta_p);
    float4 h0d = __ldg((const float4*)(H0 + (size_t)row * 128) + lane);
    float invz = 1.f / (z + 1e-16f);
    float invab = 1.f / (alpha + beta);
    float4 r;
    r.x = (alpha * h0d.x + beta * macc.x * invz) * invab;
    r.y = (alpha * h0d.y + beta * macc.y * invz) * invab;
    r.z = (alpha * h0d.z + beta * macc.z * invz) * invab;
    r.w = (alpha * h0d.w + beta * macc.w * invz) * invab;
    *((float4*)(Out + (size_t)row * 128) + lane) = r;
}

// ---------------- unpool + skip ----------------
__global__ void unpool_add(const float* __restrict__ Hi, const int* __restrict__ assign,
                           const float* __restrict__ skip, float* __restrict__ Out, int n) {
    int i = blockIdx.x * blockDim.y + threadIdx.y;
    if (i >= n) return;
    int lane = threadIdx.x;
    int a = assign[i];
    float4 v = __ldg((const float4*)(Hi + (size_t)a * 128) + lane);
    float4 sk = *((const float4*)(skip + (size_t)i * 128) + lane);
    v.x += sk.x; v.y += sk.y; v.z += sk.z; v.w += sk.w;
    *((float4*)(Out + (size_t)i * 128) + lane) = v;
}

// ---------------- streams/events (created at static init) ----------------
struct StreamEnv {
    cudaStream_t sB;
    cudaEvent_t evF, evB0, evB;
    StreamEnv() {
        cudaStreamCreateWithFlags(&sB, cudaStreamNonBlocking);
        cudaEventCreateWithFlags(&evF,  cudaEventDisableTiming);
        cudaEventCreateWithFlags(&evB0, cudaEventDisableTiming);
        cudaEventCreateWithFlags(&evB,  cudaEventDisableTiming);
    }
};
static StreamEnv g_se;

// ---------------- host ----------------
extern "C" void kernel_launch(void* const* d_in, const int* in_sizes, int n_in,
                              void* d_out, int out_size) {
    const float* x       = (const float*)d_in[0];
    const int*   A0      = (const int*)d_in[1];
    const float* A0v     = (const float*)d_in[2];
    const int*   A1      = (const int*)d_in[3];
    const float* A1v     = (const float*)d_in[4];
    const int*   A2      = (const int*)d_in[5];
    const float* A2v     = (const float*)d_in[6];
    const int*   assign0 = (const int*)d_in[7];
    const int*   assign1 = (const int*)d_in[8];
    const int*   nwgt1   = (const int*)d_in[9];
    const int*   nwgt2   = (const int*)d_in[10];
    const float* gc1b    = (const float*)d_in[12];
    const float* gc2b    = (const float*)d_in[14];
    const float* c1emb   = (const float*)d_in[17];
    const float* c1a     = (const float*)d_in[18];
    const float* c1be    = (const float*)d_in[19];
    const float* c2emb   = (const float*)d_in[22];
    const float* c2a     = (const float*)d_in[23];
    const float* c2be    = (const float*)d_in[24];

    float* out_sec = (float*)d_out;
    float* gcn_sec = out_sec + (size_t)N0c * NCc;
    float* crf_sec = gcn_sec + (size_t)N0c * NFc;

    void* fp; cudaGetSymbolAddress(&fp, g_f);
    void* ip; cudaGetSymbolAddress(&ip, g_i);
    void* wp; cudaGetSymbolAddress(&wp, g_wt);
    float* F = (float*)fp;
    int*   I = (int*)ip;
    __nv_bfloat16* WT = (__nv_bfloat16*)wp;

    float* xW  = F + F_XW;  float* T   = F + F_T;
    float* H1  = F + F_H1;  float* H01 = F + F_H01;
    float* Q1  = F + F_Q1;  float* K1  = F + F_K1;
    float* H1R = F + F_H1R; float* U1  = F + F_U1;
    float* H2  = F + F_H2;  float* H02 = F + F_H02;
    float* Q2  = F + F_Q2;  float* K2  = F + F_K2;
    float* H2R = F + F_H2R;
    float* V0  = F + F_VAL0;

    int* OFF0 = I + I_OFF0; int* SRC0 = I + I_SRC0;
    int* OFF1 = I + I_OFF1; int* SRC1 = I + I_SRC1;
    int* OFF2 = I + I_OFF2; int* SRC2 = I + I_SRC2;
    int* POF0 = I + I_POF0; int* PID0 = I + I_PID0;
    int* POF1 = I + I_POF1; int* PID1 = I + I_PID1;

    __nv_bfloat16* WT_gc1 = WT + 0 * 32768;
    __nv_bfloat16* WT_q1  = WT + 1 * 32768;
    __nv_bfloat16* WT_k1  = WT + 2 * 32768;
    __nv_bfloat16* WT_q2  = WT + 3 * 32768;
    __nv_bfloat16* WT_k2  = WT + 4 * 32768;

    const int SMEM_G  = 26112 * 4;
    const int SMEM_40 = 17408 * 4;

    static bool attr_done = false;
    if (!attr_done) {
        cudaFuncSetAttribute(gemm_mma, cudaFuncAttributeMaxDynamicSharedMemorySize, SMEM_G);
        cudaFuncSetAttribute(gemm40_mma, cudaFuncAttributeMaxDynamicSharedMemorySize, SMEM_40);
        attr_done = true;
    }

    dim3 warp8(32, 8);
    cudaStream_t s0 = 0;
    cudaStream_t sB = g_se.sB;

    cudaEventRecord(g_se.evF, s0);
    cudaStreamWaitEvent(sB, g_se.evF, 0);

    // enqueue order keeps gemm_mma(gc1) as 4th launch for ncu
    wprep_all<<<340, 256, 0, s0>>>((const float*)d_in[11], (const float*)d_in[15],
                                   (const float*)d_in[16], (const float*)d_in[20],
                                   (const float*)d_in[21], (const float*)d_in[13]);
    kzero_all<<<(162500 + 255) / 256, 256, 0, sB>>>();
    khist_all<<<(556250 + 255) / 256, 256, 0, sB>>>(A0, A1, A2, assign0, assign1);
    gemm_mma<<<dim3((N0c + 63) / 64, 1), 256, SMEM_G, s0>>>(x, WT_gc1, WT_gc1,
                                                            xW, xW, N0c);
    scan_blk_all<<<SCAN_BLOCKS, 1024, 0, sB>>>();
    scan_part_all<<<5, 128, 0, sB>>>();
    scan_add_all<<<SCAN_BLOCKS, 1024, 0, sB>>>();
    // scatter A0 first; spmm128 only needs this part
    kscatter_all<<<(400000 + 255) / 256, 256, 0, sB>>>(A0, A0v, A1, A1v, A2, A2v,
                                                       assign0, assign1, 0, 1600000);
    cudaEventRecord(g_se.evB0, sB);
    kscatter_all<<<(156250 + 255) / 256, 256, 0, sB>>>(A0, A0v, A1, A1v, A2, A2v,
                                                       assign0, assign1,
                                                       1600000, 2225000);
    cudaEventRecord(g_se.evB, sB);

    cudaStreamWaitEvent(s0, g_se.evB0, 0);
    spmm128<<<(N0c + 7) / 8, warp8, 0, s0>>>(OFF0, SRC0, V0, xW, gc1b, gcn_sec, N0c, 1);

    cudaStreamWaitEvent(s0, g_se.evB, 0);
    // level 1: pool + dual QK GEMM (one launch, gridDim.y=2) + CRF
    pool_gather<<<(N1c + 7) / 8, warp8, 0, s0>>>(POF0, PID0, gcn_sec, nwgt1, c1emb,
                                                 H1, H01, N1c);
    gemm_mma<<<dim3((N1c + 63) / 64, 2), 256, SMEM_G, s0>>>(H1, WT_q1, WT_k1,
                                                            Q1, K1, N1c);
    crf_refine<<<(N1c + 7) / 8, warp8, 0, s0>>>(OFF1, SRC1, Q1, K1, H01, c1a, c1be,
                                                H1R, N1c);

    // level 2: pool + dual QK GEMM + CRF
    pool_gather<<<(N2c + 7) / 8, warp8, 0, s0>>>(POF1, PID1, H1R, nwgt2, c2emb,
                                                 H2, H02, N2c);
    gemm_mma<<<dim3((N2c + 63) / 64, 2), 256, SMEM_G, s0>>>(H2, WT_q2, WT_k2,
                                                            Q2, K2, N2c);
    crf_refine<<<(N2c + 7) / 8, warp8, 0, s0>>>(OFF2, SRC2, Q2, K2, H02, c2a, c2be,
                                                H2R, N2c);

    // unpool level 2->1
    unpool_add<<<(N1c + 7) / 8, warp8, 0, s0>>>(H2R, assign1, H1R, U1, N1c);

    // fused unpool 1->0 + gc2 GEMM
    gemm40_mma<<<(N0c + 63) / 64, 256, SMEM_40, s0>>>(U1, assign0, gcn_sec, crf_sec,
                                                      T, N0c);
    spmm40<<<(N0c + 7) / 8, warp8, 0, s0>>>(OFF0, SRC0, V0, T, gc2b, out_sec, N0c);
}

// round 17
// speedup vs baseline: 1.1193x; 1.0368x over previous
#include <cuda_runtime.h>
#include <cuda_bf16.h>
#include <cuda_fp16.h>
#include <math.h>
#include <stdint.h>

#define N0c 100000
#define N1c 25000
#define N2c 6250
#define E0c 1600000
#define E1c 400000
#define E2c 100000
#define NFc 128
#define NCc 40

// ---------------- scratch (no allocations allowed) ----------------
constexpr size_t F_XW   = 0;
constexpr size_t F_T    = F_XW  + (size_t)N0c*NFc;
constexpr size_t F_H1   = F_T   + (size_t)N0c*NCc;
constexpr size_t F_H01  = F_H1  + (size_t)N1c*NFc;
constexpr size_t F_Q1   = F_H01 + (size_t)N1c*NFc;
constexpr size_t F_K1   = F_Q1  + (size_t)N1c*NFc;
constexpr size_t F_H1R  = F_K1  + (size_t)N1c*NFc;
constexpr size_t F_U1   = F_H1R + (size_t)N1c*NFc;
constexpr size_t F_H2   = F_U1  + (size_t)N1c*NFc;
constexpr size_t F_H02  = F_H2  + (size_t)N2c*NFc;
constexpr size_t F_Q2   = F_H02 + (size_t)N2c*NFc;
constexpr size_t F_K2   = F_Q2  + (size_t)N2c*NFc;
constexpr size_t F_H2R  = F_K2  + (size_t)N2c*NFc;
constexpr size_t F_VAL0 = F_H2R + (size_t)N2c*NFc;
constexpr size_t F_VAL1 = F_VAL0 + (size_t)E0c;
constexpr size_t F_VAL2 = F_VAL1 + (size_t)E1c;
constexpr size_t F_TOT  = F_VAL2 + (size_t)E2c;
__device__ __align__(16) float g_f[F_TOT];

constexpr size_t I_OFF0 = 0;
constexpr size_t I_CNT0 = I_OFF0 + (size_t)N0c + 4;
constexpr size_t I_SRC0 = I_CNT0 + (size_t)N0c;
constexpr size_t I_OFF1 = I_SRC0 + (size_t)E0c;
constexpr size_t I_CNT1 = I_OFF1 + (size_t)N1c + 4;
constexpr size_t I_SRC1 = I_CNT1 + (size_t)N1c;
constexpr size_t I_OFF2 = I_SRC1 + (size_t)E1c;
constexpr size_t I_CNT2 = I_OFF2 + (size_t)N2c + 4;
constexpr size_t I_SRC2 = I_CNT2 + (size_t)N2c;
constexpr size_t I_POF0 = I_SRC2 + (size_t)E2c;
constexpr size_t I_PID0 = I_POF0 + (size_t)N1c + 4;
constexpr size_t I_POF1 = I_PID0 + (size_t)N0c;
constexpr size_t I_PID1 = I_POF1 + (size_t)N2c + 4;
constexpr size_t I_PART = I_PID1 + (size_t)N1c;
constexpr size_t I_PCN1 = I_PART + 256;
constexpr size_t I_PCN2 = I_PCN1 + (size_t)N1c;
constexpr size_t I_TOT  = I_PCN2 + (size_t)N2c;
__device__ int g_i[I_TOT];

// split-bf16 weights: 6 slots x 32768 bf16 (slot5 = gc2W, 40x128 hi + lo)
__device__ __align__(16) __nv_bfloat16 g_wt[6 * 32768];

#define SCAN_BLOCKS 162
struct Seg { int* cnt; int* off; int* cur; int pbase; int n; int sblk; };
__device__ __forceinline__ Seg seg_resolve(int b) {
    Seg s;
    if (b < 98)       { s.cnt = g_i + I_CNT0; s.off = g_i + I_OFF0; s.cur = g_i + I_CNT0; s.pbase = 0;   s.n = N0c; s.sblk = b; }
    else if (b < 123) { s.cnt = g_i + I_CNT1; s.off = g_i + I_OFF1; s.cur = g_i + I_CNT1; s.pbase = 98;  s.n = N1c; s.sblk = b - 98; }
    else if (b < 130) { s.cnt = g_i + I_CNT2; s.off = g_i + I_OFF2; s.cur = g_i + I_CNT2; s.pbase = 123; s.n = N2c; s.sblk = b - 123; }
    else if (b < 155) { s.cnt = g_i + I_PCN1; s.off = g_i + I_POF0; s.cur = g_i + I_PCN1; s.pbase = 130; s.n = N1c; s.sblk = b - 130; }
    else              { s.cnt = g_i + I_PCN2; s.off = g_i + I_POF1; s.cur = g_i + I_PCN2; s.pbase = 155; s.n = N2c; s.sblk = b - 155; }
    return s;
}

// ---------------- mma helpers ----------------
__device__ __forceinline__ void mma16816(float* c, const uint32_t* a,
                                         uint32_t b0, uint32_t b1) {
    asm volatile(
        "mma.sync.aligned.m16n8k16.row.col.f32.bf16.bf16.f32 "
        "{%0,%1,%2,%3}, {%4,%5,%6,%7}, {%8,%9}, {%0,%1,%2,%3};"
        : "+f"(c[0]), "+f"(c[1]), "+f"(c[2]), "+f"(c[3])
        : "r"(a[0]), "r"(a[1]), "r"(a[2]), "r"(a[3]), "r"(b0), "r"(b1));
}
__device__ __forceinline__ void split_bf16(float a, float b, uint32_t& hi, uint32_t& lo) {
    __nv_bfloat16 ha = __float2bfloat16(a), hb = __float2bfloat16(b);
    __nv_bfloat162 hp; hp.x = ha; hp.y = hb;
    __nv_bfloat162 lp;
    lp.x = __float2bfloat16(a - __bfloat162float(ha));
    lp.y = __float2bfloat16(b - __bfloat162float(hb));
    hi = *(uint32_t*)&hp;
    lo = *(uint32_t*)&lp;
}

// ---------------- batched weight prep: 5 x [128,128] + gc2W [128,40] ----------------
__global__ void wprep_all(const float* __restrict__ w0, const float* __restrict__ w1,
                          const float* __restrict__ w2, const float* __restrict__ w3,
                          const float* __restrict__ w4, const float* __restrict__ w5) {
    int b = blockIdx.x;
    if (b < 320) {
        int seg = b >> 6;
        int t = ((b & 63) << 8) + threadIdx.x;
        if (t >= 16384) return;
        const float* W = (seg == 0) ? w0 : (seg == 1) ? w1 : (seg == 2) ? w2
                        : (seg == 3) ? w3 : w4;
        __nv_bfloat16* out = g_wt + (size_t)seg * 32768;
        int n = t >> 7, k = t & 127;
        float v = __ldg(&W[(size_t)k * 128 + n]);
        __nv_bfloat16 h = __float2bfloat16(v);
        out[t] = h;
        out[16384 + t] = __float2bfloat16(v - __bfloat162float(h));
    } else {
        int t = ((b - 320) << 8) + threadIdx.x;    // gc2W: 40x128 = 5120
        if (t >= 5120) return;
        __nv_bfloat16* out = g_wt + (size_t)5 * 32768;
        int n = t >> 7, k = t & 127;
        float v = __ldg(&w5[(size_t)k * 40 + n]);
        __nv_bfloat16 h = __float2bfloat16(v);
        out[t] = h;
        out[5120 + t] = __float2bfloat16(v - __bfloat162float(h));
    }
}

// ---------------- tensor-core GEMM: Y = X[M,128] @ W[128,128], split bf16 ----------------
// Dual-output via blockIdx.y: y==0 -> (WA,Y1), y==1 -> (WB,Y2). fp32 outputs.
#define WROW 68
__global__ void __launch_bounds__(256, 2) gemm_mma(
    const float* __restrict__ X,
    const __nv_bfloat16* __restrict__ WA, const __nv_bfloat16* __restrict__ WB,
    float* __restrict__ Y1, float* __restrict__ Y2, int M)
{
    extern __shared__ uint32_t sm[];
    uint32_t* XH = sm;            // 64*68 = 4352
    uint32_t* XL = sm + 4352;
    uint32_t* BH = sm + 8704;     // 128*68 = 8704
    uint32_t* BL = sm + 17408;    // total 26112 u32 = 104448 B
    const int tid = threadIdx.x;
    const int row0 = blockIdx.x * 64;
    const __nv_bfloat16* W = (blockIdx.y == 0) ? WA : WB;
    float* Y = (blockIdx.y == 0) ? Y1 : Y2;

    for (int i = tid; i < 1024; i += 256) {
        int r = i >> 4, c8 = (i & 15) << 3;
        int gr = row0 + r;
        float4 v0 = make_float4(0.f, 0.f, 0.f, 0.f), v1 = v0;
        if (gr < M) {
            const float4* xp = (const float4*)(X + (size_t)gr * 128 + c8);
            v0 = __ldg(xp); v1 = __ldg(xp + 1);
        }
        uint32_t hi[4], lo[4];
        split_bf16(v0.x, v0.y, hi[0], lo[0]);
        split_bf16(v0.z, v0.w, hi[1], lo[1]);
        split_bf16(v1.x, v1.y, hi[2], lo[2]);
        split_bf16(v1.z, v1.w, hi[3], lo[3]);
        int si = r * WROW + (c8 >> 1);
        *(uint4*)(XH + si) = make_uint4(hi[0], hi[1], hi[2], hi[3]);
        *(uint4*)(XL + si) = make_uint4(lo[0], lo[1], lo[2], lo[3]);
    }
    {
        const uint4* wa = (const uint4*)W;
        for (int i = tid; i < 2048; i += 256) {
            int r = i >> 4, c4 = (i & 15) << 2;
            int si = r * WROW + c4;
            *(uint4*)(BH + si) = __ldg(wa + i);
            *(uint4*)(BL + si) = __ldg(wa + 2048 + i);
        }
    }
    __syncthreads();

    const int wid = tid >> 5, lane = tid & 31;
    const int wm = wid & 1, wn = wid >> 1;     // 2 x 4 warp grid
    const int g = lane >> 2, tq = lane & 3;

    float C[2][4][4];
    #pragma unroll
    for (int mt = 0; mt < 2; mt++)
        #pragma unroll
        for (int nt = 0; nt < 4; nt++)
            #pragma unroll
            for (int j = 0; j < 4; j++) C[mt][nt][j] = 0.f;

    #pragma unroll
    for (int ks = 0; ks < 8; ks++) {
        uint32_t Ah[2][4], Al[2][4];
        #pragma unroll
        for (int mt = 0; mt < 2; mt++) {
            int r0 = (wm * 32 + mt * 16 + g) * WROW + ks * 8 + tq;
            Ah[mt][0] = XH[r0];        Ah[mt][1] = XH[r0 + 8 * WROW];
            Ah[mt][2] = XH[r0 + 4];    Ah[mt][3] = XH[r0 + 8 * WROW + 4];
            Al[mt][0] = XL[r0];        Al[mt][1] = XL[r0 + 8 * WROW];
            Al[mt][2] = XL[r0 + 4];    Al[mt][3] = XL[r0 + 8 * WROW + 4];
        }
        #pragma unroll
        for (int nt = 0; nt < 4; nt++) {
            int bi = (wn * 32 + nt * 8 + g) * WROW + ks * 8 + tq;
            uint32_t bh0 = BH[bi], bh1 = BH[bi + 4];
            uint32_t bl0 = BL[bi], bl1 = BL[bi + 4];
            #pragma unroll
            for (int mt = 0; mt < 2; mt++) {
                mma16816(C[mt][nt], Ah[mt], bh0, bh1);
                mma16816(C[mt][nt], Ah[mt], bl0, bl1);
                mma16816(C[mt][nt], Al[mt], bh0, bh1);
            }
        }
    }
    #pragma unroll
    for (int mt = 0; mt < 2; mt++) {
        int row = row0 + wm * 32 + mt * 16 + g;
        #pragma unroll
        for (int nt = 0; nt < 4; nt++) {
            int col = wn * 32 + nt * 8 + tq * 2;
            if (row < M)
                *(float2*)(Y + (size_t)row * 128 + col) =
                    make_float2(C[mt][nt][0], C[mt][nt][1]);
            if (row + 8 < M)
                *(float2*)(Y + (size_t)(row + 8) * 128 + col) =
                    make_float2(C[mt][nt][2], C[mt][nt][3]);
        }
    }
}

// ---------------- same GEMM but fp16 output (for gathered intermediates) ----------------
__global__ void __launch_bounds__(256, 2) gemm_mma_h16(
    const float* __restrict__ X, const __nv_bfloat16* __restrict__ WA,
    __half* __restrict__ Yh, int M)
{
    extern __shared__ uint32_t sm[];
    uint32_t* XH = sm;
    uint32_t* XL = sm + 4352;
    uint32_t* BH = sm + 8704;
    uint32_t* BL = sm + 17408;
    const int tid = threadIdx.x;
    const int row0 = blockIdx.x * 64;

    for (int i = tid; i < 1024; i += 256) {
        int r = i >> 4, c8 = (i & 15) << 3;
        int gr = row0 + r;
        float4 v0 = make_float4(0.f, 0.f, 0.f, 0.f), v1 = v0;
        if (gr < M) {
            const float4* xp = (const float4*)(X + (size_t)gr * 128 + c8);
            v0 = __ldg(xp); v1 = __ldg(xp + 1);
        }
        uint32_t hi[4], lo[4];
        split_bf16(v0.x, v0.y, hi[0], lo[0]);
        split_bf16(v0.z, v0.w, hi[1], lo[1]);
        split_bf16(v1.x, v1.y, hi[2], lo[2]);
        split_bf16(v1.z, v1.w, hi[3], lo[3]);
        int si = r * WROW + (c8 >> 1);
        *(uint4*)(XH + si) = make_uint4(hi[0], hi[1], hi[2], hi[3]);
        *(uint4*)(XL + si) = make_uint4(lo[0], lo[1], lo[2], lo[3]);
    }
    {
        const uint4* wa = (const uint4*)WA;
        for (int i = tid; i < 2048; i += 256) {
            int r = i >> 4, c4 = (i & 15) << 2;
            int si = r * WROW + c4;
            *(uint4*)(BH + si) = __ldg(wa + i);
            *(uint4*)(BL + si) = __ldg(wa + 2048 + i);
        }
    }
    __syncthreads();

    const int wid = tid >> 5, lane = tid & 31;
    const int wm = wid & 1, wn = wid >> 1;
    const int g = lane >> 2, tq = lane & 3;

    float C[2][4][4];
    #pragma unroll
    for (int mt = 0; mt < 2; mt++)
        #pragma unroll
        for (int nt = 0; nt < 4; nt++)
            #pragma unroll
            for (int j = 0; j < 4; j++) C[mt][nt][j] = 0.f;

    #pragma unroll
    for (int ks = 0; ks < 8; ks++) {
        uint32_t Ah[2][4], Al[2][4];
        #pragma unroll
        for (int mt = 0; mt < 2; mt++) {
            int r0 = (wm * 32 + mt * 16 + g) * WROW + ks * 8 + tq;
            Ah[mt][0] = XH[r0];        Ah[mt][1] = XH[r0 + 8 * WROW];
            Ah[mt][2] = XH[r0 + 4];    Ah[mt][3] = XH[r0 + 8 * WROW + 4];
            Al[mt][0] = XL[r0];        Al[mt][1] = XL[r0 + 8 * WROW];
            Al[mt][2] = XL[r0 + 4];    Al[mt][3] = XL[r0 + 8 * WROW + 4];
        }
        #pragma unroll
        for (int nt = 0; nt < 4; nt++) {
            int bi = (wn * 32 + nt * 8 + g) * WROW + ks * 8 + tq;
            uint32_t bh0 = BH[bi], bh1 = BH[bi + 4];
            uint32_t bl0 = BL[bi], bl1 = BL[bi + 4];
            #pragma unroll
            for (int mt = 0; mt < 2; mt++) {
                mma16816(C[mt][nt], Ah[mt], bh0, bh1);
                mma16816(C[mt][nt], Ah[mt], bl0, bl1);
                mma16816(C[mt][nt], Al[mt], bh0, bh1);
            }
        }
    }
    #pragma unroll
    for (int mt = 0; mt < 2; mt++) {
        int row = row0 + wm * 32 + mt * 16 + g;
        #pragma unroll
        for (int nt = 0; nt < 4; nt++) {
            int col = wn * 32 + nt * 8 + tq * 2;
            if (row < M)
                *(__half2*)(Yh + (size_t)row * 128 + col) =
                    __floats2half2_rn(C[mt][nt][0], C[mt][nt][1]);
            if (row + 8 < M)
                *(__half2*)(Yh + (size_t)(row + 8) * 128 + col) =
                    __floats2half2_rn(C[mt][nt][2], C[mt][nt][3]);
        }
    }
}

// ---- fused: crf = U1[assign0[row]] + gcn[row]; write crf_sec; T(half) = crf @ gc2W ----
__global__ void __launch_bounds__(256, 2) gemm40_mma(
    const float* __restrict__ U1, const int* __restrict__ assign0,
    const float* __restrict__ gcn, float* __restrict__ crf_out,
    __half* __restrict__ Yh, int M)
{
    extern __shared__ uint32_t sm[];
    uint32_t* XH = sm;
    uint32_t* XL = sm + 4352;
    uint32_t* BH = sm + 8704;
    uint32_t* BL = sm + 13056;
    const int tid = threadIdx.x;
    const int row0 = blockIdx.x * 64;
    const __nv_bfloat16* W40 = g_wt + (size_t)5 * 32768;

    for (int i = tid; i < 1024; i += 256) {
        int r = i >> 4, c8 = (i & 15) << 3;
        int gr = row0 + r;
        float4 v0 = make_float4(0.f, 0.f, 0.f, 0.f), v1 = v0;
        if (gr < M) {
            int a = __ldg(&assign0[gr]);
            const float4* up = (const float4*)(U1 + (size_t)a * 128 + c8);
            const float4* gp = (const float4*)(gcn + (size_t)gr * 128 + c8);
            float4 u0 = __ldg(up), u1 = __ldg(up + 1);
            float4 g0 = __ldg(gp), g1 = __ldg(gp + 1);
            v0.x = u0.x + g0.x; v0.y = u0.y + g0.y; v0.z = u0.z + g0.z; v0.w = u0.w + g0.w;
            v1.x = u1.x + g1.x; v1.y = u1.y + g1.y; v1.z = u1.z + g1.z; v1.w = u1.w + g1.w;
            float4* cp = (float4*)(crf_out + (size_t)gr * 128 + c8);
            cp[0] = v0; cp[1] = v1;
        }
        uint32_t hi[4], lo[4];
        split_bf16(v0.x, v0.y, hi[0], lo[0]);
        split_bf16(v0.z, v0.w, hi[1], lo[1]);
        split_bf16(v1.x, v1.y, hi[2], lo[2]);
        split_bf16(v1.z, v1.w, hi[3], lo[3]);
        int si = r * WROW + (c8 >> 1);
        *(uint4*)(XH + si) = make_uint4(hi[0], hi[1], hi[2], hi[3]);
        *(uint4*)(XL + si) = make_uint4(lo[0], lo[1], lo[2], lo[3]);
    }
    {
        const uint4* wh = (const uint4*)W40;
        const uint4* wl = (const uint4*)(W40 + 5120);
        for (int i = tid; i < 1024; i += 256) {
            int r = i >> 4, c4 = (i & 15) << 2;
            int si = r * WROW + c4;
            uint4 h = make_uint4(0, 0, 0, 0), l = h;
            if (r < 40) { h = __ldg(wh + i); l = __ldg(wl + i); }
            *(uint4*)(BH + si) = h;
            *(uint4*)(BL + si) = l;
        }
    }
    __syncthreads();

    const int wid = tid >> 5, lane = tid & 31;
    const int wm = wid & 3, wn = wid >> 2;     // 4x2 grid; 16x32 warp tiles
    const int g = lane >> 2, tq = lane & 3;

    float C[4][4];
    #pragma unroll
    for (int nt = 0; nt < 4; nt++)
        #pragma unroll
        for (int j = 0; j < 4; j++) C[nt][j] = 0.f;

    #pragma unroll
    for (int ks = 0; ks < 8; ks++) {
        uint32_t Ah[4], Al[4];
        int r0 = (wm * 16 + g) * WROW + ks * 8 + tq;
        Ah[0] = XH[r0];        Ah[1] = XH[r0 + 8 * WROW];
        Ah[2] = XH[r0 + 4];    Ah[3] = XH[r0 + 8 * WROW + 4];
        Al[0] = XL[r0];        Al[1] = XL[r0 + 8 * WROW];
        Al[2] = XL[r0 + 4];    Al[3] = XL[r0 + 8 * WROW + 4];
        #pragma unroll
        for (int nt = 0; nt < 4; nt++) {
            int bi = (wn * 32 + nt * 8 + g) * WROW + ks * 8 + tq;
            uint32_t bh0 = BH[bi], bh1 = BH[bi + 4];
            uint32_t bl0 = BL[bi], bl1 = BL[bi + 4];
            mma16816(C[nt], Ah, bh0, bh1);
            mma16816(C[nt], Ah, bl0, bl1);
            mma16816(C[nt], Al, bh0, bh1);
        }
    }
    {
        int row = row0 + wm * 16 + g;
        #pragma unroll
        for (int nt = 0; nt < 4; nt++) {
            int col = wn * 32 + nt * 8 + tq * 2;
            if (col < 40) {
                if (row < M)
                    *(__half2*)(Yh + (size_t)row * 40 + col) =
                        __floats2half2_rn(C[nt][0], C[nt][1]);
                if (row + 8 < M)
                    *(__half2*)(Yh + (size_t)(row + 8) * 40 + col) =
                        __floats2half2_rn(C[nt][2], C[nt][3]);
            }
        }
    }
}

// ---------------- batched CSR build kernels ----------------
__global__ void kzero_all() {
    int i = blockIdx.x * 256 + threadIdx.x;
    if (i < 100000)      g_i[I_CNT0 + i] = 0;
    else if (i < 125000) g_i[I_CNT1 + (i - 100000)] = 0;
    else if (i < 131250) g_i[I_CNT2 + (i - 125000)] = 0;
    else if (i < 156250) g_i[I_PCN1 + (i - 131250)] = 0;
    else if (i < 162500) g_i[I_PCN2 + (i - 156250)] = 0;
}
__global__ void khist_all(const int* __restrict__ A0, const int* __restrict__ A1,
                          const int* __restrict__ A2, const int* __restrict__ as0,
                          const int* __restrict__ as1) {
    int i4 = (blockIdx.x * 256 + threadIdx.x) * 4;
    if (i4 >= 2225000) return;
    if (i4 < 1600000) {
        int4 d = __ldg((const int4*)(A0 + i4));
        atomicAdd(&g_i[I_CNT0 + d.x], 1); atomicAdd(&g_i[I_CNT0 + d.y], 1);
        atomicAdd(&g_i[I_CNT0 + d.z], 1); atomicAdd(&g_i[I_CNT0 + d.w], 1);
    } else if (i4 < 2000000) {
        int4 d = __ldg((const int4*)(A1 + (i4 - 1600000)));
        atomicAdd(&g_i[I_CNT1 + d.x], 1); atomicAdd(&g_i[I_CNT1 + d.y], 1);
        atomicAdd(&g_i[I_CNT1 + d.z], 1); atomicAdd(&g_i[I_CNT1 + d.w], 1);
    } else if (i4 < 2100000) {
        int4 d = __ldg((const int4*)(A2 + (i4 - 2000000)));
        atomicAdd(&g_i[I_CNT2 + d.x], 1); atomicAdd(&g_i[I_CNT2 + d.y], 1);
        atomicAdd(&g_i[I_CNT2 + d.z], 1); atomicAdd(&g_i[I_CNT2 + d.w], 1);
    } else if (i4 < 2200000) {
        int4 d = __ldg((const int4*)(as0 + (i4 - 2100000)));
        atomicAdd(&g_i[I_PCN1 + d.x], 1); atomicAdd(&g_i[I_PCN1 + d.y], 1);
        atomicAdd(&g_i[I_PCN1 + d.z], 1); atomicAdd(&g_i[I_PCN1 + d.w], 1);
    } else {
        int4 d = __ldg((const int4*)(as1 + (i4 - 2200000)));
        atomicAdd(&g_i[I_PCN2 + d.x], 1); atomicAdd(&g_i[I_PCN2 + d.y], 1);
        atomicAdd(&g_i[I_PCN2 + d.z], 1); atomicAdd(&g_i[I_PCN2 + d.w], 1);
    }
}
__global__ void scan_blk_all() {
    __shared__ int wsum[32];
    Seg s = seg_resolve(blockIdx.x);
    int t = threadIdx.x;
    int i = s.sblk * 1024 + t;
    int v = (i < s.n) ? s.cnt[i] : 0;
    int x = v;
    #pragma unroll
    for (int o = 1; o < 32; o <<= 1) {
        int tmp = __shfl_up_sync(0xffffffffu, x, o);
        if ((t & 31) >= o) x += tmp;
    }
    if ((t & 31) == 31) wsum[t >> 5] = x;
    __syncthreads();
    if (t < 32) {
        int y = wsum[t];
        #pragma unroll
        for (int o = 1; o < 32; o <<= 1) {
            int tmp = __shfl_up_sync(0xffffffffu, y, o);
            if (t >= o) y += tmp;
        }
        wsum[t] = y;
    }
    __syncthreads();
    int base = (t >= 32) ? wsum[(t >> 5) - 1] : 0;
    int incl = base + x;
    if (i < s.n) s.off[i] = incl - v;
    if (t == 1023) g_i[I_PART + s.pbase + s.sblk] = incl;
}
__global__ void scan_part_all() {
    __shared__ int sh[128];
    const int bases[5] = {0, 98, 123, 130, 155};
    const int cnts[5]  = {98, 25, 7, 25, 7};
    int b = blockIdx.x, t = threadIdx.x;
    int* part = g_i + I_PART + bases[b];
    int nb = cnts[b];
    int v = (t < nb) ? part[t] : 0;
    sh[t] = v;
    __syncthreads();
    #pragma unroll
    for (int o = 1; o < 128; o <<= 1) {
        int tmp = (t >= o) ? sh[t - o] : 0;
        __syncthreads();
        sh[t] += tmp;
        __syncthreads();
    }
    if (t < nb) part[t] = sh[t] - v;
    if (t == 0) {
        int total = sh[127];
        int* off = (b == 0) ? g_i + I_OFF0 : (b == 1) ? g_i + I_OFF1
                 : (b == 2) ? g_i + I_OFF2 : (b == 3) ? g_i + I_POF0 : g_i + I_POF1;
        int n = (b == 0) ? N0c : (b == 1) ? N1c : (b == 2) ? N2c
              : (b == 3) ? N1c : N2c;
        off[n] = total;
    }
}
__global__ void scan_add_all() {
    Seg s = seg_resolve(blockIdx.x);
    int i = s.sblk * 1024 + threadIdx.x;
    if (i < s.n) {
        int v = s.off[i] + g_i[I_PART + s.pbase + s.sblk];
        s.off[i] = v;
        s.cur[i] = v;
    }
}
__global__ void kscatter_all(const int* __restrict__ A0, const float* __restrict__ A0v,
                             const int* __restrict__ A1, const float* __restrict__ A1v,
                             const int* __restrict__ A2, const float* __restrict__ A2v,
                             const int* __restrict__ as0, const int* __restrict__ as1,
                             int lo, int hi) {
    int i4 = lo + (blockIdx.x * 256 + threadIdx.x) * 4;
    if (i4 >= hi) return;
    if (i4 < 1600000) {
        int4 d  = __ldg((const int4*)(A0 + i4));
        int4 sv = __ldg((const int4*)(A0 + 1600000 + i4));
        float4 vv = __ldg((const float4*)(A0v + i4));
        int p;
        p = atomicAdd(&g_i[I_CNT0 + d.x], 1); g_i[I_SRC0 + p] = sv.x; g_f[F_VAL0 + p] = vv.x;
        p = atomicAdd(&g_i[I_CNT0 + d.y], 1); g_i[I_SRC0 + p] = sv.y; g_f[F_VAL0 + p] = vv.y;
        p = atomicAdd(&g_i[I_CNT0 + d.z], 1); g_i[I_SRC0 + p] = sv.z; g_f[F_VAL0 + p] = vv.z;
        p = atomicAdd(&g_i[I_CNT0 + d.w], 1); g_i[I_SRC0 + p] = sv.w; g_f[F_VAL0 + p] = vv.w;
    } else if (i4 < 2000000) {
        int e = i4 - 1600000;
        int4 d  = __ldg((const int4*)(A1 + e));
        int4 sv = __ldg((const int4*)(A1 + 400000 + e));
        float4 vv = __ldg((const float4*)(A1v + e));
        int p;
        p = atomicAdd(&g_i[I_CNT1 + d.x], 1); g_i[I_SRC1 + p] = sv.x; g_f[F_VAL1 + p] = vv.x;
        p = atomicAdd(&g_i[I_CNT1 + d.y], 1); g_i[I_SRC1 + p] = sv.y; g_f[F_VAL1 + p] = vv.y;
        p = atomicAdd(&g_i[I_CNT1 + d.z], 1); g_i[I_SRC1 + p] = sv.z; g_f[F_VAL1 + p] = vv.z;
        p = atomicAdd(&g_i[I_CNT1 + d.w], 1); g_i[I_SRC1 + p] = sv.w; g_f[F_VAL1 + p] = vv.w;
    } else if (i4 < 2100000) {
        int e = i4 - 2000000;
        int4 d  = __ldg((const int4*)(A2 + e));
        int4 sv = __ldg((const int4*)(A2 + 100000 + e));
        float4 vv = __ldg((const float4*)(A2v + e));
        int p;
        p = atomicAdd(&g_i[I_CNT2 + d.x], 1); g_i[I_SRC2 + p] = sv.x; g_f[F_VAL2 + p] = vv.x;
        p = atomicAdd(&g_i[I_CNT2 + d.y], 1); g_i[I_SRC2 + p] = sv.y; g_f[F_VAL2 + p] = vv.y;
        p = atomicAdd(&g_i[I_CNT2 + d.z], 1); g_i[I_SRC2 + p] = sv.z; g_f[F_VAL2 + p] = vv.z;
        p = atomicAdd(&g_i[I_CNT2 + d.w], 1); g_i[I_SRC2 + p] = sv.w; g_f[F_VAL2 + p] = vv.w;
    } else if (i4 < 2200000) {
        int e = i4 - 2100000;
        int4 d = __ldg((const int4*)(as0 + e));
        int p;
        p = atomicAdd(&g_i[I_PCN1 + d.x], 1); g_i[I_PID0 + p] = e;
        p = atomicAdd(&g_i[I_PCN1 + d.y], 1); g_i[I_PID0 + p] = e + 1;
        p = atomicAdd(&g_i[I_PCN1 + d.z], 1); g_i[I_PID0 + p] = e + 2;
        p = atomicAdd(&g_i[I_PCN1 + d.w], 1); g_i[I_PID0 + p] = e + 3;
    } else {
        int e = i4 - 2200000;
        int4 d = __ldg((const int4*)(as1 + e));
        int p;
        p = atomicAdd(&g_i[I_PCN2 + d.x], 1); g_i[I_PID1 + p] = e;
        p = atomicAdd(&g_i[I_PCN2 + d.y], 1); g_i[I_PID1 + p] = e + 1;
        p = atomicAdd(&g_i[I_PCN2 + d.z], 1); g_i[I_PID1 + p] = e + 2;
        p = atomicAdd(&g_i[I_PCN2 + d.w], 1); g_i[I_PID1 + p] = e + 3;
    }
}

// ---------------- CSR SpMM, 128 cols, fp16 payload, warp per row, unroll-2 -------------
__global__ void spmm128h(const int* __restrict__ off, const int* __restrict__ srcs,
                         const float* __restrict__ vals, const __half* __restrict__ X,
                         const float* __restrict__ bias, float* __restrict__ Y,
                         int n, int relu) {
    int row = blockIdx.x * blockDim.y + threadIdx.y;
    if (row >= n) return;
    int lane = threadIdx.x;
    int s = off[row], e = off[row + 1];
    float4 acc = make_float4(0.f, 0.f, 0.f, 0.f);
    int j = s;
    for (; j + 2 <= e; j += 2) {
        int s0 = __ldg(&srcs[j]), s1 = __ldg(&srcs[j + 1]);
        float v0 = __ldg(&vals[j]), v1 = __ldg(&vals[j + 1]);
        uint2 r0 = __ldg((const uint2*)(X + (size_t)s0 * 128 + lane * 4));
        uint2 r1 = __ldg((const uint2*)(X + (size_t)s1 * 128 + lane * 4));
        float2 a0 = __half22float2(*(__half2*)&r0.x);
        float2 b0 = __half22float2(*(__half2*)&r0.y);
        float2 a1 = __half22float2(*(__half2*)&r1.x);
        float2 b1 = __half22float2(*(__half2*)&r1.y);
        acc.x = fmaf(v0, a0.x, acc.x); acc.y = fmaf(v0, a0.y, acc.y);
        acc.z = fmaf(v0, b0.x, acc.z); acc.w = fmaf(v0, b0.y, acc.w);
        acc.x = fmaf(v1, a1.x, acc.x); acc.y = fmaf(v1, a1.y, acc.y);
        acc.z = fmaf(v1, b1.x, acc.z); acc.w = fmaf(v1, b1.y, acc.w);
    }
    if (j < e) {
        int src = __ldg(&srcs[j]);
        float v = __ldg(&vals[j]);
        uint2 r0 = __ldg((const uint2*)(X + (size_t)src * 128 + lane * 4));
        float2 a0 = __half22float2(*(__half2*)&r0.x);
        float2 b0 = __half22float2(*(__half2*)&r0.y);
        acc.x = fmaf(v, a0.x, acc.x); acc.y = fmaf(v, a0.y, acc.y);
        acc.z = fmaf(v, b0.x, acc.z); acc.w = fmaf(v, b0.y, acc.w);
    }
    float4 b = __ldg((const float4*)bias + lane);
    acc.x += b.x; acc.y += b.y; acc.z += b.z; acc.w += b.w;
    if (relu) {
        acc.x = fmaxf(acc.x, 0.f); acc.y = fmaxf(acc.y, 0.f);
        acc.z = fmaxf(acc.z, 0.f); acc.w = fmaxf(acc.w, 0.f);
    }
    *((float4*)(Y + (size_t)row * 128) + lane) = acc;
}

// ---------------- CSR SpMM, 40 cols, fp16 payload, warp per row, unroll-2 --------------
__global__ void spmm40h(const int* __restrict__ off, const int* __restrict__ srcs,
                        const float* __restrict__ vals, const __half* __restrict__ X,
                        const float* __restrict__ bias, float* __restrict__ Y, int n) {
    int row = blockIdx.x * blockDim.y + threadIdx.y;
    if (row >= n) return;
    int lane = threadIdx.x;
    int s = off[row], e = off[row + 1];
    float a0 = 0.f, a1 = 0.f;
    int j = s;
    for (; j + 2 <= e; j += 2) {
        int s0 = __ldg(&srcs[j]), s1 = __ldg(&srcs[j + 1]);
        float v0 = __ldg(&vals[j]), v1 = __ldg(&vals[j + 1]);
        float x0a = __half2float(__ldg(X + (size_t)s0 * 40 + lane));
        float x1a = __half2float(__ldg(X + (size_t)s1 * 40 + lane));
        float x0b = 0.f, x1b = 0.f;
        if (lane < 8) {
            x0b = __half2float(__ldg(X + (size_t)s0 * 40 + 32 + lane));
            x1b = __half2float(__ldg(X + (size_t)s1 * 40 + 32 + lane));
        }
        a0 = fmaf(v0, x0a, a0); a0 = fmaf(v1, x1a, a0);
        a1 = fmaf(v0, x0b, a1); a1 = fmaf(v1, x1b, a1);
    }
    if (j < e) {
        int src = __ldg(&srcs[j]);
        float v = __ldg(&vals[j]);
        a0 = fmaf(v, __half2float(__ldg(X + (size_t)src * 40 + lane)), a0);
        if (lane < 8) a1 = fmaf(v, __half2float(__ldg(X + (size_t)src * 40 + 32 + lane)), a1);
    }
    Y[(size_t)row * 40 + lane] = a0 + __ldg(&bias[lane]);
    if (lane < 8) Y[(size_t)row * 40 + 32 + lane] = a1 + __ldg(&bias[32 + lane]);
}

// ---------------- pooling via CSR gather + fused emb add, unroll-2 ----------------
__global__ void pool_gather(const int* __restrict__ off, const int* __restrict__ ids,
                            const float* __restrict__ X,
                            const int* __restrict__ nw, const float* __restrict__ emb,
                            float* __restrict__ H, float* __restrict__ H0, int n) {
    int row = blockIdx.x * blockDim.y + threadIdx.y;
    if (row >= n) return;
    int lane = threadIdx.x;
    int s = off[row], e = off[row + 1];
    float4 acc = make_float4(0.f, 0.f, 0.f, 0.f);
    int j = s;
    for (; j + 2 <= e; j += 2) {
        int n0 = __ldg(&ids[j]), n1 = __ldg(&ids[j + 1]);
        float4 v0 = __ldg((const float4*)(X + (size_t)n0 * 128) + lane);
        float4 v1 = __ldg((const float4*)(X + (size_t)n1 * 128) + lane);
        acc.x += v0.x + v1.x; acc.y += v0.y + v1.y;
        acc.z += v0.z + v1.z; acc.w += v0.w + v1.w;
    }
    if (j < e) {
        int node = __ldg(&ids[j]);
        float4 v = __ldg((const float4*)(X + (size_t)node * 128) + lane);
        acc.x += v.x; acc.y += v.y; acc.z += v.z; acc.w += v.w;
    }
    *((float4*)(H + (size_t)row * 128) + lane) = acc;
    int w = __ldg(&nw[row]);
    float4 em = __ldg((const float4*)(emb + (size_t)w * 128) + lane);
    acc.x += em.x; acc.y += em.y; acc.z += em.z; acc.w += em.w;
    *((float4*)(H0 + (size_t)row * 128) + lane) = acc;
}

// ---------------- CRF refinement: warp per dst row, online softmax, unroll-2 ----------
__global__ void crf_refine(const int* __restrict__ off, const int* __restrict__ srcs,
                           const float* __restrict__ Q, const float* __restrict__ Km,
                           const float* __restrict__ H0,
                           const float* __restrict__ alpha_p, const float* __restrict__ beta_p,
                           float* __restrict__ Out, int n) {
    int row = blockIdx.x * blockDim.y + threadIdx.y;
    if (row >= n) return;
    int lane = threadIdx.x;
    float4 q = __ldg((const float4*)(Q + (size_t)row * 128) + lane);
    int s = off[row], e = off[row + 1];
    float m = -3.4e38f, z = 0.f;
    float4 macc = make_float4(0.f, 0.f, 0.f, 0.f);
    int j = s;
    for (; j + 2 <= e; j += 2) {
        int s0 = __ldg(&srcs[j]), s1 = __ldg(&srcs[j + 1]);
        float4 k0 = __ldg((const float4*)(Km + (size_t)s0 * 128) + lane);
        float4 k1 = __ldg((const float4*)(Km + (size_t)s1 * 128) + lane);
        float4 h0 = __ldg((const float4*)(H0 + (size_t)s0 * 128) + lane);
        float4 h1 = __ldg((const float4*)(H0 + (size_t)s1 * 128) + lane);
        float p0 = q.x * k0.x + q.y * k0.y + q.z * k0.z + q.w * k0.w;
        float p1 = q.x * k1.x + q.y * k1.y + q.z * k1.z + q.w * k1.w;
        #pragma unroll
        for (int o = 16; o; o >>= 1) {
            p0 += __shfl_xor_sync(0xffffffffu, p0, o);
            p1 += __shfl_xor_sync(0xffffffffu, p1, o);
        }
        p0 *= 0.08838834764831845f;
        p1 *= 0.08838834764831845f;
        if (p0 > m) {
            float sc = __expf(m - p0);
            z *= sc; macc.x *= sc; macc.y *= sc; macc.z *= sc; macc.w *= sc;
            m = p0;
        }
        float w0 = __expf(p0 - m);
        z += w0;
        macc.x = fmaf(w0, h0.x, macc.x); macc.y = fmaf(w0, h0.y, macc.y);
        macc.z = fmaf(w0, h0.z, macc.z); macc.w = fmaf(w0, h0.w, macc.w);
        if (p1 > m) {
            float sc = __expf(m - p1);
            z *= sc; macc.x *= sc; macc.y *= sc; macc.z *= sc; macc.w *= sc;
            m = p1;
        }
        float w1 = __expf(p1 - m);
        z += w1;
        macc.x = fmaf(w1, h1.x, macc.x); macc.y = fmaf(w1, h1.y, macc.y);
        macc.z = fmaf(w1, h1.z, macc.z); macc.w = fmaf(w1, h1.w, macc.w);
    }
    if (j < e) {
        int src = __ldg(&srcs[j]);
        float4 kv = __ldg((const float4*)(Km + (size_t)src * 128) + lane);
        float4 hv = __ldg((const float4*)(H0 + (size_t)src * 128) + lane);
        float p = q.x * kv.x + q.y * kv.y + q.z * kv.z + q.w * kv.w;
        #pragma unroll
        for (int o = 16; o; o >>= 1) p += __shfl_xor_sync(0xffffffffu, p, o);
        p *= 0.08838834764831845f;
        if (p > m) {
            float sc = __expf(m - p);
            z *= sc; macc.x *= sc; macc.y *= sc; macc.z *= sc; macc.w *= sc;
            m = p;
        }
        float w = __expf(p - m);
        z += w;
        macc.x = fmaf(w, hv.x, macc.x); macc.y = fmaf(w, hv.y, macc.y);
        macc.z = fmaf(w, hv.z, macc.z); macc.w = fmaf(w, hv.w, macc.w);
    }
    float alpha = __ldg(alpha_p), beta = __ldg(beta_p);
    float4 h0d = __ldg((const float4*)(H0 + (size_t)row * 128) + lane);
    float invz = 1.f / (z + 1e-16f);
    float invab = 1.f / (alpha + beta);
    float4 r;
    r.x = (alpha * h0d.x + beta * macc.x * invz) * invab;
    r.y = (alpha * h0d.y + beta * macc.y * invz) * invab;
    r.z = (alpha * h0d.z + beta * macc.z * invz) * invab;
    r.w = (alpha * h0d.w + beta * macc.w * invz) * invab;
    *((float4*)(Out + (size_t)row * 128) + lane) = r;
}

// ---------------- unpool + skip ----------------
__global__ void unpool_add(const float* __restrict__ Hi, const int* __restrict__ assign,
                           const float* __restrict__ skip, float* __restrict__ Out, int n) {
    int i = blockIdx.x * blockDim.y + threadIdx.y;
    if (i >= n) return;
    int lane = threadIdx.x;
    int a = assign[i];
    float4 v = __ldg((const float4*)(Hi + (size_t)a * 128) + lane);
    float4 sk = *((const float4*)(skip + (size_t)i * 128) + lane);
    v.x += sk.x; v.y += sk.y; v.z += sk.z; v.w += sk.w;
    *((float4*)(Out + (size_t)i * 128) + lane) = v;
}

// ---------------- streams/events (created at static init) ----------------
struct StreamEnv {
    cudaStream_t sB;
    cudaEvent_t evF, evB0, evB;
    StreamEnv() {
        cudaStreamCreateWithFlags(&sB, cudaStreamNonBlocking);
        cudaEventCreateWithFlags(&evF,  cudaEventDisableTiming);
        cudaEventCreateWithFlags(&evB0, cudaEventDisableTiming);
        cudaEventCreateWithFlags(&evB,  cudaEventDisableTiming);
    }
};
static StreamEnv g_se;

// ---------------- host ----------------
extern "C" void kernel_launch(void* const* d_in, const int* in_sizes, int n_in,
                              void* d_out, int out_size) {
    const float* x       = (const float*)d_in[0];
    const int*   A0      = (const int*)d_in[1];
    const float* A0v     = (const float*)d_in[2];
    const int*   A1      = (const int*)d_in[3];
    const float* A1v     = (const float*)d_in[4];
    const int*   A2      = (const int*)d_in[5];
    const float* A2v     = (const float*)d_in[6];
    const int*   assign0 = (const int*)d_in[7];
    const int*   assign1 = (const int*)d_in[8];
    const int*   nwgt1   = (const int*)d_in[9];
    const int*   nwgt2   = (const int*)d_in[10];
    const float* gc1b    = (const float*)d_in[12];
    const float* gc2b    = (const float*)d_in[14];
    const float* c1emb   = (const float*)d_in[17];
    const float* c1a     = (const float*)d_in[18];
    const float* c1be    = (const float*)d_in[19];
    const float* c2emb   = (const float*)d_in[22];
    const float* c2a     = (const float*)d_in[23];
    const float* c2be    = (const float*)d_in[24];

    float* out_sec = (float*)d_out;
    float* gcn_sec = out_sec + (size_t)N0c * NCc;
    float* crf_sec = gcn_sec + (size_t)N0c * NFc;

    void* fp; cudaGetSymbolAddress(&fp, g_f);
    void* ip; cudaGetSymbolAddress(&ip, g_i);
    void* wp; cudaGetSymbolAddress(&wp, g_wt);
    float* F = (float*)fp;
    int*   I = (int*)ip;
    __nv_bfloat16* WT = (__nv_bfloat16*)wp;

    __half* xWh = (__half*)(F + F_XW);          // N0 x 128 fp16
    __half* Th  = (__half*)(F + F_T);           // N0 x 40 fp16
    float* H1  = F + F_H1;  float* H01 = F + F_H01;
    float* Q1  = F + F_Q1;  float* K1  = F + F_K1;
    float* H1R = F + F_H1R; float* U1  = F + F_U1;
    float* H2  = F + F_H2;  float* H02 = F + F_H02;
    float* Q2  = F + F_Q2;  float* K2  = F + F_K2;
    float* H2R = F + F_H2R;
    float* V0  = F + F_VAL0;

    int* OFF0 = I + I_OFF0; int* SRC0 = I + I_SRC0;
    int* OFF1 = I + I_OFF1; int* SRC1 = I + I_SRC1;
    int* OFF2 = I + I_OFF2; int* SRC2 = I + I_SRC2;
    int* POF0 = I + I_POF0; int* PID0 = I + I_PID0;
    int* POF1 = I + I_POF1; int* PID1 = I + I_PID1;

    __nv_bfloat16* WT_gc1 = WT + 0 * 32768;
    __nv_bfloat16* WT_q1  = WT + 1 * 32768;
    __nv_bfloat16* WT_k1  = WT + 2 * 32768;
    __nv_bfloat16* WT_q2  = WT + 3 * 32768;
    __nv_bfloat16* WT_k2  = WT + 4 * 32768;

    const int SMEM_G  = 26112 * 4;
    const int SMEM_40 = 17408 * 4;

    static bool attr_done = false;
    if (!attr_done) {
        cudaFuncSetAttribute(gemm_mma, cudaFuncAttributeMaxDynamicSharedMemorySize, SMEM_G);
        cudaFuncSetAttribute(gemm_mma_h16, cudaFuncAttributeMaxDynamicSharedMemorySize, SMEM_G);
        cudaFuncSetAttribute(gemm40_mma, cudaFuncAttributeMaxDynamicSharedMemorySize, SMEM_40);
        attr_done = true;
    }

    dim3 warp8(32, 8);
    cudaStream_t s0 = 0;
    cudaStream_t sB = g_se.sB;

    cudaEventRecord(g_se.evF, s0);
    cudaStreamWaitEvent(sB, g_se.evF, 0);

    // enqueue order keeps the gc1 GEMM as 4th launch for ncu
    wprep_all<<<340, 256, 0, s0>>>((const float*)d_in[11], (const float*)d_in[15],
                                   (const float*)d_in[16], (const float*)d_in[20],
                                   (const float*)d_in[21], (const float*)d_in[13]);
    kzero_all<<<(162500 + 255) / 256, 256, 0, sB>>>();
    khist_all<<<(556250 + 255) / 256, 256, 0, sB>>>(A0, A1, A2, assign0, assign1);
    gemm_mma_h16<<<(N0c + 63) / 64, 256, SMEM_G, s0>>>(x, WT_gc1, xWh, N0c);
    scan_blk_all<<<SCAN_BLOCKS, 1024, 0, sB>>>();
    scan_part_all<<<5, 128, 0, sB>>>();
    scan_add_all<<<SCAN_BLOCKS, 1024, 0, sB>>>();
    kscatter_all<<<(400000 + 255) / 256, 256, 0, sB>>>(A0, A0v, A1, A1v, A2, A2v,
                                                       assign0, assign1, 0, 1600000);
    cudaEventRecord(g_se.evB0, sB);
    kscatter_all<<<(156250 + 255) / 256, 256, 0, sB>>>(A0, A0v, A1, A1v, A2, A2v,
                                                       assign0, assign1,
                                                       1600000, 2225000);
    cudaEventRecord(g_se.evB, sB);

    cudaStreamWaitEvent(s0, g_se.evB0, 0);
    spmm128h<<<(N0c + 7) / 8, warp8, 0, s0>>>(OFF0, SRC0, V0, xWh, gc1b, gcn_sec,
                                              N0c, 1);

    cudaStreamWaitEvent(s0, g_se.evB, 0);
    // level 1: pool + dual QK GEMM (one launch, gridDim.y=2) + CRF
    pool_gather<<<(N1c + 7) / 8, warp8, 0, s0>>>(POF0, PID0, gcn_sec, nwgt1, c1emb,
                                                 H1, H01, N1c);
    gemm_mma<<<dim3((N1c + 63) / 64, 2), 256, SMEM_G, s0>>>(H1, WT_q1, WT_k1,
                                                            Q1, K1, N1c);
    crf_refine<<<(N1c + 7) / 8, warp8, 0, s0>>>(OFF1, SRC1, Q1, K1, H01, c1a, c1be,
                                                H1R, N1c);

    // level 2: pool + dual QK GEMM + CRF
    pool_gather<<<(N2c + 7) / 8, warp8, 0, s0>>>(POF1, PID1, H1R, nwgt2, c2emb,
                                                 H2, H02, N2c);
    gemm_mma<<<dim3((N2c + 63) / 64, 2), 256, SMEM_G, s0>>>(H2, WT_q2, WT_k2,
                                                            Q2, K2, N2c);
    crf_refine<<<(N2c + 7) / 8, warp8, 0, s0>>>(OFF2, SRC2, Q2, K2, H02, c2a, c2be,
                                                H2R, N2c);

    // unpool level 2->1
    unpool_add<<<(N1c + 7) / 8, warp8, 0, s0>>>(H2R, assign1, H1R, U1, N1c);

    // fused unpool 1->0 + gc2 GEMM (fp16 T out)
    gemm40_mma<<<(N0c + 63) / 64, 256, SMEM_40, s0>>>(U1, assign0, gcn_sec, crf_sec,
                                                      Th, N0c);
    spmm40h<<<(N0c + 7) / 8, warp8, 0, s0>>>(OFF0, SRC0, V0, Th, gc2b, out_sec, N0c);
}